// round 12
// baseline (speedup 1.0000x reference)
#include <cuda_runtime.h>
#include <cuda_bf16.h>
#include <math.h>
#include <stdint.h>

#define TOK   16384
#define DIM   768
#define NSEQ  1024
#define NHEADS 12
#define HD    64
#define ENC_HEADS 6
#define EPSV  1e-5f
#define QLD   2304            // fused qkv row stride

// fp32 (tf32-rounded) weight buffer offsets — fc only
#define OFF_WFC1 2654208
#define OFF_WFC2 5013504
#define WTOT     7372800
// bf16 plane offsets (halfs) — Wq/Wk/Wv contiguous = fused [2304 x 768]
#define OFF_WQKV 0
#define OFF_WENC 1769472
#define OFF_WDEC 2359296
#define WBTOT    2654208

// ---------------- scratch (device globals; allocation is forbidden) ----------------
__device__ __nv_bfloat16 g_xhb[TOK * DIM];
__device__ __nv_bfloat16 g_xlb[TOK * DIM];
__device__ __nv_bfloat16 g_ahb[TOK * DIM];
__device__ __nv_bfloat16 g_alb[TOK * DIM];
__device__ __nv_bfloat16 g_wbh[WBTOT];
__device__ __nv_bfloat16 g_wbl[WBTOT];
__device__ float g_qkv[TOK * QLD];
__device__ float g_enc[TOK * DIM];
__device__ float g_dec[TOK * DIM];
__device__ float g_xmid[TOK * DIM];
__device__ float g_h[TOK * DIM];
__device__ float g_act[TOK * 3072];
__device__ float g_wh[WTOT];
__device__ float g_wl[WTOT];
__device__ float g_post[TOK * 4];
__device__ float g_prior[TOK * 4];
__device__ int   g_idx[TOK];

// ---------------- small PTX helpers (all sm_80-baseline legal) ----------------
__device__ __forceinline__ uint32_t s2u(const void* p) {
    uint32_t a;
    asm("{ .reg .u64 t; cvta.to.shared.u64 t, %1; cvt.u32.u64 %0, t; }" : "=r"(a) : "l"(p));
    return a;
}
__device__ __forceinline__ uint32_t f2tf32(float v) {
    uint32_t r;
    asm("cvt.rna.tf32.f32 %0, %1;" : "=r"(r) : "f"(v));
    return r;
}
__device__ __forceinline__ float tf32r(float v) { return __uint_as_float(f2tf32(v)); }

__device__ __forceinline__ void cpasync16(uint32_t dst, const void* src) {
    asm volatile("cp.async.cg.shared.global [%0], [%1], 16;" :: "r"(dst), "l"(src));
}
__device__ __forceinline__ void cp_commit() {
    asm volatile("cp.async.commit_group;" ::: "memory");
}
__device__ __forceinline__ void mma_frag(float* d, const uint32_t* a, const uint32_t* b) {
    asm volatile(
        "mma.sync.aligned.m16n8k8.row.col.f32.tf32.tf32.f32 "
        "{%0,%1,%2,%3}, {%4,%5,%6,%7}, {%8,%9}, {%0,%1,%2,%3};"
        : "+f"(d[0]), "+f"(d[1]), "+f"(d[2]), "+f"(d[3])
        : "r"(a[0]), "r"(a[1]), "r"(a[2]), "r"(a[3]), "r"(b[0]), "r"(b[1]));
}
__device__ __forceinline__ void mma_bf(float* d, const uint32_t* a, const uint32_t* b) {
    asm volatile(
        "mma.sync.aligned.m16n8k16.row.col.f32.bf16.bf16.f32 "
        "{%0,%1,%2,%3}, {%4,%5,%6,%7}, {%8,%9}, {%0,%1,%2,%3};"
        : "+f"(d[0]), "+f"(d[1]), "+f"(d[2]), "+f"(d[3])
        : "r"(a[0]), "r"(a[1]), "r"(a[2]), "r"(a[3]), "r"(b[0]), "r"(b[1]));
}
__device__ __forceinline__ void ldm_x4(uint32_t* r, uint32_t addr) {
    asm volatile("ldmatrix.sync.aligned.m8n8.x4.shared.b16 {%0,%1,%2,%3}, [%4];"
                 : "=r"(r[0]), "=r"(r[1]), "=r"(r[2]), "=r"(r[3]) : "r"(addr));
}
__device__ __forceinline__ void split2(float a, float b, uint32_t& hi, uint32_t& lo) {
    __nv_bfloat16 ha = __float2bfloat16(a), hb = __float2bfloat16(b);
    __nv_bfloat162 H(ha, hb);
    __nv_bfloat162 L(__float2bfloat16(a - __bfloat162float(ha)),
                     __float2bfloat16(b - __bfloat162float(hb)));
    hi = *(uint32_t*)&H;
    lo = *(uint32_t*)&L;
}

// ================= bf16x3 GEMM (fp32-grade): C = A*B^T, tile 256x128, Kchunk 32 ====
// 8 warps: warp (wid>>1) owns 64 M-rows, (wid&1) owns 64 N-cols.
#define PLA 20480              // A plane bytes (256 rows * 80B)
#define PLB 10240              // B plane bytes (128 rows * 80B)
#define BUFB2 (2 * PLA + 2 * PLB)   // 61440
#define SMB2  (2 * BUFB2)           // 122880

__global__ __launch_bounds__(256, 1) void tgemm_b(
    const __nv_bfloat16* __restrict__ Ah, const __nv_bfloat16* __restrict__ Al, int lda,
    const __nv_bfloat16* __restrict__ Bh, const __nv_bfloat16* __restrict__ Bl, int ldb,
    float* __restrict__ C, int ldc, int K) {
    extern __shared__ char smb[];
    const uint32_t sbase = s2u(smb);

    const int tid = threadIdx.x;
    const int wid = tid >> 5, lane = tid & 31;
    const int g = lane >> 2, t4 = lane & 3;
    const int bm = blockIdx.y * 256, bn = blockIdx.x * 128;
    const int wm = (wid >> 1) * 64, wn = (wid & 1) * 64;

    const uint32_t aoff = (uint32_t)(wm + (lane & 15)) * 80 + ((lane >> 4) * 16);
    const uint32_t boff = (uint32_t)(wn + (lane & 7) + ((lane & 16) >> 1)) * 80
                        + (((lane >> 3) & 1) * 16);

    float acc[4][8][4];
#pragma unroll
    for (int a = 0; a < 4; ++a)
#pragma unroll
        for (int b = 0; b < 8; ++b)
#pragma unroll
            for (int c = 0; c < 4; ++c) acc[a][b][c] = 0.f;

    const int nch = K >> 5;

    auto stage = [&](int ch, int buf) {
        uint32_t base = sbase + (uint32_t)buf * BUFB2;
        int kc = ch << 5;
#pragma unroll
        for (int it = 0; it < 12; ++it) {
            int idx = tid + it * 256;          // 0..3071
            if (idx < 2048) {                  // A planes: 2 x 256 rows x 4 j
                int plane = idx >> 10;
                int rem = idx & 1023;
                int row = rem >> 2, j = rem & 3;
                const __nv_bfloat16* src = (plane ? Al : Ah) + (size_t)(bm + row) * lda + kc + j * 8;
                cpasync16(base + (uint32_t)plane * PLA + (uint32_t)row * 80 + (uint32_t)j * 16, src);
            } else {                           // B planes: 2 x 128 rows x 4 j
                int idx2 = idx - 2048;
                int plane = idx2 >> 9;
                int rem = idx2 & 511;
                int row = rem >> 2, j = rem & 3;
                const __nv_bfloat16* src = (plane ? Bl : Bh) + (size_t)(bn + row) * ldb + kc + j * 8;
                cpasync16(base + 2u * PLA + (uint32_t)plane * PLB + (uint32_t)row * 80 + (uint32_t)j * 16, src);
            }
        }
        cp_commit();
    };

    stage(0, 0);
    for (int ch = 0; ch < nch; ++ch) {
        bool more = (ch + 1 < nch);
        if (more) stage(ch + 1, (ch + 1) & 1);
        if (more) asm volatile("cp.async.wait_group 1;" ::: "memory");
        else      asm volatile("cp.async.wait_group 0;" ::: "memory");
        __syncthreads();

        const uint32_t cb = sbase + (ch & 1) * BUFB2;
        const uint32_t aH = cb + aoff;
        const uint32_t aL = cb + PLA + aoff;
        const uint32_t bH = cb + 2u * PLA + boff;
        const uint32_t bL = cb + 2u * PLA + PLB + boff;

#pragma unroll
        for (int ks = 0; ks < 2; ++ks) {
            const uint32_t kb = (uint32_t)ks * 32;
            uint32_t ah[4][4], bh[4][4];
#pragma unroll
            for (int mf = 0; mf < 4; ++mf) ldm_x4(ah[mf], aH + mf * 1280 + kb);
#pragma unroll
            for (int p = 0; p < 4; ++p) ldm_x4(bh[p], bH + p * 1280 + kb);
#pragma unroll
            for (int mf = 0; mf < 4; ++mf)
#pragma unroll
                for (int nf = 0; nf < 8; ++nf)
                    mma_bf(acc[mf][nf], ah[mf], &bh[nf >> 1][(nf & 1) * 2]);

            uint32_t al[4][4];
#pragma unroll
            for (int mf = 0; mf < 4; ++mf) ldm_x4(al[mf], aL + mf * 1280 + kb);
#pragma unroll
            for (int mf = 0; mf < 4; ++mf)
#pragma unroll
                for (int nf = 0; nf < 8; ++nf)
                    mma_bf(acc[mf][nf], al[mf], &bh[nf >> 1][(nf & 1) * 2]);

            uint32_t bl[4][4];
#pragma unroll
            for (int p = 0; p < 4; ++p) ldm_x4(bl[p], bL + p * 1280 + kb);
#pragma unroll
            for (int mf = 0; mf < 4; ++mf)
#pragma unroll
                for (int nf = 0; nf < 8; ++nf)
                    mma_bf(acc[mf][nf], ah[mf], &bl[nf >> 1][(nf & 1) * 2]);
        }
        __syncthreads();
    }

#pragma unroll
    for (int mf = 0; mf < 4; ++mf) {
#pragma unroll
        for (int half = 0; half < 2; ++half) {
            int row = bm + wm + mf * 16 + g + half * 8;
            float* cp = C + (size_t)row * ldc + bn + wn;
#pragma unroll
            for (int nf = 0; nf < 8; ++nf) {
                int col = nf * 8 + 2 * t4;
                *(float2*)(cp + col) =
                    make_float2(acc[mf][nf][half * 2 + 0], acc[mf][nf][half * 2 + 1]);
            }
        }
    }
}

// ================= tf32 single-pass GEMM (FFN), tile 256x128 ==========
#define ASTR 36
#define APLF (256 * ASTR)       // A floats (9216)
#define BPLF (128 * ASTR)       // B floats (4608)
#define BUFT2 ((APLF + BPLF) * 4)   // 55296 bytes
#define SMT2  (2 * BUFT2)           // 110592

__global__ __launch_bounds__(256, 1) void tgemm_t(
    const float* __restrict__ Ah, int lda,
    const float* __restrict__ Bh, int ldb,
    float* __restrict__ C, int ldc, int K, int epi, const float* __restrict__ res) {
    extern __shared__ float smf[];
    const uint32_t sbase = s2u(smf);

    const int tid = threadIdx.x;
    const int wid = tid >> 5, lane = tid & 31;
    const int g = lane >> 2, t4 = lane & 3;
    const int bm = blockIdx.y * 256, bn = blockIdx.x * 128;
    const int wm = (wid >> 1) * 64, wn = (wid & 1) * 64;

    float acc[4][8][4];
#pragma unroll
    for (int a = 0; a < 4; ++a)
#pragma unroll
        for (int b = 0; b < 8; ++b)
#pragma unroll
            for (int c = 0; c < 4; ++c) acc[a][b][c] = 0.f;

    const int nch = K >> 5;

    auto stage = [&](int ch, int buf) {
        uint32_t base = sbase + (uint32_t)buf * BUFT2;
        int kc = ch << 5;
#pragma unroll
        for (int it = 0; it < 12; ++it) {
            int idx = tid + it * 256;          // 0..3071
            if (idx < 2048) {                  // A: 256 rows x 8 j
                int row = idx >> 3, j = idx & 7;
                cpasync16(base + (uint32_t)row * (ASTR * 4) + (uint32_t)j * 16,
                          Ah + (size_t)(bm + row) * lda + kc + j * 4);
            } else {
                int idx2 = idx - 2048;         // B: 128 rows x 8 j
                int row = idx2 >> 3, j = idx2 & 7;
                cpasync16(base + (uint32_t)APLF * 4 + (uint32_t)row * (ASTR * 4) + (uint32_t)j * 16,
                          Bh + (size_t)(bn + row) * ldb + kc + j * 4);
            }
        }
        cp_commit();
    };

    stage(0, 0);
    for (int ch = 0; ch < nch; ++ch) {
        bool more = (ch + 1 < nch);
        if (more) stage(ch + 1, (ch + 1) & 1);
        if (more) asm volatile("cp.async.wait_group 1;" ::: "memory");
        else      asm volatile("cp.async.wait_group 0;" ::: "memory");
        __syncthreads();

        const float* As = smf + (ch & 1) * (BUFT2 / 4);
        const float* Bs = As + APLF;

#pragma unroll
        for (int ks = 0; ks < 4; ++ks) {
            const int ko = ks * 8 + t4;
            uint32_t ah[4][4], bh[8][2];
#pragma unroll
            for (int mf = 0; mf < 4; ++mf) {
                int r0 = (wm + mf * 16 + g) * ASTR + ko;
                ah[mf][0] = __float_as_uint(As[r0]);
                ah[mf][1] = __float_as_uint(As[r0 + 8 * ASTR]);
                ah[mf][2] = __float_as_uint(As[r0 + 4]);
                ah[mf][3] = __float_as_uint(As[r0 + 8 * ASTR + 4]);
            }
#pragma unroll
            for (int nf = 0; nf < 8; ++nf) {
                int rb = (wn + nf * 8 + g) * ASTR + ko;
                bh[nf][0] = __float_as_uint(Bs[rb]);
                bh[nf][1] = __float_as_uint(Bs[rb + 4]);
            }
#pragma unroll
            for (int mf = 0; mf < 4; ++mf)
#pragma unroll
                for (int nf = 0; nf < 8; ++nf)
                    mma_frag(acc[mf][nf], ah[mf], bh[nf]);
        }
        __syncthreads();
    }

#pragma unroll
    for (int mf = 0; mf < 4; ++mf) {
#pragma unroll
        for (int half = 0; half < 2; ++half) {
            int row = bm + wm + mf * 16 + g + half * 8;
            float* cp = C + (size_t)row * ldc + bn + wn;
            const float* rp = (epi == 2) ? (res + (size_t)row * ldc + bn + wn) : nullptr;
#pragma unroll
            for (int nf = 0; nf < 8; ++nf) {
                float v0 = acc[mf][nf][half * 2 + 0];
                float v1 = acc[mf][nf][half * 2 + 1];
                int col = nf * 8 + 2 * t4;
                if (epi == 1) {
                    float a = fmaxf(v0, 0.f), b = fmaxf(v1, 0.f);
                    v0 = tf32r(a * a); v1 = tf32r(b * b);
                } else if (epi == 2) {
                    v0 += rp[col]; v1 += rp[col + 1];
                }
                *(float2*)(cp + col) = make_float2(v0, v1);
            }
        }
    }
}

// ================= tensor-core flash attention (bf16x3, fused rope+rmsnorm) ======
#define ATS   72
#define QPL   (128 * ATS)
#define KPL   (64 * ATS)
#define ATT_SMEM ((2 * QPL + 8 * KPL) * 2)   // 110592 bytes

__global__ __launch_bounds__(256) void attn_tc(
    const float* __restrict__ q, const float* __restrict__ k, const float* __restrict__ v,
    const float* __restrict__ cosb, const float* __restrict__ sinb,
    __nv_bfloat16* __restrict__ outh, __nv_bfloat16* __restrict__ outl) {
    extern __shared__ __nv_bfloat16 sm[];
    const uint32_t sbase = s2u(sm);
    const int tid = threadIdx.x, wid = tid >> 5, lane = tid & 31;
    const int g = lane >> 2, t4 = lane & 3;
    const int qt = blockIdx.x, bh_ = blockIdx.y;
    const int b = bh_ / NHEADS, h = bh_ - b * NHEADS;
    const size_t base  = (size_t)b * NSEQ * QLD + (size_t)h * HD;
    const size_t obase = (size_t)b * NSEQ * DIM + (size_t)h * HD;
    const bool causal = (h >= ENC_HEADS);
    const int jmax = causal ? 2 * qt + 1 : (NSEQ / 64 - 1);
    const int wm = wid * 16;
    const float NEGINF = __int_as_float(0xff800000);

    const uint32_t qoff = (uint32_t)(wm + (lane & 15)) * 144 + ((lane >> 4) * 16);
    const uint32_t boff = (uint32_t)((lane & 7) + ((lane & 16) >> 1)) * 144
                        + (((lane >> 3) & 1) * 16);

    // stage Q: rope + per-head rmsnorm + bf16 split (warp per row, lane = freq)
    for (int rr = wid; rr < 128; rr += 8) {
        int n = qt * 128 + rr;
        float2 qv = *(const float2*)(q + base + (size_t)n * QLD + 2 * lane);
        float c = cosb[n * 32 + lane], s = sinb[n * 32 + lane];
        float r0 = qv.x * c - qv.y * s;
        float r1 = qv.x * s + qv.y * c;
        float ss = r0 * r0 + r1 * r1;
#pragma unroll
        for (int o = 16; o > 0; o >>= 1) ss += __shfl_xor_sync(0xffffffffu, ss, o);
        float inv = rsqrtf(ss * (1.f / HD) + EPSV);
        uint32_t hi, lo;
        split2(r0 * inv, r1 * inv, hi, lo);
        *(uint32_t*)(sm + rr * ATS + 2 * lane) = hi;
        *(uint32_t*)(sm + QPL + rr * ATS + 2 * lane) = lo;
    }

    auto stage = [&](int j, int buf) {
        __nv_bfloat16* Kh = sm + 2 * QPL + buf * 4 * KPL;
        __nv_bfloat16* Kl = Kh + KPL;
        __nv_bfloat16* Vh = Kh + 2 * KPL;
        __nv_bfloat16* Vl = Kh + 3 * KPL;
        for (int rr = wid; rr < 64; rr += 8) {
            int n = j * 64 + rr;
            // K: rope + rmsnorm + split
            float2 kv2 = *(const float2*)(k + base + (size_t)n * QLD + 2 * lane);
            float c = cosb[n * 32 + lane], s = sinb[n * 32 + lane];
            float r0 = kv2.x * c - kv2.y * s;
            float r1 = kv2.x * s + kv2.y * c;
            float ss = r0 * r0 + r1 * r1;
#pragma unroll
            for (int o = 16; o > 0; o >>= 1) ss += __shfl_xor_sync(0xffffffffu, ss, o);
            float inv = rsqrtf(ss * (1.f / HD) + EPSV);
            uint32_t hi, lo;
            split2(r0 * inv, r1 * inv, hi, lo);
            *(uint32_t*)(Kh + rr * ATS + 2 * lane) = hi;
            *(uint32_t*)(Kl + rr * ATS + 2 * lane) = lo;
            // V: plain split, transposed store
            float2 vv = *(const float2*)(v + base + (size_t)n * QLD + 2 * lane);
            __nv_bfloat16 v0h = __float2bfloat16(vv.x);
            __nv_bfloat16 v1h = __float2bfloat16(vv.y);
            Vh[(2 * lane) * ATS + rr]     = v0h;
            Vh[(2 * lane + 1) * ATS + rr] = v1h;
            Vl[(2 * lane) * ATS + rr]     = __float2bfloat16(vv.x - __bfloat162float(v0h));
            Vl[(2 * lane + 1) * ATS + rr] = __float2bfloat16(vv.y - __bfloat162float(v1h));
        }
    };

    stage(0, 0);
    __syncthreads();

    uint32_t aQh[4][4], aQl[4][4];
#pragma unroll
    for (int ks = 0; ks < 4; ++ks) {
        ldm_x4(aQh[ks], sbase + qoff + ks * 32);
        ldm_x4(aQl[ks], sbase + QPL * 2 + qoff + ks * 32);
    }

    float acc[8][4];
#pragma unroll
    for (int nf = 0; nf < 8; ++nf)
#pragma unroll
        for (int e = 0; e < 4; ++e) acc[nf][e] = 0.f;
    float m0 = -1e30f, m1 = -1e30f, l0 = 0.f, l1 = 0.f;

    for (int j = 0; j <= jmax; ++j) {
        if (j + 1 <= jmax) stage(j + 1, (j + 1) & 1);

        const uint32_t kvb = sbase + (2 * QPL + (j & 1) * 4 * KPL) * 2;
        const uint32_t Kb  = kvb + boff;
        const uint32_t Klb = kvb + KPL * 2 + boff;
        const uint32_t Vb  = kvb + 2 * KPL * 2 + boff;
        const uint32_t Vlb = kvb + 3 * KPL * 2 + boff;

        float s[8][4];
#pragma unroll
        for (int nf = 0; nf < 8; ++nf)
#pragma unroll
            for (int e = 0; e < 4; ++e) s[nf][e] = 0.f;

#pragma unroll
        for (int ks = 0; ks < 4; ++ks) {
            const uint32_t kb = (uint32_t)ks * 32;
            uint32_t bk[4][4];
#pragma unroll
            for (int p = 0; p < 4; ++p) ldm_x4(bk[p], Kb + p * 2304 + kb);
#pragma unroll
            for (int nf = 0; nf < 8; ++nf) {
                mma_bf(s[nf], aQh[ks], &bk[nf >> 1][(nf & 1) * 2]);
                mma_bf(s[nf], aQl[ks], &bk[nf >> 1][(nf & 1) * 2]);
            }
            uint32_t bkl[4][4];
#pragma unroll
            for (int p = 0; p < 4; ++p) ldm_x4(bkl[p], Klb + p * 2304 + kb);
#pragma unroll
            for (int nf = 0; nf < 8; ++nf)
                mma_bf(s[nf], aQh[ks], &bkl[nf >> 1][(nf & 1) * 2]);
        }

        int row0 = qt * 128 + wm + g;
        float mx0 = NEGINF, mx1 = NEGINF;
#pragma unroll
        for (int nf = 0; nf < 8; ++nf) {
            int colb = j * 64 + nf * 8 + 2 * t4;
#pragma unroll
            for (int e = 0; e < 4; ++e) {
                float val = s[nf][e] * 0.125f;
                if (causal && (colb + (e & 1)) > (row0 + (e >> 1) * 8)) val = NEGINF;
                s[nf][e] = val;
            }
            mx0 = fmaxf(mx0, fmaxf(s[nf][0], s[nf][1]));
            mx1 = fmaxf(mx1, fmaxf(s[nf][2], s[nf][3]));
        }
        mx0 = fmaxf(mx0, __shfl_xor_sync(0xffffffffu, mx0, 1));
        mx0 = fmaxf(mx0, __shfl_xor_sync(0xffffffffu, mx0, 2));
        mx1 = fmaxf(mx1, __shfl_xor_sync(0xffffffffu, mx1, 1));
        mx1 = fmaxf(mx1, __shfl_xor_sync(0xffffffffu, mx1, 2));
        float mn0 = fmaxf(m0, mx0), mn1 = fmaxf(m1, mx1);
        float c0 = expf(m0 - mn0), c1 = expf(m1 - mn1);
        float ls0 = 0.f, ls1 = 0.f;
#pragma unroll
        for (int nf = 0; nf < 8; ++nf) {
            float p0 = expf(s[nf][0] - mn0);
            float p1 = expf(s[nf][1] - mn0);
            float p2 = expf(s[nf][2] - mn1);
            float p3 = expf(s[nf][3] - mn1);
            s[nf][0] = p0; s[nf][1] = p1; s[nf][2] = p2; s[nf][3] = p3;
            ls0 += p0 + p1; ls1 += p2 + p3;
        }
        ls0 += __shfl_xor_sync(0xffffffffu, ls0, 1);
        ls0 += __shfl_xor_sync(0xffffffffu, ls0, 2);
        ls1 += __shfl_xor_sync(0xffffffffu, ls1, 1);
        ls1 += __shfl_xor_sync(0xffffffffu, ls1, 2);
        l0 = l0 * c0 + ls0;
        l1 = l1 * c1 + ls1;
        m0 = mn0; m1 = mn1;
#pragma unroll
        for (int nf = 0; nf < 8; ++nf) {
            acc[nf][0] *= c0; acc[nf][1] *= c0;
            acc[nf][2] *= c1; acc[nf][3] *= c1;
        }

#pragma unroll
        for (int ks = 0; ks < 4; ++ks) {
            const uint32_t kb = (uint32_t)ks * 32;
            uint32_t aPh[4], aPl[4];
            split2(s[2 * ks][0],     s[2 * ks][1],     aPh[0], aPl[0]);
            split2(s[2 * ks][2],     s[2 * ks][3],     aPh[1], aPl[1]);
            split2(s[2 * ks + 1][0], s[2 * ks + 1][1], aPh[2], aPl[2]);
            split2(s[2 * ks + 1][2], s[2 * ks + 1][3], aPh[3], aPl[3]);
            uint32_t bv[4][4];
#pragma unroll
            for (int p = 0; p < 4; ++p) ldm_x4(bv[p], Vb + p * 2304 + kb);
#pragma unroll
            for (int nf = 0; nf < 8; ++nf) {
                mma_bf(acc[nf], aPh, &bv[nf >> 1][(nf & 1) * 2]);
                mma_bf(acc[nf], aPl, &bv[nf >> 1][(nf & 1) * 2]);
            }
            uint32_t bvl[4][4];
#pragma unroll
            for (int p = 0; p < 4; ++p) ldm_x4(bvl[p], Vlb + p * 2304 + kb);
#pragma unroll
            for (int nf = 0; nf < 8; ++nf)
                mma_bf(acc[nf], aPh, &bvl[nf >> 1][(nf & 1) * 2]);
        }
        __syncthreads();
    }

    float iv0 = 1.f / l0, iv1 = 1.f / l1;
    int r0 = qt * 128 + wm + g, r1 = r0 + 8;
#pragma unroll
    for (int nf = 0; nf < 8; ++nf) {
        int col = nf * 8 + 2 * t4;
        uint32_t hi, lo;
        split2(acc[nf][0] * iv0, acc[nf][1] * iv0, hi, lo);
        *(uint32_t*)(outh + obase + (size_t)r0 * DIM + col) = hi;
        *(uint32_t*)(outl + obase + (size_t)r0 * DIM + col) = lo;
        split2(acc[nf][2] * iv1, acc[nf][3] * iv1, hi, lo);
        *(uint32_t*)(outh + obase + (size_t)r1 * DIM + col) = hi;
        *(uint32_t*)(outl + obase + (size_t)r1 * DIM + col) = lo;
    }
}

// ---------------- elementwise helpers ----------------
__device__ __forceinline__ float block_reduce_sum_256(float v) {
    __shared__ float sh[8];
    int lane = threadIdx.x & 31;
    int w = threadIdx.x >> 5;
#pragma unroll
    for (int o = 16; o > 0; o >>= 1) v += __shfl_xor_sync(0xffffffffu, v, o);
    if (lane == 0) sh[w] = v;
    __syncthreads();
    float r = (threadIdx.x < 8) ? sh[threadIdx.x] : 0.f;
    if (w == 0) {
#pragma unroll
        for (int o = 4; o > 0; o >>= 1) r += __shfl_xor_sync(0xffffffffu, r, o);
        if (lane == 0) sh[0] = r;
    }
    __syncthreads();
    float out = sh[0];
    __syncthreads();
    return out;
}

__global__ void splitcopy(const float* __restrict__ in, float* __restrict__ hi,
                          float* __restrict__ lo) {
    int i = blockIdx.x * 256 + threadIdx.x;
    float4 v = ((const float4*)in)[i];
    float4 h = make_float4(tf32r(v.x), tf32r(v.y), tf32r(v.z), tf32r(v.w));
    ((float4*)hi)[i] = h;
    ((float4*)lo)[i] = make_float4(tf32r(v.x - h.x), tf32r(v.y - h.y),
                                   tf32r(v.z - h.z), tf32r(v.w - h.w));
}

__global__ void splitcopy_b4(const float* __restrict__ i0, const float* __restrict__ i1,
                             const float* __restrict__ i2, const float* __restrict__ i3,
                             __nv_bfloat16* __restrict__ hi, __nv_bfloat16* __restrict__ lo,
                             int elems4_per) {
    int w = blockIdx.y;
    const float* in = (w == 0) ? i0 : (w == 1) ? i1 : (w == 2) ? i2 : i3;
    size_t obase = (size_t)w * elems4_per;
    int i = blockIdx.x * 256 + threadIdx.x;
    float4 v = ((const float4*)in)[i];
    uint32_t h0, l0, h1, l1;
    split2(v.x, v.y, h0, l0);
    split2(v.z, v.w, h1, l1);
    ((uint32_t*)hi)[(obase + i) * 2]     = h0;
    ((uint32_t*)hi)[(obase + i) * 2 + 1] = h1;
    ((uint32_t*)lo)[(obase + i) * 2]     = l0;
    ((uint32_t*)lo)[(obase + i) * 2 + 1] = l1;
}

__global__ void splitcopy_b(const float* __restrict__ in, __nv_bfloat16* __restrict__ hi,
                            __nv_bfloat16* __restrict__ lo) {
    int i = blockIdx.x * 256 + threadIdx.x;
    float4 v = ((const float4*)in)[i];
    uint32_t h0, l0, h1, l1;
    split2(v.x, v.y, h0, l0);
    split2(v.z, v.w, h1, l1);
    ((uint32_t*)hi)[i * 2]     = h0;
    ((uint32_t*)hi)[i * 2 + 1] = h1;
    ((uint32_t*)lo)[i * 2]     = l0;
    ((uint32_t*)lo)[i * 2 + 1] = l1;
}

__global__ void rmsnorm_kernel(const float* __restrict__ in,
                               __nv_bfloat16* __restrict__ oh, __nv_bfloat16* __restrict__ ol) {
    int t = blockIdx.x;
    const float* row = in + (size_t)t * DIM;
    float v0 = row[threadIdx.x];
    float v1 = row[threadIdx.x + 256];
    float v2 = row[threadIdx.x + 512];
    float ss = block_reduce_sum_256(v0 * v0 + v1 * v1 + v2 * v2);
    float inv = rsqrtf(ss * (1.f / DIM) + EPSV);
#pragma unroll
    for (int i = 0; i < 3; ++i) {
        int d = threadIdx.x + i * 256;
        float y = (i == 0 ? v0 : (i == 1 ? v1 : v2)) * inv;
        __nv_bfloat16 hb = __float2bfloat16(y);
        oh[(size_t)t * DIM + d] = hb;
        ol[(size_t)t * DIM + d] = __float2bfloat16(y - __bfloat162float(hb));
    }
}

__global__ void logits_kernel(const float* __restrict__ enc, const float* __restrict__ dec,
                              const float* __restrict__ Wp, const float* __restrict__ bp,
                              const float* __restrict__ Wpr, const float* __restrict__ bpr,
                              float* __restrict__ post, float* __restrict__ prior) {
    int t = blockIdx.x;
    int w = threadIdx.x >> 5;
    int lane = threadIdx.x & 31;
    const float* src  = (w < 4) ? enc + (size_t)t * DIM : dec + (size_t)t * DIM;
    const float* wrow = (w < 4) ? Wp + (size_t)w * DIM : Wpr + (size_t)(w - 4) * DIM;
    float s = 0.f;
    for (int i = lane; i < DIM; i += 32) s += src[i] * wrow[i];
#pragma unroll
    for (int o = 16; o > 0; o >>= 1) s += __shfl_xor_sync(0xffffffffu, s, o);
    if (lane == 0) {
        if (w < 4) post[t * 4 + w] = s + bp[w];
        else       prior[t * 4 + (w - 4)] = s + bpr[w - 4];
    }
}

__device__ __forceinline__ unsigned rotl32(unsigned x, int d) { return (x << d) | (x >> (32 - d)); }

__device__ __forceinline__ void threefry2x32_042(unsigned c0, unsigned c1, unsigned& o0, unsigned& o1) {
    const unsigned k0 = 0u, k1 = 42u;
    const unsigned k2 = k0 ^ k1 ^ 0x1BD11BDAu;
    const unsigned ks[3] = {k0, k1, k2};
    const int rot[2][4] = {{13, 15, 26, 6}, {17, 29, 16, 24}};
    unsigned x0 = c0 + k0, x1 = c1 + k1;
#pragma unroll
    for (int i = 0; i < 5; ++i) {
        const int* rr = rot[i & 1];
#pragma unroll
        for (int j = 0; j < 4; ++j) { x0 += x1; x1 = rotl32(x1, rr[j]); x1 ^= x0; }
        x0 += ks[(i + 1) % 3];
        x1 += ks[(i + 2) % 3] + (unsigned)(i + 1);
    }
    o0 = x0; o1 = x1;
}

__device__ __forceinline__ float log_sigmoid(float x) {
    return fminf(x, 0.f) - log1pf(expf(-fabsf(x)));
}

__global__ void latent_kernel(const float* __restrict__ post, const float* __restrict__ prior,
                              float* __restrict__ kl_out, float* __restrict__ klraw_out,
                              float* __restrict__ z_out, int* __restrict__ idx_out) {
    int t = blockIdx.x * blockDim.x + threadIdx.x;
    if (t >= TOK) return;
    float lsp[4], lsnp[4];
    int idx = 0;
    float klr = 0.f;
#pragma unroll
    for (int j = 0; j < 4; ++j) {
        unsigned e = (unsigned)(t * 4 + j);
        unsigned o0, o1;
        threefry2x32_042(0u, e, o0, o1);
        unsigned bits = o0 ^ o1;
        float u = __uint_as_float((bits >> 9) | 0x3f800000u) - 1.0f;
        float x = post[t * 4 + j];
        float pr = prior[t * 4 + j];
        float prob = 1.f / (1.f + expf(-x));
        if (u <= prob) idx |= (1 << j);
        lsp[j]  = log_sigmoid(x);
        lsnp[j] = log_sigmoid(-x);
        float lspr  = log_sigmoid(pr);
        float lsnpr = log_sigmoid(-pr);
        klr += prob * (lsp[j] - lspr) + (1.f - prob) * (lsnp[j] - lsnpr);
    }
    klraw_out[t] = klr;
    kl_out[t] = fmaxf(klr - 0.125f, 0.f);
    idx_out[t] = idx;
#pragma unroll
    for (int c = 0; c < 16; ++c) {
        float lg = 0.f;
#pragma unroll
        for (int j = 0; j < 4; ++j) lg += ((c >> j) & 1) ? lsp[j] : lsnp[j];
        float soft = expf(lg);
        float hard = (c == idx) ? 1.f : 0.f;
        z_out[t * 16 + c] = (hard + soft) - soft;
    }
}

__global__ void xmid_kernel(const float* __restrict__ x, const float* __restrict__ dec,
                            const float* __restrict__ Wz, const int* __restrict__ idx,
                            float* __restrict__ xmid, float* __restrict__ h) {
    int t = blockIdx.x;
    int code = idx[t];
    float v[3];
    float ss = 0.f;
#pragma unroll
    for (int i = 0; i < 3; ++i) {
        int d = threadIdx.x + i * 256;
        float val = x[(size_t)t * DIM + d] + dec[(size_t)t * DIM + d] + Wz[d * 16 + code];
        v[i] = val;
        ss += val * val;
    }
    ss = block_reduce_sum_256(ss);
    float inv = rsqrtf(ss * (1.f / DIM) + EPSV);
#pragma unroll
    for (int i = 0; i < 3; ++i) {
        int d = threadIdx.x + i * 256;
        xmid[(size_t)t * DIM + d] = v[i];
        h[(size_t)t * DIM + d]    = tf32r(v[i] * inv);
    }
}

// ---------------- launcher ----------------
extern "C" void kernel_launch(void* const* d_in, const int* in_sizes, int n_in,
                              void* d_out, int out_size) {
    const float* x     = (const float*)d_in[0];
    const float* cosb  = (const float*)d_in[1];
    const float* sinb  = (const float*)d_in[2];
    const float* Wq    = (const float*)d_in[3];
    const float* Wk    = (const float*)d_in[4];
    const float* Wv    = (const float*)d_in[5];
    const float* Wenc  = (const float*)d_in[6];
    const float* Wdec  = (const float*)d_in[7];
    const float* Wpost = (const float*)d_in[8];
    const float* bpost = (const float*)d_in[9];
    const float* Wpri  = (const float*)d_in[10];
    const float* bpri  = (const float*)d_in[11];
    const float* Wz    = (const float*)d_in[12];
    const float* Wfc1  = (const float*)d_in[13];
    const float* Wfc2  = (const float*)d_in[14];

    float *qkv, *enc, *dec, *xmid, *h, *act, *wh, *wl, *post, *prior;
    __nv_bfloat16 *xhb, *xlb, *ahb, *alb, *wbh, *wbl;
    int* idx;
    cudaGetSymbolAddress((void**)&xhb,  g_xhb);
    cudaGetSymbolAddress((void**)&xlb,  g_xlb);
    cudaGetSymbolAddress((void**)&ahb,  g_ahb);
    cudaGetSymbolAddress((void**)&alb,  g_alb);
    cudaGetSymbolAddress((void**)&wbh,  g_wbh);
    cudaGetSymbolAddress((void**)&wbl,  g_wbl);
    cudaGetSymbolAddress((void**)&qkv,  g_qkv);
    cudaGetSymbolAddress((void**)&enc,  g_enc);
    cudaGetSymbolAddress((void**)&dec,  g_dec);
    cudaGetSymbolAddress((void**)&xmid, g_xmid);
    cudaGetSymbolAddress((void**)&h,    g_h);
    cudaGetSymbolAddress((void**)&act,  g_act);
    cudaGetSymbolAddress((void**)&wh,   g_wh);
    cudaGetSymbolAddress((void**)&wl,   g_wl);
    cudaGetSymbolAddress((void**)&post, g_post);
    cudaGetSymbolAddress((void**)&prior, g_prior);
    cudaGetSymbolAddress((void**)&idx,  g_idx);

    float* out_x     = (float*)d_out;
    float* out_kl    = out_x + (size_t)TOK * DIM;
    float* out_klraw = out_kl + TOK;
    float* out_z     = out_klraw + TOK;

    cudaFuncSetAttribute(tgemm_b, cudaFuncAttributeMaxDynamicSharedMemorySize, SMB2);
    cudaFuncSetAttribute(tgemm_t, cudaFuncAttributeMaxDynamicSharedMemorySize, SMT2);
    cudaFuncSetAttribute(attn_tc, cudaFuncAttributeMaxDynamicSharedMemorySize, ATT_SMEM);

    // weight splits
    splitcopy_b4<<<dim3(576, 4), 256>>>(Wq, Wk, Wv, Wenc, wbh, wbl, 147456);
    splitcopy_b<<<288, 256>>>(Wdec, wbh + OFF_WDEC, wbl + OFF_WDEC);
    splitcopy<<<2304, 256>>>(Wfc1, wh + OFF_WFC1, wl + OFF_WFC1);
    splitcopy<<<2304, 256>>>(Wfc2, wh + OFF_WFC2, wl + OFF_WFC2);

    // rmsnorm(x) -> bf16 hi/lo
    rmsnorm_kernel<<<TOK, 256>>>(x, xhb, xlb);

    // fused QKV (bf16x3): one [16384 x 2304] GEMM, tile 256x128
    tgemm_b<<<dim3(QLD / 128, TOK / 256), 256, SMB2>>>(
        xhb, xlb, DIM, wbh + OFF_WQKV, wbl + OFF_WQKV, DIM, qkv, QLD, DIM);

    // tensor-core flash attention (rope + per-head rmsnorm fused into staging)
    attn_tc<<<dim3(NSEQ / 128, 16 * NHEADS), 256, ATT_SMEM>>>(
        qkv, qkv + 768, qkv + 1536, cosb, sinb, ahb, alb);

    // output projections (bf16x3)
    dim3 gout(DIM / 128, TOK / 256);
    tgemm_b<<<gout, 256, SMB2>>>(ahb, alb, DIM, wbh + OFF_WENC, wbl + OFF_WENC, DIM, enc, DIM, DIM);
    tgemm_b<<<gout, 256, SMB2>>>(ahb + 384, alb + 384, DIM, wbh + OFF_WDEC, wbl + OFF_WDEC, 384, dec, DIM, 384);

    // posterior / prior logits
    logits_kernel<<<TOK, 256>>>(enc, dec, Wpost, bpost, Wpri, bpri, post, prior);

    // sampling / KL / z_one_hot
    latent_kernel<<<TOK / 128, 128>>>(post, prior, out_kl, out_klraw, out_z, idx);

    // x_mid + rmsnorm
    xmid_kernel<<<TOK, 256>>>(x, dec, Wz, idx, xmid, h);

    // FFN (single-pass tf32, tile 256x128)
    tgemm_t<<<dim3(3072 / 128, TOK / 256), 256, SMT2>>>(h, DIM, wh + OFF_WFC1, DIM, act, 3072, DIM, 1, nullptr);
    tgemm_t<<<gout, 256, SMT2>>>(act, 3072, wh + OFF_WFC2, 3072, out_x, DIM, 3072, 2, xmid);
}

// round 13
// speedup vs baseline: 1.0127x; 1.0127x over previous
#include <cuda_runtime.h>
#include <cuda_bf16.h>
#include <math.h>
#include <stdint.h>

#define TOK   16384
#define DIM   768
#define NSEQ  1024
#define NHEADS 12
#define HD    64
#define ENC_HEADS 6
#define EPSV  1e-5f
#define QLD   2304            // fused qkv row stride

// fp32 (tf32-rounded) weight buffer offsets — fc only
#define OFF_WFC1 2654208
#define OFF_WFC2 5013504
#define WTOT     7372800
// bf16 plane offsets (halfs) — Wq/Wk/Wv contiguous = fused [2304 x 768]
#define OFF_WQKV 0
#define OFF_WENC 1769472
#define OFF_WDEC 2359296
#define WBTOT    2654208

// ---------------- scratch (device globals; allocation is forbidden) ----------------
__device__ __nv_bfloat16 g_xhb[TOK * DIM];
__device__ __nv_bfloat16 g_xlb[TOK * DIM];
__device__ __nv_bfloat16 g_ahb[TOK * DIM];
__device__ __nv_bfloat16 g_alb[TOK * DIM];
__device__ __nv_bfloat16 g_wbh[WBTOT];
__device__ __nv_bfloat16 g_wbl[WBTOT];
__device__ float g_qkv[TOK * QLD];
__device__ float g_enc[TOK * DIM];
__device__ float g_dec[TOK * DIM];
__device__ float g_xmid[TOK * DIM];
__device__ float g_h[TOK * DIM];
__device__ float g_act[TOK * 3072];
__device__ float g_wh[WTOT];
__device__ float g_wl[WTOT];
__device__ float g_post[TOK * 4];
__device__ float g_prior[TOK * 4];
__device__ int   g_idx[TOK];

// ---------------- small PTX helpers (all sm_80-baseline legal) ----------------
__device__ __forceinline__ uint32_t s2u(const void* p) {
    uint32_t a;
    asm("{ .reg .u64 t; cvta.to.shared.u64 t, %1; cvt.u32.u64 %0, t; }" : "=r"(a) : "l"(p));
    return a;
}
__device__ __forceinline__ uint32_t f2tf32(float v) {
    uint32_t r;
    asm("cvt.rna.tf32.f32 %0, %1;" : "=r"(r) : "f"(v));
    return r;
}
__device__ __forceinline__ float tf32r(float v) { return __uint_as_float(f2tf32(v)); }

__device__ __forceinline__ void cpasync16(uint32_t dst, const void* src) {
    asm volatile("cp.async.cg.shared.global [%0], [%1], 16;" :: "r"(dst), "l"(src));
}
__device__ __forceinline__ void cp_commit() {
    asm volatile("cp.async.commit_group;" ::: "memory");
}
__device__ __forceinline__ void mma_frag(float* d, const uint32_t* a, const uint32_t* b) {
    asm volatile(
        "mma.sync.aligned.m16n8k8.row.col.f32.tf32.tf32.f32 "
        "{%0,%1,%2,%3}, {%4,%5,%6,%7}, {%8,%9}, {%0,%1,%2,%3};"
        : "+f"(d[0]), "+f"(d[1]), "+f"(d[2]), "+f"(d[3])
        : "r"(a[0]), "r"(a[1]), "r"(a[2]), "r"(a[3]), "r"(b[0]), "r"(b[1]));
}
__device__ __forceinline__ void mma_bf(float* d, const uint32_t* a, const uint32_t* b) {
    asm volatile(
        "mma.sync.aligned.m16n8k16.row.col.f32.bf16.bf16.f32 "
        "{%0,%1,%2,%3}, {%4,%5,%6,%7}, {%8,%9}, {%0,%1,%2,%3};"
        : "+f"(d[0]), "+f"(d[1]), "+f"(d[2]), "+f"(d[3])
        : "r"(a[0]), "r"(a[1]), "r"(a[2]), "r"(a[3]), "r"(b[0]), "r"(b[1]));
}
__device__ __forceinline__ void ldm_x4(uint32_t* r, uint32_t addr) {
    asm volatile("ldmatrix.sync.aligned.m8n8.x4.shared.b16 {%0,%1,%2,%3}, [%4];"
                 : "=r"(r[0]), "=r"(r[1]), "=r"(r[2]), "=r"(r[3]) : "r"(addr));
}
__device__ __forceinline__ void split2(float a, float b, uint32_t& hi, uint32_t& lo) {
    __nv_bfloat16 ha = __float2bfloat16(a), hb = __float2bfloat16(b);
    __nv_bfloat162 H(ha, hb);
    __nv_bfloat162 L(__float2bfloat16(a - __bfloat162float(ha)),
                     __float2bfloat16(b - __bfloat162float(hb)));
    hi = *(uint32_t*)&H;
    lo = *(uint32_t*)&L;
}

// ================= bf16x3 GEMM (fp32-grade): C = A*B^T, tile 128x128, Kchunk 32 ====
#define PLANE_B 10240
#define BUF_B   (4 * PLANE_B)
#define SMB     (2 * BUF_B)       // 81920

__global__ __launch_bounds__(256, 2) void tgemm_b(
    const __nv_bfloat16* __restrict__ Ah, const __nv_bfloat16* __restrict__ Al, int lda,
    const __nv_bfloat16* __restrict__ Bh, const __nv_bfloat16* __restrict__ Bl, int ldb,
    float* __restrict__ C, int ldc, int K) {
    extern __shared__ char smb[];
    const uint32_t sbase = s2u(smb);

    const int tid = threadIdx.x;
    const int wid = tid >> 5, lane = tid & 31;
    const int g = lane >> 2, t4 = lane & 3;
    const int bm = blockIdx.y * 128, bn = blockIdx.x * 128;
    const int wm = (wid & 1) * 64, wn = (wid >> 1) * 32;

    const uint32_t aoff = (uint32_t)(wm + (lane & 15)) * 80 + ((lane >> 4) * 16);
    const uint32_t boff = (uint32_t)(wn + (lane & 7) + ((lane & 16) >> 1)) * 80
                        + (((lane >> 3) & 1) * 16);

    float acc[4][4][4];
#pragma unroll
    for (int a = 0; a < 4; ++a)
#pragma unroll
        for (int b = 0; b < 4; ++b)
#pragma unroll
            for (int c = 0; c < 4; ++c) acc[a][b][c] = 0.f;

    const int nch = K >> 5;

    auto stage = [&](int ch, int buf) {
        uint32_t base = sbase + (uint32_t)buf * BUF_B;
        int kc = ch << 5;
#pragma unroll
        for (int it = 0; it < 8; ++it) {
            int idx = tid + it * 256;
            int plane = idx >> 9;
            int rem = idx & 511;
            int row = rem >> 2, j = rem & 3;
            const __nv_bfloat16* src;
            if      (plane == 0) src = Ah + (size_t)(bm + row) * lda + kc + j * 8;
            else if (plane == 1) src = Al + (size_t)(bm + row) * lda + kc + j * 8;
            else if (plane == 2) src = Bh + (size_t)(bn + row) * ldb + kc + j * 8;
            else                 src = Bl + (size_t)(bn + row) * ldb + kc + j * 8;
            cpasync16(base + (uint32_t)plane * PLANE_B + (uint32_t)row * 80 + (uint32_t)j * 16, src);
        }
        cp_commit();
    };

    stage(0, 0);
    for (int ch = 0; ch < nch; ++ch) {
        bool more = (ch + 1 < nch);
        if (more) stage(ch + 1, (ch + 1) & 1);
        if (more) asm volatile("cp.async.wait_group 1;" ::: "memory");
        else      asm volatile("cp.async.wait_group 0;" ::: "memory");
        __syncthreads();

        const uint32_t cb = sbase + (ch & 1) * BUF_B;
        const uint32_t aH = cb + aoff;
        const uint32_t aL = cb + PLANE_B + aoff;
        const uint32_t bH = cb + 2u * PLANE_B + boff;
        const uint32_t bL = cb + 3u * PLANE_B + boff;

#pragma unroll
        for (int ks = 0; ks < 2; ++ks) {
            const uint32_t kb = (uint32_t)ks * 32;
            uint32_t ah[4][4], bh[2][4];
#pragma unroll
            for (int mf = 0; mf < 4; ++mf) ldm_x4(ah[mf], aH + mf * 1280 + kb);
#pragma unroll
            for (int p = 0; p < 2; ++p) ldm_x4(bh[p], bH + p * 1280 + kb);
#pragma unroll
            for (int mf = 0; mf < 4; ++mf)
#pragma unroll
                for (int nf = 0; nf < 4; ++nf)
                    mma_bf(acc[mf][nf], ah[mf], &bh[nf >> 1][(nf & 1) * 2]);

            uint32_t al[4][4];
#pragma unroll
            for (int mf = 0; mf < 4; ++mf) ldm_x4(al[mf], aL + mf * 1280 + kb);
#pragma unroll
            for (int mf = 0; mf < 4; ++mf)
#pragma unroll
                for (int nf = 0; nf < 4; ++nf)
                    mma_bf(acc[mf][nf], al[mf], &bh[nf >> 1][(nf & 1) * 2]);

            uint32_t bl[2][4];
#pragma unroll
            for (int p = 0; p < 2; ++p) ldm_x4(bl[p], bL + p * 1280 + kb);
#pragma unroll
            for (int mf = 0; mf < 4; ++mf)
#pragma unroll
                for (int nf = 0; nf < 4; ++nf)
                    mma_bf(acc[mf][nf], ah[mf], &bl[nf >> 1][(nf & 1) * 2]);
        }
        __syncthreads();
    }

#pragma unroll
    for (int mf = 0; mf < 4; ++mf) {
#pragma unroll
        for (int half = 0; half < 2; ++half) {
            int row = bm + wm + mf * 16 + g + half * 8;
            float* cp = C + (size_t)row * ldc + bn + wn;
#pragma unroll
            for (int nf = 0; nf < 4; ++nf) {
                int col = nf * 8 + 2 * t4;
                *(float2*)(cp + col) =
                    make_float2(acc[mf][nf][half * 2 + 0], acc[mf][nf][half * 2 + 1]);
            }
        }
    }
}

// ================= tf32 single-pass GEMM (for FFN) ==========
#define ASTR 36
#define MATF (128 * ASTR)
#define MATB (MATF * 4)
#define SM1 (2 * 2 * MATB)   // 73728

__global__ __launch_bounds__(256, 2) void tgemm_t(
    const float* __restrict__ Ah, int lda,
    const float* __restrict__ Bh, int ldb,
    float* __restrict__ C, int ldc, int K, int epi, const float* __restrict__ res) {
    extern __shared__ float smf[];
    const uint32_t sbase = s2u(smf);
    constexpr int BUFF = 2 * MATF;

    const int tid = threadIdx.x;
    const int wid = tid >> 5, lane = tid & 31;
    const int g = lane >> 2, t4 = lane & 3;
    const int bm = blockIdx.y * 128, bn = blockIdx.x * 128;
    const int wm = (wid & 1) * 64, wn = (wid >> 1) * 32;

    float acc[4][4][4];
#pragma unroll
    for (int a = 0; a < 4; ++a)
#pragma unroll
        for (int b = 0; b < 4; ++b)
#pragma unroll
            for (int c = 0; c < 4; ++c) acc[a][b][c] = 0.f;

    const int nch = K >> 5;

    auto stage = [&](int ch, int buf) {
        uint32_t base = sbase + (uint32_t)buf * (BUFF * 4);
        int kc = ch << 5;
#pragma unroll
        for (int it = 0; it < 4; ++it) {
            int idx = tid + it * 256;
            int row = idx >> 3, j = idx & 7;
            uint32_t doff = (uint32_t)row * (ASTR * 4) + (uint32_t)j * 16;
            cpasync16(base + doff, Ah + (size_t)(bm + row) * lda + kc + j * 4);
            cpasync16(base + MATB + doff, Bh + (size_t)(bn + row) * ldb + kc + j * 4);
        }
        cp_commit();
    };

    stage(0, 0);
    for (int ch = 0; ch < nch; ++ch) {
        bool more = (ch + 1 < nch);
        if (more) stage(ch + 1, (ch + 1) & 1);
        if (more) asm volatile("cp.async.wait_group 1;" ::: "memory");
        else      asm volatile("cp.async.wait_group 0;" ::: "memory");
        __syncthreads();

        const float* As = smf + (ch & 1) * BUFF;
        const float* Bs = As + MATF;

#pragma unroll
        for (int ks = 0; ks < 4; ++ks) {
            const int ko = ks * 8 + t4;
            uint32_t ah[4][4], bh[4][2];
#pragma unroll
            for (int mf = 0; mf < 4; ++mf) {
                int r0 = (wm + mf * 16 + g) * ASTR + ko;
                ah[mf][0] = __float_as_uint(As[r0]);
                ah[mf][1] = __float_as_uint(As[r0 + 8 * ASTR]);
                ah[mf][2] = __float_as_uint(As[r0 + 4]);
                ah[mf][3] = __float_as_uint(As[r0 + 8 * ASTR + 4]);
            }
#pragma unroll
            for (int nf = 0; nf < 4; ++nf) {
                int rb = (wn + nf * 8 + g) * ASTR + ko;
                bh[nf][0] = __float_as_uint(Bs[rb]);
                bh[nf][1] = __float_as_uint(Bs[rb + 4]);
            }
#pragma unroll
            for (int mf = 0; mf < 4; ++mf)
#pragma unroll
                for (int nf = 0; nf < 4; ++nf)
                    mma_frag(acc[mf][nf], ah[mf], bh[nf]);
        }
        __syncthreads();
    }

#pragma unroll
    for (int mf = 0; mf < 4; ++mf) {
#pragma unroll
        for (int half = 0; half < 2; ++half) {
            int row = bm + wm + mf * 16 + g + half * 8;
            float* cp = C + (size_t)row * ldc + bn + wn;
            const float* rp = (epi == 2) ? (res + (size_t)row * ldc + bn + wn) : nullptr;
#pragma unroll
            for (int nf = 0; nf < 4; ++nf) {
                float v0 = acc[mf][nf][half * 2 + 0];
                float v1 = acc[mf][nf][half * 2 + 1];
                int col = nf * 8 + 2 * t4;
                if (epi == 1) {
                    float a = fmaxf(v0, 0.f), b = fmaxf(v1, 0.f);
                    v0 = tf32r(a * a); v1 = tf32r(b * b);
                } else if (epi == 2) {
                    v0 += rp[col]; v1 += rp[col + 1];
                }
                *(float2*)(cp + col) = make_float2(v0, v1);
            }
        }
    }
}

// ================= tensor-core flash attention (bf16x3, fused rope+rmsnorm) ======
#define ATS   72
#define QPL   (128 * ATS)
#define KPL   (64 * ATS)
#define ATT_SMEM ((2 * QPL + 8 * KPL) * 2)   // 110592 bytes

__global__ __launch_bounds__(256) void attn_tc(
    const float* __restrict__ q, const float* __restrict__ k, const float* __restrict__ v,
    const float* __restrict__ cosb, const float* __restrict__ sinb,
    __nv_bfloat16* __restrict__ outh, __nv_bfloat16* __restrict__ outl) {
    extern __shared__ __nv_bfloat16 sm[];
    const uint32_t sbase = s2u(sm);
    const int tid = threadIdx.x, wid = tid >> 5, lane = tid & 31;
    const int g = lane >> 2, t4 = lane & 3;
    const int qt = blockIdx.x, bh_ = blockIdx.y;
    const int b = bh_ / NHEADS, h = bh_ - b * NHEADS;
    const size_t base  = (size_t)b * NSEQ * QLD + (size_t)h * HD;
    const size_t obase = (size_t)b * NSEQ * DIM + (size_t)h * HD;
    const bool causal = (h >= ENC_HEADS);
    const int jmax = causal ? 2 * qt + 1 : (NSEQ / 64 - 1);
    const int wm = wid * 16;
    const float NEGINF = __int_as_float(0xff800000);

    const uint32_t qoff = (uint32_t)(wm + (lane & 15)) * 144 + ((lane >> 4) * 16);
    const uint32_t boff = (uint32_t)((lane & 7) + ((lane & 16) >> 1)) * 144
                        + (((lane >> 3) & 1) * 16);

    // stage Q: rope + per-head rmsnorm + bf16 split (warp per row, lane = freq)
    for (int rr = wid; rr < 128; rr += 8) {
        int n = qt * 128 + rr;
        float2 qv = *(const float2*)(q + base + (size_t)n * QLD + 2 * lane);
        float c = cosb[n * 32 + lane], s = sinb[n * 32 + lane];
        float r0 = qv.x * c - qv.y * s;
        float r1 = qv.x * s + qv.y * c;
        float ss = r0 * r0 + r1 * r1;
#pragma unroll
        for (int o = 16; o > 0; o >>= 1) ss += __shfl_xor_sync(0xffffffffu, ss, o);
        float inv = rsqrtf(ss * (1.f / HD) + EPSV);
        uint32_t hi, lo;
        split2(r0 * inv, r1 * inv, hi, lo);
        *(uint32_t*)(sm + rr * ATS + 2 * lane) = hi;
        *(uint32_t*)(sm + QPL + rr * ATS + 2 * lane) = lo;
    }

    auto stage = [&](int j, int buf) {
        __nv_bfloat16* Kh = sm + 2 * QPL + buf * 4 * KPL;
        __nv_bfloat16* Kl = Kh + KPL;
        __nv_bfloat16* Vh = Kh + 2 * KPL;
        __nv_bfloat16* Vl = Kh + 3 * KPL;
        for (int rr = wid; rr < 64; rr += 8) {
            int n = j * 64 + rr;
            float2 kv2 = *(const float2*)(k + base + (size_t)n * QLD + 2 * lane);
            float c = cosb[n * 32 + lane], s = sinb[n * 32 + lane];
            float r0 = kv2.x * c - kv2.y * s;
            float r1 = kv2.x * s + kv2.y * c;
            float ss = r0 * r0 + r1 * r1;
#pragma unroll
            for (int o = 16; o > 0; o >>= 1) ss += __shfl_xor_sync(0xffffffffu, ss, o);
            float inv = rsqrtf(ss * (1.f / HD) + EPSV);
            uint32_t hi, lo;
            split2(r0 * inv, r1 * inv, hi, lo);
            *(uint32_t*)(Kh + rr * ATS + 2 * lane) = hi;
            *(uint32_t*)(Kl + rr * ATS + 2 * lane) = lo;
            float2 vv = *(const float2*)(v + base + (size_t)n * QLD + 2 * lane);
            __nv_bfloat16 v0h = __float2bfloat16(vv.x);
            __nv_bfloat16 v1h = __float2bfloat16(vv.y);
            Vh[(2 * lane) * ATS + rr]     = v0h;
            Vh[(2 * lane + 1) * ATS + rr] = v1h;
            Vl[(2 * lane) * ATS + rr]     = __float2bfloat16(vv.x - __bfloat162float(v0h));
            Vl[(2 * lane + 1) * ATS + rr] = __float2bfloat16(vv.y - __bfloat162float(v1h));
        }
    };

    stage(0, 0);
    __syncthreads();

    uint32_t aQh[4][4], aQl[4][4];
#pragma unroll
    for (int ks = 0; ks < 4; ++ks) {
        ldm_x4(aQh[ks], sbase + qoff + ks * 32);
        ldm_x4(aQl[ks], sbase + QPL * 2 + qoff + ks * 32);
    }

    float acc[8][4];
#pragma unroll
    for (int nf = 0; nf < 8; ++nf)
#pragma unroll
        for (int e = 0; e < 4; ++e) acc[nf][e] = 0.f;
    float m0 = -1e30f, m1 = -1e30f, l0 = 0.f, l1 = 0.f;

    for (int j = 0; j <= jmax; ++j) {
        if (j + 1 <= jmax) stage(j + 1, (j + 1) & 1);

        const uint32_t kvb = sbase + (2 * QPL + (j & 1) * 4 * KPL) * 2;
        const uint32_t Kb  = kvb + boff;
        const uint32_t Klb = kvb + KPL * 2 + boff;
        const uint32_t Vb  = kvb + 2 * KPL * 2 + boff;
        const uint32_t Vlb = kvb + 3 * KPL * 2 + boff;

        float s[8][4];
#pragma unroll
        for (int nf = 0; nf < 8; ++nf)
#pragma unroll
            for (int e = 0; e < 4; ++e) s[nf][e] = 0.f;

#pragma unroll
        for (int ks = 0; ks < 4; ++ks) {
            const uint32_t kb = (uint32_t)ks * 32;
            uint32_t bk[4][4];
#pragma unroll
            for (int p = 0; p < 4; ++p) ldm_x4(bk[p], Kb + p * 2304 + kb);
#pragma unroll
            for (int nf = 0; nf < 8; ++nf) {
                mma_bf(s[nf], aQh[ks], &bk[nf >> 1][(nf & 1) * 2]);
                mma_bf(s[nf], aQl[ks], &bk[nf >> 1][(nf & 1) * 2]);
            }
            uint32_t bkl[4][4];
#pragma unroll
            for (int p = 0; p < 4; ++p) ldm_x4(bkl[p], Klb + p * 2304 + kb);
#pragma unroll
            for (int nf = 0; nf < 8; ++nf)
                mma_bf(s[nf], aQh[ks], &bkl[nf >> 1][(nf & 1) * 2]);
        }

        int row0 = qt * 128 + wm + g;
        float mx0 = NEGINF, mx1 = NEGINF;
#pragma unroll
        for (int nf = 0; nf < 8; ++nf) {
            int colb = j * 64 + nf * 8 + 2 * t4;
#pragma unroll
            for (int e = 0; e < 4; ++e) {
                float val = s[nf][e] * 0.125f;
                if (causal && (colb + (e & 1)) > (row0 + (e >> 1) * 8)) val = NEGINF;
                s[nf][e] = val;
            }
            mx0 = fmaxf(mx0, fmaxf(s[nf][0], s[nf][1]));
            mx1 = fmaxf(mx1, fmaxf(s[nf][2], s[nf][3]));
        }
        mx0 = fmaxf(mx0, __shfl_xor_sync(0xffffffffu, mx0, 1));
        mx0 = fmaxf(mx0, __shfl_xor_sync(0xffffffffu, mx0, 2));
        mx1 = fmaxf(mx1, __shfl_xor_sync(0xffffffffu, mx1, 1));
        mx1 = fmaxf(mx1, __shfl_xor_sync(0xffffffffu, mx1, 2));
        float mn0 = fmaxf(m0, mx0), mn1 = fmaxf(m1, mx1);
        float c0 = expf(m0 - mn0), c1 = expf(m1 - mn1);
        float ls0 = 0.f, ls1 = 0.f;
#pragma unroll
        for (int nf = 0; nf < 8; ++nf) {
            float p0 = expf(s[nf][0] - mn0);
            float p1 = expf(s[nf][1] - mn0);
            float p2 = expf(s[nf][2] - mn1);
            float p3 = expf(s[nf][3] - mn1);
            s[nf][0] = p0; s[nf][1] = p1; s[nf][2] = p2; s[nf][3] = p3;
            ls0 += p0 + p1; ls1 += p2 + p3;
        }
        ls0 += __shfl_xor_sync(0xffffffffu, ls0, 1);
        ls0 += __shfl_xor_sync(0xffffffffu, ls0, 2);
        ls1 += __shfl_xor_sync(0xffffffffu, ls1, 1);
        ls1 += __shfl_xor_sync(0xffffffffu, ls1, 2);
        l0 = l0 * c0 + ls0;
        l1 = l1 * c1 + ls1;
        m0 = mn0; m1 = mn1;
#pragma unroll
        for (int nf = 0; nf < 8; ++nf) {
            acc[nf][0] *= c0; acc[nf][1] *= c0;
            acc[nf][2] *= c1; acc[nf][3] *= c1;
        }

#pragma unroll
        for (int ks = 0; ks < 4; ++ks) {
            const uint32_t kb = (uint32_t)ks * 32;
            uint32_t aPh[4], aPl[4];
            split2(s[2 * ks][0],     s[2 * ks][1],     aPh[0], aPl[0]);
            split2(s[2 * ks][2],     s[2 * ks][3],     aPh[1], aPl[1]);
            split2(s[2 * ks + 1][0], s[2 * ks + 1][1], aPh[2], aPl[2]);
            split2(s[2 * ks + 1][2], s[2 * ks + 1][3], aPh[3], aPl[3]);
            uint32_t bv[4][4];
#pragma unroll
            for (int p = 0; p < 4; ++p) ldm_x4(bv[p], Vb + p * 2304 + kb);
#pragma unroll
            for (int nf = 0; nf < 8; ++nf) {
                mma_bf(acc[nf], aPh, &bv[nf >> 1][(nf & 1) * 2]);
                mma_bf(acc[nf], aPl, &bv[nf >> 1][(nf & 1) * 2]);
            }
            uint32_t bvl[4][4];
#pragma unroll
            for (int p = 0; p < 4; ++p) ldm_x4(bvl[p], Vlb + p * 2304 + kb);
#pragma unroll
            for (int nf = 0; nf < 8; ++nf)
                mma_bf(acc[nf], aPh, &bvl[nf >> 1][(nf & 1) * 2]);
        }
        __syncthreads();
    }

    float iv0 = 1.f / l0, iv1 = 1.f / l1;
    int r0 = qt * 128 + wm + g, r1 = r0 + 8;
#pragma unroll
    for (int nf = 0; nf < 8; ++nf) {
        int col = nf * 8 + 2 * t4;
        uint32_t hi, lo;
        split2(acc[nf][0] * iv0, acc[nf][1] * iv0, hi, lo);
        *(uint32_t*)(outh + obase + (size_t)r0 * DIM + col) = hi;
        *(uint32_t*)(outl + obase + (size_t)r0 * DIM + col) = lo;
        split2(acc[nf][2] * iv1, acc[nf][3] * iv1, hi, lo);
        *(uint32_t*)(outh + obase + (size_t)r1 * DIM + col) = hi;
        *(uint32_t*)(outl + obase + (size_t)r1 * DIM + col) = lo;
    }
}

// ---------------- elementwise helpers ----------------
__device__ __forceinline__ float block_reduce_sum_256(float v) {
    __shared__ float sh[8];
    int lane = threadIdx.x & 31;
    int w = threadIdx.x >> 5;
#pragma unroll
    for (int o = 16; o > 0; o >>= 1) v += __shfl_xor_sync(0xffffffffu, v, o);
    if (lane == 0) sh[w] = v;
    __syncthreads();
    float r = (threadIdx.x < 8) ? sh[threadIdx.x] : 0.f;
    if (w == 0) {
#pragma unroll
        for (int o = 4; o > 0; o >>= 1) r += __shfl_xor_sync(0xffffffffu, r, o);
        if (lane == 0) sh[0] = r;
    }
    __syncthreads();
    float out = sh[0];
    __syncthreads();
    return out;
}

__global__ void splitcopy(const float* __restrict__ in, float* __restrict__ hi,
                          float* __restrict__ lo) {
    int i = blockIdx.x * 256 + threadIdx.x;
    float4 v = ((const float4*)in)[i];
    float4 h = make_float4(tf32r(v.x), tf32r(v.y), tf32r(v.z), tf32r(v.w));
    ((float4*)hi)[i] = h;
    ((float4*)lo)[i] = make_float4(tf32r(v.x - h.x), tf32r(v.y - h.y),
                                   tf32r(v.z - h.z), tf32r(v.w - h.w));
}

__global__ void splitcopy_b4(const float* __restrict__ i0, const float* __restrict__ i1,
                             const float* __restrict__ i2, const float* __restrict__ i3,
                             __nv_bfloat16* __restrict__ hi, __nv_bfloat16* __restrict__ lo,
                             int elems4_per) {
    int w = blockIdx.y;
    const float* in = (w == 0) ? i0 : (w == 1) ? i1 : (w == 2) ? i2 : i3;
    size_t obase = (size_t)w * elems4_per;
    int i = blockIdx.x * 256 + threadIdx.x;
    float4 v = ((const float4*)in)[i];
    uint32_t h0, l0, h1, l1;
    split2(v.x, v.y, h0, l0);
    split2(v.z, v.w, h1, l1);
    ((uint32_t*)hi)[(obase + i) * 2]     = h0;
    ((uint32_t*)hi)[(obase + i) * 2 + 1] = h1;
    ((uint32_t*)lo)[(obase + i) * 2]     = l0;
    ((uint32_t*)lo)[(obase + i) * 2 + 1] = l1;
}

__global__ void splitcopy_b(const float* __restrict__ in, __nv_bfloat16* __restrict__ hi,
                            __nv_bfloat16* __restrict__ lo) {
    int i = blockIdx.x * 256 + threadIdx.x;
    float4 v = ((const float4*)in)[i];
    uint32_t h0, l0, h1, l1;
    split2(v.x, v.y, h0, l0);
    split2(v.z, v.w, h1, l1);
    ((uint32_t*)hi)[i * 2]     = h0;
    ((uint32_t*)hi)[i * 2 + 1] = h1;
    ((uint32_t*)lo)[i * 2]     = l0;
    ((uint32_t*)lo)[i * 2 + 1] = l1;
}

__global__ void rmsnorm_kernel(const float* __restrict__ in,
                               __nv_bfloat16* __restrict__ oh, __nv_bfloat16* __restrict__ ol) {
    int t = blockIdx.x;
    const float* row = in + (size_t)t * DIM;
    float v0 = row[threadIdx.x];
    float v1 = row[threadIdx.x + 256];
    float v2 = row[threadIdx.x + 512];
    float ss = block_reduce_sum_256(v0 * v0 + v1 * v1 + v2 * v2);
    float inv = rsqrtf(ss * (1.f / DIM) + EPSV);
#pragma unroll
    for (int i = 0; i < 3; ++i) {
        int d = threadIdx.x + i * 256;
        float y = (i == 0 ? v0 : (i == 1 ? v1 : v2)) * inv;
        __nv_bfloat16 hb = __float2bfloat16(y);
        oh[(size_t)t * DIM + d] = hb;
        ol[(size_t)t * DIM + d] = __float2bfloat16(y - __bfloat162float(hb));
    }
}

__global__ void logits_kernel(const float* __restrict__ enc, const float* __restrict__ dec,
                              const float* __restrict__ Wp, const float* __restrict__ bp,
                              const float* __restrict__ Wpr, const float* __restrict__ bpr,
                              float* __restrict__ post, float* __restrict__ prior) {
    int t = blockIdx.x;
    int w = threadIdx.x >> 5;
    int lane = threadIdx.x & 31;
    const float* src  = (w < 4) ? enc + (size_t)t * DIM : dec + (size_t)t * DIM;
    const float* wrow = (w < 4) ? Wp + (size_t)w * DIM : Wpr + (size_t)(w - 4) * DIM;
    float s = 0.f;
    for (int i = lane; i < DIM; i += 32) s += src[i] * wrow[i];
#pragma unroll
    for (int o = 16; o > 0; o >>= 1) s += __shfl_xor_sync(0xffffffffu, s, o);
    if (lane == 0) {
        if (w < 4) post[t * 4 + w] = s + bp[w];
        else       prior[t * 4 + (w - 4)] = s + bpr[w - 4];
    }
}

__device__ __forceinline__ unsigned rotl32(unsigned x, int d) { return (x << d) | (x >> (32 - d)); }

__device__ __forceinline__ void threefry2x32_042(unsigned c0, unsigned c1, unsigned& o0, unsigned& o1) {
    const unsigned k0 = 0u, k1 = 42u;
    const unsigned k2 = k0 ^ k1 ^ 0x1BD11BDAu;
    const unsigned ks[3] = {k0, k1, k2};
    const int rot[2][4] = {{13, 15, 26, 6}, {17, 29, 16, 24}};
    unsigned x0 = c0 + k0, x1 = c1 + k1;
#pragma unroll
    for (int i = 0; i < 5; ++i) {
        const int* rr = rot[i & 1];
#pragma unroll
        for (int j = 0; j < 4; ++j) { x0 += x1; x1 = rotl32(x1, rr[j]); x1 ^= x0; }
        x0 += ks[(i + 1) % 3];
        x1 += ks[(i + 2) % 3] + (unsigned)(i + 1);
    }
    o0 = x0; o1 = x1;
}

__device__ __forceinline__ float log_sigmoid(float x) {
    return fminf(x, 0.f) - log1pf(expf(-fabsf(x)));
}

__global__ void latent_kernel(const float* __restrict__ post, const float* __restrict__ prior,
                              float* __restrict__ kl_out, float* __restrict__ klraw_out,
                              float* __restrict__ z_out, int* __restrict__ idx_out) {
    int t = blockIdx.x * blockDim.x + threadIdx.x;
    if (t >= TOK) return;
    float lsp[4], lsnp[4];
    int idx = 0;
    float klr = 0.f;
#pragma unroll
    for (int j = 0; j < 4; ++j) {
        unsigned e = (unsigned)(t * 4 + j);
        unsigned o0, o1;
        threefry2x32_042(0u, e, o0, o1);
        unsigned bits = o0 ^ o1;
        float u = __uint_as_float((bits >> 9) | 0x3f800000u) - 1.0f;
        float x = post[t * 4 + j];
        float pr = prior[t * 4 + j];
        float prob = 1.f / (1.f + expf(-x));
        if (u <= prob) idx |= (1 << j);
        lsp[j]  = log_sigmoid(x);
        lsnp[j] = log_sigmoid(-x);
        float lspr  = log_sigmoid(pr);
        float lsnpr = log_sigmoid(-pr);
        klr += prob * (lsp[j] - lspr) + (1.f - prob) * (lsnp[j] - lsnpr);
    }
    klraw_out[t] = klr;
    kl_out[t] = fmaxf(klr - 0.125f, 0.f);
    idx_out[t] = idx;
#pragma unroll
    for (int c = 0; c < 16; ++c) {
        float lg = 0.f;
#pragma unroll
        for (int j = 0; j < 4; ++j) lg += ((c >> j) & 1) ? lsp[j] : lsnp[j];
        float soft = expf(lg);
        float hard = (c == idx) ? 1.f : 0.f;
        z_out[t * 16 + c] = (hard + soft) - soft;
    }
}

__global__ void xmid_kernel(const float* __restrict__ x, const float* __restrict__ dec,
                            const float* __restrict__ Wz, const int* __restrict__ idx,
                            float* __restrict__ xmid, float* __restrict__ h) {
    int t = blockIdx.x;
    int code = idx[t];
    float v[3];
    float ss = 0.f;
#pragma unroll
    for (int i = 0; i < 3; ++i) {
        int d = threadIdx.x + i * 256;
        float val = x[(size_t)t * DIM + d] + dec[(size_t)t * DIM + d] + Wz[d * 16 + code];
        v[i] = val;
        ss += val * val;
    }
    ss = block_reduce_sum_256(ss);
    float inv = rsqrtf(ss * (1.f / DIM) + EPSV);
#pragma unroll
    for (int i = 0; i < 3; ++i) {
        int d = threadIdx.x + i * 256;
        xmid[(size_t)t * DIM + d] = v[i];
        h[(size_t)t * DIM + d]    = tf32r(v[i] * inv);
    }
}

// ---------------- launcher ----------------
extern "C" void kernel_launch(void* const* d_in, const int* in_sizes, int n_in,
                              void* d_out, int out_size) {
    const float* x     = (const float*)d_in[0];
    const float* cosb  = (const float*)d_in[1];
    const float* sinb  = (const float*)d_in[2];
    const float* Wq    = (const float*)d_in[3];
    const float* Wk    = (const float*)d_in[4];
    const float* Wv    = (const float*)d_in[5];
    const float* Wenc  = (const float*)d_in[6];
    const float* Wdec  = (const float*)d_in[7];
    const float* Wpost = (const float*)d_in[8];
    const float* bpost = (const float*)d_in[9];
    const float* Wpri  = (const float*)d_in[10];
    const float* bpri  = (const float*)d_in[11];
    const float* Wz    = (const float*)d_in[12];
    const float* Wfc1  = (const float*)d_in[13];
    const float* Wfc2  = (const float*)d_in[14];

    float *qkv, *enc, *dec, *xmid, *h, *act, *wh, *wl, *post, *prior;
    __nv_bfloat16 *xhb, *xlb, *ahb, *alb, *wbh, *wbl;
    int* idx;
    cudaGetSymbolAddress((void**)&xhb,  g_xhb);
    cudaGetSymbolAddress((void**)&xlb,  g_xlb);
    cudaGetSymbolAddress((void**)&ahb,  g_ahb);
    cudaGetSymbolAddress((void**)&alb,  g_alb);
    cudaGetSymbolAddress((void**)&wbh,  g_wbh);
    cudaGetSymbolAddress((void**)&wbl,  g_wbl);
    cudaGetSymbolAddress((void**)&qkv,  g_qkv);
    cudaGetSymbolAddress((void**)&enc,  g_enc);
    cudaGetSymbolAddress((void**)&dec,  g_dec);
    cudaGetSymbolAddress((void**)&xmid, g_xmid);
    cudaGetSymbolAddress((void**)&h,    g_h);
    cudaGetSymbolAddress((void**)&act,  g_act);
    cudaGetSymbolAddress((void**)&wh,   g_wh);
    cudaGetSymbolAddress((void**)&wl,   g_wl);
    cudaGetSymbolAddress((void**)&post, g_post);
    cudaGetSymbolAddress((void**)&prior, g_prior);
    cudaGetSymbolAddress((void**)&idx,  g_idx);

    float* out_x     = (float*)d_out;
    float* out_kl    = out_x + (size_t)TOK * DIM;
    float* out_klraw = out_kl + TOK;
    float* out_z     = out_klraw + TOK;

    cudaFuncSetAttribute(tgemm_b, cudaFuncAttributeMaxDynamicSharedMemorySize, SMB);
    cudaFuncSetAttribute(tgemm_t, cudaFuncAttributeMaxDynamicSharedMemorySize, SM1);
    cudaFuncSetAttribute(attn_tc, cudaFuncAttributeMaxDynamicSharedMemorySize, ATT_SMEM);

    // weight splits
    splitcopy_b4<<<dim3(576, 4), 256>>>(Wq, Wk, Wv, Wenc, wbh, wbl, 147456);
    splitcopy_b<<<288, 256>>>(Wdec, wbh + OFF_WDEC, wbl + OFF_WDEC);
    splitcopy<<<2304, 256>>>(Wfc1, wh + OFF_WFC1, wl + OFF_WFC1);
    splitcopy<<<2304, 256>>>(Wfc2, wh + OFF_WFC2, wl + OFF_WFC2);

    // rmsnorm(x) -> bf16 hi/lo
    rmsnorm_kernel<<<TOK, 256>>>(x, xhb, xlb);

    // fused QKV (bf16x3): one [16384 x 2304] GEMM, tile 128x128 (R11 config)
    tgemm_b<<<dim3(QLD / 128, TOK / 128), 256, SMB>>>(
        xhb, xlb, DIM, wbh + OFF_WQKV, wbl + OFF_WQKV, DIM, qkv, QLD, DIM);

    // tensor-core flash attention (rope + per-head rmsnorm fused into staging)
    attn_tc<<<dim3(NSEQ / 128, 16 * NHEADS), 256, ATT_SMEM>>>(
        qkv, qkv + 768, qkv + 1536, cosb, sinb, ahb, alb);

    // output projections (bf16x3)
    dim3 gout(DIM / 128, TOK / 128);
    tgemm_b<<<gout, 256, SMB>>>(ahb, alb, DIM, wbh + OFF_WENC, wbl + OFF_WENC, DIM, enc, DIM, DIM);
    tgemm_b<<<gout, 256, SMB>>>(ahb + 384, alb + 384, DIM, wbh + OFF_WDEC, wbl + OFF_WDEC, 384, dec, DIM, 384);

    // posterior / prior logits
    logits_kernel<<<TOK, 256>>>(enc, dec, Wpost, bpost, Wpri, bpri, post, prior);

    // sampling / KL / z_one_hot
    latent_kernel<<<TOK / 128, 128>>>(post, prior, out_kl, out_klraw, out_z, idx);

    // x_mid + rmsnorm
    xmid_kernel<<<TOK, 256>>>(x, dec, Wz, idx, xmid, h);

    // FFN (single-pass tf32, tile 128x128)
    tgemm_t<<<dim3(3072 / 128, TOK / 128), 256, SM1>>>(h, DIM, wh + OFF_WFC1, DIM, act, 3072, DIM, 1, nullptr);
    tgemm_t<<<gout, 256, SM1>>>(act, 3072, wh + OFF_WFC2, 3072, out_x, DIM, 3072, 2, xmid);
}

// round 14
// speedup vs baseline: 1.0276x; 1.0148x over previous
#include <cuda_runtime.h>
#include <cuda_bf16.h>
#include <math.h>
#include <stdint.h>

#define TOK   16384
#define DIM   768
#define NSEQ  1024
#define NHEADS 12
#define HD    64
#define ENC_HEADS 6
#define EPSV  1e-5f
#define QLD   2304            // fused qkv row stride

// bf16 plane offsets (halfs) — all weights now bf16 hi/lo planes
#define OFF_WQKV 0
#define OFF_WENC 1769472
#define OFF_WDEC 2359296
#define OFF_WFC1 2654208
#define OFF_WFC2 5013504
#define WBTOT    7372800

// ---------------- scratch (device globals; allocation is forbidden) ----------------
__device__ __nv_bfloat16 g_xhb[TOK * DIM];
__device__ __nv_bfloat16 g_xlb[TOK * DIM];
__device__ __nv_bfloat16 g_ahb[TOK * DIM];
__device__ __nv_bfloat16 g_alb[TOK * DIM];
__device__ __nv_bfloat16 g_hh[TOK * DIM];
__device__ __nv_bfloat16 g_hl[TOK * DIM];
__device__ __nv_bfloat16 g_acth[TOK * 3072];
__device__ __nv_bfloat16 g_actl[TOK * 3072];
__device__ __nv_bfloat16 g_wbh[WBTOT];
__device__ __nv_bfloat16 g_wbl[WBTOT];
__device__ float g_qkv[TOK * QLD];
__device__ float g_enc[TOK * DIM];
__device__ float g_dec[TOK * DIM];
__device__ float g_xmid[TOK * DIM];
__device__ float g_post[TOK * 4];
__device__ float g_prior[TOK * 4];
__device__ int   g_idx[TOK];

// ---------------- small PTX helpers (all sm_80-baseline legal) ----------------
__device__ __forceinline__ uint32_t s2u(const void* p) {
    uint32_t a;
    asm("{ .reg .u64 t; cvta.to.shared.u64 t, %1; cvt.u32.u64 %0, t; }" : "=r"(a) : "l"(p));
    return a;
}
__device__ __forceinline__ void cpasync16(uint32_t dst, const void* src) {
    asm volatile("cp.async.cg.shared.global [%0], [%1], 16;" :: "r"(dst), "l"(src));
}
__device__ __forceinline__ void cp_commit() {
    asm volatile("cp.async.commit_group;" ::: "memory");
}
__device__ __forceinline__ void mma_bf(float* d, const uint32_t* a, const uint32_t* b) {
    asm volatile(
        "mma.sync.aligned.m16n8k16.row.col.f32.bf16.bf16.f32 "
        "{%0,%1,%2,%3}, {%4,%5,%6,%7}, {%8,%9}, {%0,%1,%2,%3};"
        : "+f"(d[0]), "+f"(d[1]), "+f"(d[2]), "+f"(d[3])
        : "r"(a[0]), "r"(a[1]), "r"(a[2]), "r"(a[3]), "r"(b[0]), "r"(b[1]));
}
__device__ __forceinline__ void ldm_x4(uint32_t* r, uint32_t addr) {
    asm volatile("ldmatrix.sync.aligned.m8n8.x4.shared.b16 {%0,%1,%2,%3}, [%4];"
                 : "=r"(r[0]), "=r"(r[1]), "=r"(r[2]), "=r"(r[3]) : "r"(addr));
}
__device__ __forceinline__ void split2(float a, float b, uint32_t& hi, uint32_t& lo) {
    __nv_bfloat16 ha = __float2bfloat16(a), hb = __float2bfloat16(b);
    __nv_bfloat162 H(ha, hb);
    __nv_bfloat162 L(__float2bfloat16(a - __bfloat162float(ha)),
                     __float2bfloat16(b - __bfloat162float(hb)));
    hi = *(uint32_t*)&H;
    lo = *(uint32_t*)&L;
}

// ================= bf16x3 GEMM (fp32-grade): C = A*B^T, tile 128x128, Kchunk 32 ====
// epi: 0 = fp32 store; 1 = relu(v)^2 -> bf16 hi/lo planes (Ch, Cl); 2 = fp32 v+res
#define PLANE_B 10240
#define BUF_B   (4 * PLANE_B)
#define SMB     (2 * BUF_B)       // 81920

__global__ __launch_bounds__(256, 2) void tgemm_b(
    const __nv_bfloat16* __restrict__ Ah, const __nv_bfloat16* __restrict__ Al, int lda,
    const __nv_bfloat16* __restrict__ Bh, const __nv_bfloat16* __restrict__ Bl, int ldb,
    float* __restrict__ C, int ldc, int K, int epi, const float* __restrict__ res,
    __nv_bfloat16* __restrict__ Ch, __nv_bfloat16* __restrict__ Cl) {
    extern __shared__ char smb[];
    const uint32_t sbase = s2u(smb);

    const int tid = threadIdx.x;
    const int wid = tid >> 5, lane = tid & 31;
    const int g = lane >> 2, t4 = lane & 3;
    const int bm = blockIdx.y * 128, bn = blockIdx.x * 128;
    const int wm = (wid & 1) * 64, wn = (wid >> 1) * 32;

    const uint32_t aoff = (uint32_t)(wm + (lane & 15)) * 80 + ((lane >> 4) * 16);
    const uint32_t boff = (uint32_t)(wn + (lane & 7) + ((lane & 16) >> 1)) * 80
                        + (((lane >> 3) & 1) * 16);

    float acc[4][4][4];
#pragma unroll
    for (int a = 0; a < 4; ++a)
#pragma unroll
        for (int b = 0; b < 4; ++b)
#pragma unroll
            for (int c = 0; c < 4; ++c) acc[a][b][c] = 0.f;

    const int nch = K >> 5;

    auto stage = [&](int ch, int buf) {
        uint32_t base = sbase + (uint32_t)buf * BUF_B;
        int kc = ch << 5;
#pragma unroll
        for (int it = 0; it < 8; ++it) {
            int idx = tid + it * 256;
            int plane = idx >> 9;
            int rem = idx & 511;
            int row = rem >> 2, j = rem & 3;
            const __nv_bfloat16* src;
            if      (plane == 0) src = Ah + (size_t)(bm + row) * lda + kc + j * 8;
            else if (plane == 1) src = Al + (size_t)(bm + row) * lda + kc + j * 8;
            else if (plane == 2) src = Bh + (size_t)(bn + row) * ldb + kc + j * 8;
            else                 src = Bl + (size_t)(bn + row) * ldb + kc + j * 8;
            cpasync16(base + (uint32_t)plane * PLANE_B + (uint32_t)row * 80 + (uint32_t)j * 16, src);
        }
        cp_commit();
    };

    stage(0, 0);
    for (int ch = 0; ch < nch; ++ch) {
        bool more = (ch + 1 < nch);
        if (more) stage(ch + 1, (ch + 1) & 1);
        if (more) asm volatile("cp.async.wait_group 1;" ::: "memory");
        else      asm volatile("cp.async.wait_group 0;" ::: "memory");
        __syncthreads();

        const uint32_t cb = sbase + (ch & 1) * BUF_B;
        const uint32_t aH = cb + aoff;
        const uint32_t aL = cb + PLANE_B + aoff;
        const uint32_t bH = cb + 2u * PLANE_B + boff;
        const uint32_t bL = cb + 3u * PLANE_B + boff;

#pragma unroll
        for (int ks = 0; ks < 2; ++ks) {
            const uint32_t kb = (uint32_t)ks * 32;
            uint32_t ah[4][4], bh[2][4];
#pragma unroll
            for (int mf = 0; mf < 4; ++mf) ldm_x4(ah[mf], aH + mf * 1280 + kb);
#pragma unroll
            for (int p = 0; p < 2; ++p) ldm_x4(bh[p], bH + p * 1280 + kb);
#pragma unroll
            for (int mf = 0; mf < 4; ++mf)
#pragma unroll
                for (int nf = 0; nf < 4; ++nf)
                    mma_bf(acc[mf][nf], ah[mf], &bh[nf >> 1][(nf & 1) * 2]);

            uint32_t al[4][4];
#pragma unroll
            for (int mf = 0; mf < 4; ++mf) ldm_x4(al[mf], aL + mf * 1280 + kb);
#pragma unroll
            for (int mf = 0; mf < 4; ++mf)
#pragma unroll
                for (int nf = 0; nf < 4; ++nf)
                    mma_bf(acc[mf][nf], al[mf], &bh[nf >> 1][(nf & 1) * 2]);

            uint32_t bl[2][4];
#pragma unroll
            for (int p = 0; p < 2; ++p) ldm_x4(bl[p], bL + p * 1280 + kb);
#pragma unroll
            for (int mf = 0; mf < 4; ++mf)
#pragma unroll
                for (int nf = 0; nf < 4; ++nf)
                    mma_bf(acc[mf][nf], ah[mf], &bl[nf >> 1][(nf & 1) * 2]);
        }
        __syncthreads();
    }

#pragma unroll
    for (int mf = 0; mf < 4; ++mf) {
#pragma unroll
        for (int half = 0; half < 2; ++half) {
            int row = bm + wm + mf * 16 + g + half * 8;
            size_t rbase = (size_t)row * ldc + bn + wn;
            if (epi == 1) {
#pragma unroll
                for (int nf = 0; nf < 4; ++nf) {
                    int col = nf * 8 + 2 * t4;
                    float a = fmaxf(acc[mf][nf][half * 2 + 0], 0.f);
                    float b = fmaxf(acc[mf][nf][half * 2 + 1], 0.f);
                    uint32_t hi, lo;
                    split2(a * a, b * b, hi, lo);
                    *(uint32_t*)(Ch + rbase + col) = hi;
                    *(uint32_t*)(Cl + rbase + col) = lo;
                }
            } else {
                float* cp = C + rbase;
                const float* rp = (epi == 2) ? (res + rbase) : nullptr;
#pragma unroll
                for (int nf = 0; nf < 4; ++nf) {
                    float v0 = acc[mf][nf][half * 2 + 0];
                    float v1 = acc[mf][nf][half * 2 + 1];
                    int col = nf * 8 + 2 * t4;
                    if (epi == 2) { v0 += rp[col]; v1 += rp[col + 1]; }
                    *(float2*)(cp + col) = make_float2(v0, v1);
                }
            }
        }
    }
}

// ================= tensor-core flash attention (bf16x3, ldmatrix) — R11 version ===
#define ATS   72
#define QPL   (128 * ATS)
#define KPL   (64 * ATS)
#define ATT_SMEM ((2 * QPL + 8 * KPL) * 2)   // 110592 bytes

__global__ __launch_bounds__(256) void attn_tc(
    const float* __restrict__ q, const float* __restrict__ k, const float* __restrict__ v,
    __nv_bfloat16* __restrict__ outh, __nv_bfloat16* __restrict__ outl) {
    extern __shared__ __nv_bfloat16 sm[];
    const uint32_t sbase = s2u(sm);
    const int tid = threadIdx.x, wid = tid >> 5, lane = tid & 31;
    const int g = lane >> 2, t4 = lane & 3;
    const int qt = blockIdx.x, bh_ = blockIdx.y;
    const int b = bh_ / NHEADS, h = bh_ - b * NHEADS;
    const size_t base  = (size_t)b * NSEQ * QLD + (size_t)h * HD;
    const size_t obase = (size_t)b * NSEQ * DIM + (size_t)h * HD;
    const bool causal = (h >= ENC_HEADS);
    const int jmax = causal ? 2 * qt + 1 : (NSEQ / 64 - 1);
    const int wm = wid * 16;
    const float NEGINF = __int_as_float(0xff800000);

    const uint32_t qoff = (uint32_t)(wm + (lane & 15)) * 144 + ((lane >> 4) * 16);
    const uint32_t boff = (uint32_t)((lane & 7) + ((lane & 16) >> 1)) * 144
                        + (((lane >> 3) & 1) * 16);

    for (int i = tid; i < 128 * 32; i += 256) {
        int row = i >> 5, d2 = (i & 31) * 2;
        float2 qv = *(const float2*)(q + base + (size_t)(qt * 128 + row) * QLD + d2);
        uint32_t hi, lo;
        split2(qv.x, qv.y, hi, lo);
        *(uint32_t*)(sm + row * ATS + d2) = hi;
        *(uint32_t*)(sm + QPL + row * ATS + d2) = lo;
    }

    auto stage = [&](int j, int buf) {
        __nv_bfloat16* Kh = sm + 2 * QPL + buf * 4 * KPL;
        __nv_bfloat16* Kl = Kh + KPL;
        __nv_bfloat16* Vh = Kh + 2 * KPL;
        __nv_bfloat16* Vl = Kh + 3 * KPL;
        for (int i = tid; i < 64 * 64; i += 256) {
            int kv = i >> 6, d = i & 63;
            size_t gi = base + (size_t)(j * 64 + kv) * QLD + d;
            float kf = k[gi], vf = v[gi];
            __nv_bfloat16 khb = __float2bfloat16(kf);
            __nv_bfloat16 vhb = __float2bfloat16(vf);
            Kh[kv * ATS + d] = khb;
            Kl[kv * ATS + d] = __float2bfloat16(kf - __bfloat162float(khb));
            Vh[d * ATS + kv] = vhb;
            Vl[d * ATS + kv] = __float2bfloat16(vf - __bfloat162float(vhb));
        }
    };

    stage(0, 0);
    __syncthreads();

    uint32_t aQh[4][4], aQl[4][4];
#pragma unroll
    for (int ks = 0; ks < 4; ++ks) {
        ldm_x4(aQh[ks], sbase + qoff + ks * 32);
        ldm_x4(aQl[ks], sbase + QPL * 2 + qoff + ks * 32);
    }

    float acc[8][4];
#pragma unroll
    for (int nf = 0; nf < 8; ++nf)
#pragma unroll
        for (int e = 0; e < 4; ++e) acc[nf][e] = 0.f;
    float m0 = -1e30f, m1 = -1e30f, l0 = 0.f, l1 = 0.f;

    for (int j = 0; j <= jmax; ++j) {
        if (j + 1 <= jmax) stage(j + 1, (j + 1) & 1);

        const uint32_t kvb = sbase + (2 * QPL + (j & 1) * 4 * KPL) * 2;
        const uint32_t Kb  = kvb + boff;
        const uint32_t Klb = kvb + KPL * 2 + boff;
        const uint32_t Vb  = kvb + 2 * KPL * 2 + boff;
        const uint32_t Vlb = kvb + 3 * KPL * 2 + boff;

        float s[8][4];
#pragma unroll
        for (int nf = 0; nf < 8; ++nf)
#pragma unroll
            for (int e = 0; e < 4; ++e) s[nf][e] = 0.f;

#pragma unroll
        for (int ks = 0; ks < 4; ++ks) {
            const uint32_t kb = (uint32_t)ks * 32;
            uint32_t bk[4][4];
#pragma unroll
            for (int p = 0; p < 4; ++p) ldm_x4(bk[p], Kb + p * 2304 + kb);
#pragma unroll
            for (int nf = 0; nf < 8; ++nf) {
                mma_bf(s[nf], aQh[ks], &bk[nf >> 1][(nf & 1) * 2]);
                mma_bf(s[nf], aQl[ks], &bk[nf >> 1][(nf & 1) * 2]);
            }
            uint32_t bkl[4][4];
#pragma unroll
            for (int p = 0; p < 4; ++p) ldm_x4(bkl[p], Klb + p * 2304 + kb);
#pragma unroll
            for (int nf = 0; nf < 8; ++nf)
                mma_bf(s[nf], aQh[ks], &bkl[nf >> 1][(nf & 1) * 2]);
        }

        int row0 = qt * 128 + wm + g;
        float mx0 = NEGINF, mx1 = NEGINF;
#pragma unroll
        for (int nf = 0; nf < 8; ++nf) {
            int colb = j * 64 + nf * 8 + 2 * t4;
#pragma unroll
            for (int e = 0; e < 4; ++e) {
                float val = s[nf][e] * 0.125f;
                if (causal && (colb + (e & 1)) > (row0 + (e >> 1) * 8)) val = NEGINF;
                s[nf][e] = val;
            }
            mx0 = fmaxf(mx0, fmaxf(s[nf][0], s[nf][1]));
            mx1 = fmaxf(mx1, fmaxf(s[nf][2], s[nf][3]));
        }
        mx0 = fmaxf(mx0, __shfl_xor_sync(0xffffffffu, mx0, 1));
        mx0 = fmaxf(mx0, __shfl_xor_sync(0xffffffffu, mx0, 2));
        mx1 = fmaxf(mx1, __shfl_xor_sync(0xffffffffu, mx1, 1));
        mx1 = fmaxf(mx1, __shfl_xor_sync(0xffffffffu, mx1, 2));
        float mn0 = fmaxf(m0, mx0), mn1 = fmaxf(m1, mx1);
        float c0 = expf(m0 - mn0), c1 = expf(m1 - mn1);
        float ls0 = 0.f, ls1 = 0.f;
#pragma unroll
        for (int nf = 0; nf < 8; ++nf) {
            float p0 = expf(s[nf][0] - mn0);
            float p1 = expf(s[nf][1] - mn0);
            float p2 = expf(s[nf][2] - mn1);
            float p3 = expf(s[nf][3] - mn1);
            s[nf][0] = p0; s[nf][1] = p1; s[nf][2] = p2; s[nf][3] = p3;
            ls0 += p0 + p1; ls1 += p2 + p3;
        }
        ls0 += __shfl_xor_sync(0xffffffffu, ls0, 1);
        ls0 += __shfl_xor_sync(0xffffffffu, ls0, 2);
        ls1 += __shfl_xor_sync(0xffffffffu, ls1, 1);
        ls1 += __shfl_xor_sync(0xffffffffu, ls1, 2);
        l0 = l0 * c0 + ls0;
        l1 = l1 * c1 + ls1;
        m0 = mn0; m1 = mn1;
#pragma unroll
        for (int nf = 0; nf < 8; ++nf) {
            acc[nf][0] *= c0; acc[nf][1] *= c0;
            acc[nf][2] *= c1; acc[nf][3] *= c1;
        }

#pragma unroll
        for (int ks = 0; ks < 4; ++ks) {
            const uint32_t kb = (uint32_t)ks * 32;
            uint32_t aPh[4], aPl[4];
            split2(s[2 * ks][0],     s[2 * ks][1],     aPh[0], aPl[0]);
            split2(s[2 * ks][2],     s[2 * ks][3],     aPh[1], aPl[1]);
            split2(s[2 * ks + 1][0], s[2 * ks + 1][1], aPh[2], aPl[2]);
            split2(s[2 * ks + 1][2], s[2 * ks + 1][3], aPh[3], aPl[3]);
            uint32_t bv[4][4];
#pragma unroll
            for (int p = 0; p < 4; ++p) ldm_x4(bv[p], Vb + p * 2304 + kb);
#pragma unroll
            for (int nf = 0; nf < 8; ++nf) {
                mma_bf(acc[nf], aPh, &bv[nf >> 1][(nf & 1) * 2]);
                mma_bf(acc[nf], aPl, &bv[nf >> 1][(nf & 1) * 2]);
            }
            uint32_t bvl[4][4];
#pragma unroll
            for (int p = 0; p < 4; ++p) ldm_x4(bvl[p], Vlb + p * 2304 + kb);
#pragma unroll
            for (int nf = 0; nf < 8; ++nf)
                mma_bf(acc[nf], aPh, &bvl[nf >> 1][(nf & 1) * 2]);
        }
        __syncthreads();
    }

    float iv0 = 1.f / l0, iv1 = 1.f / l1;
    int r0 = qt * 128 + wm + g, r1 = r0 + 8;
#pragma unroll
    for (int nf = 0; nf < 8; ++nf) {
        int col = nf * 8 + 2 * t4;
        uint32_t hi, lo;
        split2(acc[nf][0] * iv0, acc[nf][1] * iv0, hi, lo);
        *(uint32_t*)(outh + obase + (size_t)r0 * DIM + col) = hi;
        *(uint32_t*)(outl + obase + (size_t)r0 * DIM + col) = lo;
        split2(acc[nf][2] * iv1, acc[nf][3] * iv1, hi, lo);
        *(uint32_t*)(outh + obase + (size_t)r1 * DIM + col) = hi;
        *(uint32_t*)(outl + obase + (size_t)r1 * DIM + col) = lo;
    }
}

// ---------------- elementwise helpers ----------------
__device__ __forceinline__ float block_reduce_sum_256(float v) {
    __shared__ float sh[8];
    int lane = threadIdx.x & 31;
    int w = threadIdx.x >> 5;
#pragma unroll
    for (int o = 16; o > 0; o >>= 1) v += __shfl_xor_sync(0xffffffffu, v, o);
    if (lane == 0) sh[w] = v;
    __syncthreads();
    float r = (threadIdx.x < 8) ? sh[threadIdx.x] : 0.f;
    if (w == 0) {
#pragma unroll
        for (int o = 4; o > 0; o >>= 1) r += __shfl_xor_sync(0xffffffffu, r, o);
        if (lane == 0) sh[0] = r;
    }
    __syncthreads();
    float out = sh[0];
    __syncthreads();
    return out;
}

__global__ void splitcopy_b4(const float* __restrict__ i0, const float* __restrict__ i1,
                             const float* __restrict__ i2, const float* __restrict__ i3,
                             __nv_bfloat16* __restrict__ hi, __nv_bfloat16* __restrict__ lo,
                             int elems4_per) {
    int w = blockIdx.y;
    const float* in = (w == 0) ? i0 : (w == 1) ? i1 : (w == 2) ? i2 : i3;
    size_t obase = (size_t)w * elems4_per;
    int i = blockIdx.x * 256 + threadIdx.x;
    float4 v = ((const float4*)in)[i];
    uint32_t h0, l0, h1, l1;
    split2(v.x, v.y, h0, l0);
    split2(v.z, v.w, h1, l1);
    ((uint32_t*)hi)[(obase + i) * 2]     = h0;
    ((uint32_t*)hi)[(obase + i) * 2 + 1] = h1;
    ((uint32_t*)lo)[(obase + i) * 2]     = l0;
    ((uint32_t*)lo)[(obase + i) * 2 + 1] = l1;
}

__global__ void splitcopy_b(const float* __restrict__ in, __nv_bfloat16* __restrict__ hi,
                            __nv_bfloat16* __restrict__ lo) {
    int i = blockIdx.x * 256 + threadIdx.x;
    float4 v = ((const float4*)in)[i];
    uint32_t h0, l0, h1, l1;
    split2(v.x, v.y, h0, l0);
    split2(v.z, v.w, h1, l1);
    ((uint32_t*)hi)[i * 2]     = h0;
    ((uint32_t*)hi)[i * 2 + 1] = h1;
    ((uint32_t*)lo)[i * 2]     = l0;
    ((uint32_t*)lo)[i * 2 + 1] = l1;
}

__global__ void rmsnorm_kernel(const float* __restrict__ in,
                               __nv_bfloat16* __restrict__ oh, __nv_bfloat16* __restrict__ ol) {
    int t = blockIdx.x;
    const float* row = in + (size_t)t * DIM;
    float v0 = row[threadIdx.x];
    float v1 = row[threadIdx.x + 256];
    float v2 = row[threadIdx.x + 512];
    float ss = block_reduce_sum_256(v0 * v0 + v1 * v1 + v2 * v2);
    float inv = rsqrtf(ss * (1.f / DIM) + EPSV);
#pragma unroll
    for (int i = 0; i < 3; ++i) {
        int d = threadIdx.x + i * 256;
        float y = (i == 0 ? v0 : (i == 1 ? v1 : v2)) * inv;
        __nv_bfloat16 hb = __float2bfloat16(y);
        oh[(size_t)t * DIM + d] = hb;
        ol[(size_t)t * DIM + d] = __float2bfloat16(y - __bfloat162float(hb));
    }
}

// rope + per-head rmsnorm on fused qkv (q at col 0, k at col 768), stride QLD
__global__ void rope_norm_kernel(float* __restrict__ qkv,
                                 const float* __restrict__ cosb, const float* __restrict__ sinb) {
    int t = blockIdx.x;
    float* arr = qkv + (blockIdx.y == 0 ? 0 : 768);
    int h = threadIdx.x >> 5;
    int f = threadIdx.x & 31;
    int n = t & (NSEQ - 1);
    float c = cosb[n * 32 + f];
    float s = sinb[n * 32 + f];
    float* p = arr + (size_t)t * QLD + h * HD;
    float re = p[2 * f], im = p[2 * f + 1];
    float r0 = re * c - im * s;
    float r1 = re * s + im * c;
    float ss = r0 * r0 + r1 * r1;
#pragma unroll
    for (int o = 16; o > 0; o >>= 1) ss += __shfl_xor_sync(0xffffffffu, ss, o);
    float inv = rsqrtf(ss * (1.f / HD) + EPSV);
    p[2 * f]     = r0 * inv;
    p[2 * f + 1] = r1 * inv;
}

__global__ void logits_kernel(const float* __restrict__ enc, const float* __restrict__ dec,
                              const float* __restrict__ Wp, const float* __restrict__ bp,
                              const float* __restrict__ Wpr, const float* __restrict__ bpr,
                              float* __restrict__ post, float* __restrict__ prior) {
    int t = blockIdx.x;
    int w = threadIdx.x >> 5;
    int lane = threadIdx.x & 31;
    const float* src  = (w < 4) ? enc + (size_t)t * DIM : dec + (size_t)t * DIM;
    const float* wrow = (w < 4) ? Wp + (size_t)w * DIM : Wpr + (size_t)(w - 4) * DIM;
    float s = 0.f;
    for (int i = lane; i < DIM; i += 32) s += src[i] * wrow[i];
#pragma unroll
    for (int o = 16; o > 0; o >>= 1) s += __shfl_xor_sync(0xffffffffu, s, o);
    if (lane == 0) {
        if (w < 4) post[t * 4 + w] = s + bp[w];
        else       prior[t * 4 + (w - 4)] = s + bpr[w - 4];
    }
}

__device__ __forceinline__ unsigned rotl32(unsigned x, int d) { return (x << d) | (x >> (32 - d)); }

__device__ __forceinline__ void threefry2x32_042(unsigned c0, unsigned c1, unsigned& o0, unsigned& o1) {
    const unsigned k0 = 0u, k1 = 42u;
    const unsigned k2 = k0 ^ k1 ^ 0x1BD11BDAu;
    const unsigned ks[3] = {k0, k1, k2};
    const int rot[2][4] = {{13, 15, 26, 6}, {17, 29, 16, 24}};
    unsigned x0 = c0 + k0, x1 = c1 + k1;
#pragma unroll
    for (int i = 0; i < 5; ++i) {
        const int* rr = rot[i & 1];
#pragma unroll
        for (int j = 0; j < 4; ++j) { x0 += x1; x1 = rotl32(x1, rr[j]); x1 ^= x0; }
        x0 += ks[(i + 1) % 3];
        x1 += ks[(i + 2) % 3] + (unsigned)(i + 1);
    }
    o0 = x0; o1 = x1;
}

__device__ __forceinline__ float log_sigmoid(float x) {
    return fminf(x, 0.f) - log1pf(expf(-fabsf(x)));
}

__global__ void latent_kernel(const float* __restrict__ post, const float* __restrict__ prior,
                              float* __restrict__ kl_out, float* __restrict__ klraw_out,
                              float* __restrict__ z_out, int* __restrict__ idx_out) {
    int t = blockIdx.x * blockDim.x + threadIdx.x;
    if (t >= TOK) return;
    float lsp[4], lsnp[4];
    int idx = 0;
    float klr = 0.f;
#pragma unroll
    for (int j = 0; j < 4; ++j) {
        unsigned e = (unsigned)(t * 4 + j);
        unsigned o0, o1;
        threefry2x32_042(0u, e, o0, o1);
        unsigned bits = o0 ^ o1;
        float u = __uint_as_float((bits >> 9) | 0x3f800000u) - 1.0f;
        float x = post[t * 4 + j];
        float pr = prior[t * 4 + j];
        float prob = 1.f / (1.f + expf(-x));
        if (u <= prob) idx |= (1 << j);
        lsp[j]  = log_sigmoid(x);
        lsnp[j] = log_sigmoid(-x);
        float lspr  = log_sigmoid(pr);
        float lsnpr = log_sigmoid(-pr);
        klr += prob * (lsp[j] - lspr) + (1.f - prob) * (lsnp[j] - lsnpr);
    }
    klraw_out[t] = klr;
    kl_out[t] = fmaxf(klr - 0.125f, 0.f);
    idx_out[t] = idx;
#pragma unroll
    for (int c = 0; c < 16; ++c) {
        float lg = 0.f;
#pragma unroll
        for (int j = 0; j < 4; ++j) lg += ((c >> j) & 1) ? lsp[j] : lsnp[j];
        float soft = expf(lg);
        float hard = (c == idx) ? 1.f : 0.f;
        z_out[t * 16 + c] = (hard + soft) - soft;
    }
}

// x_mid = x + dec_out + W_z[:, idx];  h = rmsnorm(x_mid) -> bf16 hi/lo planes
__global__ void xmid_kernel(const float* __restrict__ x, const float* __restrict__ dec,
                            const float* __restrict__ Wz, const int* __restrict__ idx,
                            float* __restrict__ xmid,
                            __nv_bfloat16* __restrict__ hh, __nv_bfloat16* __restrict__ hl) {
    int t = blockIdx.x;
    int code = idx[t];
    float v[3];
    float ss = 0.f;
#pragma unroll
    for (int i = 0; i < 3; ++i) {
        int d = threadIdx.x + i * 256;
        float val = x[(size_t)t * DIM + d] + dec[(size_t)t * DIM + d] + Wz[d * 16 + code];
        v[i] = val;
        ss += val * val;
    }
    ss = block_reduce_sum_256(ss);
    float inv = rsqrtf(ss * (1.f / DIM) + EPSV);
#pragma unroll
    for (int i = 0; i < 3; ++i) {
        int d = threadIdx.x + i * 256;
        xmid[(size_t)t * DIM + d] = v[i];
        float y = v[i] * inv;
        __nv_bfloat16 hb = __float2bfloat16(y);
        hh[(size_t)t * DIM + d] = hb;
        hl[(size_t)t * DIM + d] = __float2bfloat16(y - __bfloat162float(hb));
    }
}

// ---------------- launcher ----------------
extern "C" void kernel_launch(void* const* d_in, const int* in_sizes, int n_in,
                              void* d_out, int out_size) {
    const float* x     = (const float*)d_in[0];
    const float* cosb  = (const float*)d_in[1];
    const float* sinb  = (const float*)d_in[2];
    const float* Wq    = (const float*)d_in[3];
    const float* Wk    = (const float*)d_in[4];
    const float* Wv    = (const float*)d_in[5];
    const float* Wenc  = (const float*)d_in[6];
    const float* Wdec  = (const float*)d_in[7];
    const float* Wpost = (const float*)d_in[8];
    const float* bpost = (const float*)d_in[9];
    const float* Wpri  = (const float*)d_in[10];
    const float* bpri  = (const float*)d_in[11];
    const float* Wz    = (const float*)d_in[12];
    const float* Wfc1  = (const float*)d_in[13];
    const float* Wfc2  = (const float*)d_in[14];

    float *qkv, *enc, *dec, *xmid, *post, *prior;
    __nv_bfloat16 *xhb, *xlb, *ahb, *alb, *wbh, *wbl, *hh, *hl, *acth, *actl;
    int* idx;
    cudaGetSymbolAddress((void**)&xhb,  g_xhb);
    cudaGetSymbolAddress((void**)&xlb,  g_xlb);
    cudaGetSymbolAddress((void**)&ahb,  g_ahb);
    cudaGetSymbolAddress((void**)&alb,  g_alb);
    cudaGetSymbolAddress((void**)&wbh,  g_wbh);
    cudaGetSymbolAddress((void**)&wbl,  g_wbl);
    cudaGetSymbolAddress((void**)&hh,   g_hh);
    cudaGetSymbolAddress((void**)&hl,   g_hl);
    cudaGetSymbolAddress((void**)&acth, g_acth);
    cudaGetSymbolAddress((void**)&actl, g_actl);
    cudaGetSymbolAddress((void**)&qkv,  g_qkv);
    cudaGetSymbolAddress((void**)&enc,  g_enc);
    cudaGetSymbolAddress((void**)&dec,  g_dec);
    cudaGetSymbolAddress((void**)&xmid, g_xmid);
    cudaGetSymbolAddress((void**)&post, g_post);
    cudaGetSymbolAddress((void**)&prior, g_prior);
    cudaGetSymbolAddress((void**)&idx,  g_idx);

    float* out_x     = (float*)d_out;
    float* out_kl    = out_x + (size_t)TOK * DIM;
    float* out_klraw = out_kl + TOK;
    float* out_z     = out_klraw + TOK;

    cudaFuncSetAttribute(tgemm_b, cudaFuncAttributeMaxDynamicSharedMemorySize, SMB);
    cudaFuncSetAttribute(attn_tc, cudaFuncAttributeMaxDynamicSharedMemorySize, ATT_SMEM);

    // weight splits (all bf16 hi/lo planes)
    splitcopy_b4<<<dim3(576, 4), 256>>>(Wq, Wk, Wv, Wenc, wbh, wbl, 147456);
    splitcopy_b<<<288, 256>>>(Wdec, wbh + OFF_WDEC, wbl + OFF_WDEC);
    splitcopy_b<<<2304, 256>>>(Wfc1, wbh + OFF_WFC1, wbl + OFF_WFC1);
    splitcopy_b<<<2304, 256>>>(Wfc2, wbh + OFF_WFC2, wbl + OFF_WFC2);

    // rmsnorm(x) -> bf16 hi/lo
    rmsnorm_kernel<<<TOK, 256>>>(x, xhb, xlb);

    // fused QKV (bf16x3): one [16384 x 2304] GEMM, tile 128x128 (R11 config)
    tgemm_b<<<dim3(QLD / 128, TOK / 128), 256, SMB>>>(
        xhb, xlb, DIM, wbh + OFF_WQKV, wbl + OFF_WQKV, DIM, qkv, QLD, DIM,
        0, nullptr, nullptr, nullptr);

    // rope + per-head rmsnorm on fused qkv (separate kernel — R11 config)
    rope_norm_kernel<<<dim3(TOK, 2), 384>>>(qkv, cosb, sinb);

    // tensor-core flash attention (R11 version)
    attn_tc<<<dim3(NSEQ / 128, 16 * NHEADS), 256, ATT_SMEM>>>(
        qkv, qkv + 768, qkv + 1536, ahb, alb);

    // output projections (bf16x3)
    dim3 gout(DIM / 128, TOK / 128);
    tgemm_b<<<gout, 256, SMB>>>(ahb, alb, DIM, wbh + OFF_WENC, wbl + OFF_WENC, DIM,
                                enc, DIM, DIM, 0, nullptr, nullptr, nullptr);
    tgemm_b<<<gout, 256, SMB>>>(ahb + 384, alb + 384, DIM, wbh + OFF_WDEC, wbl + OFF_WDEC, 384,
                                dec, DIM, 384, 0, nullptr, nullptr, nullptr);

    // posterior / prior logits
    logits_kernel<<<TOK, 256>>>(enc, dec, Wpost, bpost, Wpri, bpri, post, prior);

    // sampling / KL / z_one_hot
    latent_kernel<<<TOK / 128, 128>>>(post, prior, out_kl, out_klraw, out_z, idx);

    // x_mid + rmsnorm -> bf16 planes
    xmid_kernel<<<TOK, 256>>>(x, dec, Wz, idx, xmid, hh, hl);

    // FFN via bf16x3 (fp32-grade, 25% fewer mma than tf32 path)
    tgemm_b<<<dim3(3072 / 128, TOK / 128), 256, SMB>>>(
        hh, hl, DIM, wbh + OFF_WFC1, wbl + OFF_WFC1, DIM,
        nullptr, 3072, DIM, 1, nullptr, acth, actl);
    tgemm_b<<<gout, 256, SMB>>>(
        acth, actl, 3072, wbh + OFF_WFC2, wbl + OFF_WFC2, 3072,
        out_x, DIM, 3072, 2, xmid, nullptr, nullptr);
}

// round 15
// speedup vs baseline: 1.1397x; 1.1090x over previous
#include <cuda_runtime.h>
#include <cuda_bf16.h>
#include <math.h>
#include <stdint.h>

#define TOK   16384
#define DIM   768
#define NSEQ  1024
#define NHEADS 12
#define HD    64
#define ENC_HEADS 6
#define EPSV  1e-5f
#define QLD   2304            // fused qkv row stride

// fp32 (tf32-rounded) weight buffer offsets — fc only
#define OFF_WFC1 2654208
#define OFF_WFC2 5013504
#define WTOT     7372800
// bf16 plane offsets (halfs) — Wq/Wk/Wv contiguous = fused [2304 x 768]
#define OFF_WQKV 0
#define OFF_WENC 1769472
#define OFF_WDEC 2359296
#define WBTOT    2654208

// ---------------- scratch (device globals; allocation is forbidden) ----------------
__device__ __nv_bfloat16 g_xhb[TOK * DIM];
__device__ __nv_bfloat16 g_xlb[TOK * DIM];
__device__ __nv_bfloat16 g_ahb[TOK * DIM];
__device__ __nv_bfloat16 g_alb[TOK * DIM];
__device__ __nv_bfloat16 g_wbh[WBTOT];
__device__ __nv_bfloat16 g_wbl[WBTOT];
__device__ float g_qkv[TOK * QLD];
__device__ float g_enc[TOK * DIM];
__device__ float g_dec[TOK * DIM];
__device__ float g_xmid[TOK * DIM];
__device__ float g_h[TOK * DIM];
__device__ float g_act[TOK * 3072];
__device__ float g_wh[WTOT];
__device__ float g_wl[WTOT];
__device__ float g_post[TOK * 4];
__device__ float g_prior[TOK * 4];
__device__ int   g_idx[TOK];

// ---------------- small PTX helpers (all sm_80-baseline legal) ----------------
__device__ __forceinline__ uint32_t s2u(const void* p) {
    uint32_t a;
    asm("{ .reg .u64 t; cvta.to.shared.u64 t, %1; cvt.u32.u64 %0, t; }" : "=r"(a) : "l"(p));
    return a;
}
__device__ __forceinline__ uint32_t f2tf32(float v) {
    uint32_t r;
    asm("cvt.rna.tf32.f32 %0, %1;" : "=r"(r) : "f"(v));
    return r;
}
__device__ __forceinline__ float tf32r(float v) { return __uint_as_float(f2tf32(v)); }

__device__ __forceinline__ void cpasync16(uint32_t dst, const void* src) {
    asm volatile("cp.async.cg.shared.global [%0], [%1], 16;" :: "r"(dst), "l"(src));
}
__device__ __forceinline__ void cp_commit() {
    asm volatile("cp.async.commit_group;" ::: "memory");
}
__device__ __forceinline__ void mma_frag(float* d, const uint32_t* a, const uint32_t* b) {
    asm volatile(
        "mma.sync.aligned.m16n8k8.row.col.f32.tf32.tf32.f32 "
        "{%0,%1,%2,%3}, {%4,%5,%6,%7}, {%8,%9}, {%0,%1,%2,%3};"
        : "+f"(d[0]), "+f"(d[1]), "+f"(d[2]), "+f"(d[3])
        : "r"(a[0]), "r"(a[1]), "r"(a[2]), "r"(a[3]), "r"(b[0]), "r"(b[1]));
}
__device__ __forceinline__ void mma_bf(float* d, const uint32_t* a, const uint32_t* b) {
    asm volatile(
        "mma.sync.aligned.m16n8k16.row.col.f32.bf16.bf16.f32 "
        "{%0,%1,%2,%3}, {%4,%5,%6,%7}, {%8,%9}, {%0,%1,%2,%3};"
        : "+f"(d[0]), "+f"(d[1]), "+f"(d[2]), "+f"(d[3])
        : "r"(a[0]), "r"(a[1]), "r"(a[2]), "r"(a[3]), "r"(b[0]), "r"(b[1]));
}
__device__ __forceinline__ void ldm_x4(uint32_t* r, uint32_t addr) {
    asm volatile("ldmatrix.sync.aligned.m8n8.x4.shared.b16 {%0,%1,%2,%3}, [%4];"
                 : "=r"(r[0]), "=r"(r[1]), "=r"(r[2]), "=r"(r[3]) : "r"(addr));
}
__device__ __forceinline__ void split2(float a, float b, uint32_t& hi, uint32_t& lo) {
    __nv_bfloat16 ha = __float2bfloat16(a), hb = __float2bfloat16(b);
    __nv_bfloat162 H(ha, hb);
    __nv_bfloat162 L(__float2bfloat16(a - __bfloat162float(ha)),
                     __float2bfloat16(b - __bfloat162float(hb)));
    hi = *(uint32_t*)&H;
    lo = *(uint32_t*)&L;
}

// ================= bf16x3 GEMM (fp32-grade): C = A*B^T, tile 128x128, Kchunk 32 ====
#define PLANE_B 10240
#define BUF_B   (4 * PLANE_B)
#define SMB     (2 * BUF_B)       // 81920

__global__ __launch_bounds__(256, 2) void tgemm_b(
    const __nv_bfloat16* __restrict__ Ah, const __nv_bfloat16* __restrict__ Al, int lda,
    const __nv_bfloat16* __restrict__ Bh, const __nv_bfloat16* __restrict__ Bl, int ldb,
    float* __restrict__ C, int ldc, int K) {
    extern __shared__ char smb[];
    const uint32_t sbase = s2u(smb);

    const int tid = threadIdx.x;
    const int wid = tid >> 5, lane = tid & 31;
    const int g = lane >> 2, t4 = lane & 3;
    const int bm = blockIdx.y * 128, bn = blockIdx.x * 128;
    const int wm = (wid & 1) * 64, wn = (wid >> 1) * 32;

    const uint32_t aoff = (uint32_t)(wm + (lane & 15)) * 80 + ((lane >> 4) * 16);
    const uint32_t boff = (uint32_t)(wn + (lane & 7) + ((lane & 16) >> 1)) * 80
                        + (((lane >> 3) & 1) * 16);

    float acc[4][4][4];
#pragma unroll
    for (int a = 0; a < 4; ++a)
#pragma unroll
        for (int b = 0; b < 4; ++b)
#pragma unroll
            for (int c = 0; c < 4; ++c) acc[a][b][c] = 0.f;

    const int nch = K >> 5;

    auto stage = [&](int ch, int buf) {
        uint32_t base = sbase + (uint32_t)buf * BUF_B;
        int kc = ch << 5;
#pragma unroll
        for (int it = 0; it < 8; ++it) {
            int idx = tid + it * 256;
            int plane = idx >> 9;
            int rem = idx & 511;
            int row = rem >> 2, j = rem & 3;
            const __nv_bfloat16* src;
            if      (plane == 0) src = Ah + (size_t)(bm + row) * lda + kc + j * 8;
            else if (plane == 1) src = Al + (size_t)(bm + row) * lda + kc + j * 8;
            else if (plane == 2) src = Bh + (size_t)(bn + row) * ldb + kc + j * 8;
            else                 src = Bl + (size_t)(bn + row) * ldb + kc + j * 8;
            cpasync16(base + (uint32_t)plane * PLANE_B + (uint32_t)row * 80 + (uint32_t)j * 16, src);
        }
        cp_commit();
    };

    stage(0, 0);
    for (int ch = 0; ch < nch; ++ch) {
        bool more = (ch + 1 < nch);
        if (more) stage(ch + 1, (ch + 1) & 1);
        if (more) asm volatile("cp.async.wait_group 1;" ::: "memory");
        else      asm volatile("cp.async.wait_group 0;" ::: "memory");
        __syncthreads();

        const uint32_t cb = sbase + (ch & 1) * BUF_B;
        const uint32_t aH = cb + aoff;
        const uint32_t aL = cb + PLANE_B + aoff;
        const uint32_t bH = cb + 2u * PLANE_B + boff;
        const uint32_t bL = cb + 3u * PLANE_B + boff;

#pragma unroll
        for (int ks = 0; ks < 2; ++ks) {
            const uint32_t kb = (uint32_t)ks * 32;
            uint32_t ah[4][4], bh[2][4];
#pragma unroll
            for (int mf = 0; mf < 4; ++mf) ldm_x4(ah[mf], aH + mf * 1280 + kb);
#pragma unroll
            for (int p = 0; p < 2; ++p) ldm_x4(bh[p], bH + p * 1280 + kb);
#pragma unroll
            for (int mf = 0; mf < 4; ++mf)
#pragma unroll
                for (int nf = 0; nf < 4; ++nf)
                    mma_bf(acc[mf][nf], ah[mf], &bh[nf >> 1][(nf & 1) * 2]);

            uint32_t al[4][4];
#pragma unroll
            for (int mf = 0; mf < 4; ++mf) ldm_x4(al[mf], aL + mf * 1280 + kb);
#pragma unroll
            for (int mf = 0; mf < 4; ++mf)
#pragma unroll
                for (int nf = 0; nf < 4; ++nf)
                    mma_bf(acc[mf][nf], al[mf], &bh[nf >> 1][(nf & 1) * 2]);

            uint32_t bl[2][4];
#pragma unroll
            for (int p = 0; p < 2; ++p) ldm_x4(bl[p], bL + p * 1280 + kb);
#pragma unroll
            for (int mf = 0; mf < 4; ++mf)
#pragma unroll
                for (int nf = 0; nf < 4; ++nf)
                    mma_bf(acc[mf][nf], ah[mf], &bl[nf >> 1][(nf & 1) * 2]);
        }
        __syncthreads();
    }

#pragma unroll
    for (int mf = 0; mf < 4; ++mf) {
#pragma unroll
        for (int half = 0; half < 2; ++half) {
            int row = bm + wm + mf * 16 + g + half * 8;
            float* cp = C + (size_t)row * ldc + bn + wn;
#pragma unroll
            for (int nf = 0; nf < 4; ++nf) {
                int col = nf * 8 + 2 * t4;
                *(float2*)(cp + col) =
                    make_float2(acc[mf][nf][half * 2 + 0], acc[mf][nf][half * 2 + 1]);
            }
        }
    }
}

// ================= tf32 single-pass GEMM (for FFN) ==========
#define ASTR 36
#define MATF (128 * ASTR)
#define MATB (MATF * 4)
#define SM1 (2 * 2 * MATB)   // 73728

__global__ __launch_bounds__(256, 2) void tgemm_t(
    const float* __restrict__ Ah, int lda,
    const float* __restrict__ Bh, int ldb,
    float* __restrict__ C, int ldc, int K, int epi, const float* __restrict__ res) {
    extern __shared__ float smf[];
    const uint32_t sbase = s2u(smf);
    constexpr int BUFF = 2 * MATF;

    const int tid = threadIdx.x;
    const int wid = tid >> 5, lane = tid & 31;
    const int g = lane >> 2, t4 = lane & 3;
    const int bm = blockIdx.y * 128, bn = blockIdx.x * 128;
    const int wm = (wid & 1) * 64, wn = (wid >> 1) * 32;

    float acc[4][4][4];
#pragma unroll
    for (int a = 0; a < 4; ++a)
#pragma unroll
        for (int b = 0; b < 4; ++b)
#pragma unroll
            for (int c = 0; c < 4; ++c) acc[a][b][c] = 0.f;

    const int nch = K >> 5;

    auto stage = [&](int ch, int buf) {
        uint32_t base = sbase + (uint32_t)buf * (BUFF * 4);
        int kc = ch << 5;
#pragma unroll
        for (int it = 0; it < 4; ++it) {
            int idx = tid + it * 256;
            int row = idx >> 3, j = idx & 7;
            uint32_t doff = (uint32_t)row * (ASTR * 4) + (uint32_t)j * 16;
            cpasync16(base + doff, Ah + (size_t)(bm + row) * lda + kc + j * 4);
            cpasync16(base + MATB + doff, Bh + (size_t)(bn + row) * ldb + kc + j * 4);
        }
        cp_commit();
    };

    stage(0, 0);
    for (int ch = 0; ch < nch; ++ch) {
        bool more = (ch + 1 < nch);
        if (more) stage(ch + 1, (ch + 1) & 1);
        if (more) asm volatile("cp.async.wait_group 1;" ::: "memory");
        else      asm volatile("cp.async.wait_group 0;" ::: "memory");
        __syncthreads();

        const float* As = smf + (ch & 1) * BUFF;
        const float* Bs = As + MATF;

#pragma unroll
        for (int ks = 0; ks < 4; ++ks) {
            const int ko = ks * 8 + t4;
            uint32_t ah[4][4], bh[4][2];
#pragma unroll
            for (int mf = 0; mf < 4; ++mf) {
                int r0 = (wm + mf * 16 + g) * ASTR + ko;
                ah[mf][0] = __float_as_uint(As[r0]);
                ah[mf][1] = __float_as_uint(As[r0 + 8 * ASTR]);
                ah[mf][2] = __float_as_uint(As[r0 + 4]);
                ah[mf][3] = __float_as_uint(As[r0 + 8 * ASTR + 4]);
            }
#pragma unroll
            for (int nf = 0; nf < 4; ++nf) {
                int rb = (wn + nf * 8 + g) * ASTR + ko;
                bh[nf][0] = __float_as_uint(Bs[rb]);
                bh[nf][1] = __float_as_uint(Bs[rb + 4]);
            }
#pragma unroll
            for (int mf = 0; mf < 4; ++mf)
#pragma unroll
                for (int nf = 0; nf < 4; ++nf)
                    mma_frag(acc[mf][nf], ah[mf], bh[nf]);
        }
        __syncthreads();
    }

#pragma unroll
    for (int mf = 0; mf < 4; ++mf) {
#pragma unroll
        for (int half = 0; half < 2; ++half) {
            int row = bm + wm + mf * 16 + g + half * 8;
            float* cp = C + (size_t)row * ldc + bn + wn;
            const float* rp = (epi == 2) ? (res + (size_t)row * ldc + bn + wn) : nullptr;
#pragma unroll
            for (int nf = 0; nf < 4; ++nf) {
                float v0 = acc[mf][nf][half * 2 + 0];
                float v1 = acc[mf][nf][half * 2 + 1];
                int col = nf * 8 + 2 * t4;
                if (epi == 1) {
                    float a = fmaxf(v0, 0.f), b = fmaxf(v1, 0.f);
                    v0 = tf32r(a * a); v1 = tf32r(b * b);
                } else if (epi == 2) {
                    v0 += rp[col]; v1 += rp[col + 1];
                }
                *(float2*)(cp + col) = make_float2(v0, v1);
            }
        }
    }
}

// ================= tensor-core flash attention (bf16x3, ldmatrix) — R11 version ===
#define ATS   72
#define QPL   (128 * ATS)
#define KPL   (64 * ATS)
#define ATT_SMEM ((2 * QPL + 8 * KPL) * 2)   // 110592 bytes

__global__ __launch_bounds__(256) void attn_tc(
    const float* __restrict__ q, const float* __restrict__ k, const float* __restrict__ v,
    __nv_bfloat16* __restrict__ outh, __nv_bfloat16* __restrict__ outl) {
    extern __shared__ __nv_bfloat16 sm[];
    const uint32_t sbase = s2u(sm);
    const int tid = threadIdx.x, wid = tid >> 5, lane = tid & 31;
    const int g = lane >> 2, t4 = lane & 3;
    const int qt = blockIdx.x, bh_ = blockIdx.y;
    const int b = bh_ / NHEADS, h = bh_ - b * NHEADS;
    const size_t base  = (size_t)b * NSEQ * QLD + (size_t)h * HD;
    const size_t obase = (size_t)b * NSEQ * DIM + (size_t)h * HD;
    const bool causal = (h >= ENC_HEADS);
    const int jmax = causal ? 2 * qt + 1 : (NSEQ / 64 - 1);
    const int wm = wid * 16;
    const float NEGINF = __int_as_float(0xff800000);

    const uint32_t qoff = (uint32_t)(wm + (lane & 15)) * 144 + ((lane >> 4) * 16);
    const uint32_t boff = (uint32_t)((lane & 7) + ((lane & 16) >> 1)) * 144
                        + (((lane >> 3) & 1) * 16);

    for (int i = tid; i < 128 * 32; i += 256) {
        int row = i >> 5, d2 = (i & 31) * 2;
        float2 qv = *(const float2*)(q + base + (size_t)(qt * 128 + row) * QLD + d2);
        uint32_t hi, lo;
        split2(qv.x, qv.y, hi, lo);
        *(uint32_t*)(sm + row * ATS + d2) = hi;
        *(uint32_t*)(sm + QPL + row * ATS + d2) = lo;
    }

    auto stage = [&](int j, int buf) {
        __nv_bfloat16* Kh = sm + 2 * QPL + buf * 4 * KPL;
        __nv_bfloat16* Kl = Kh + KPL;
        __nv_bfloat16* Vh = Kh + 2 * KPL;
        __nv_bfloat16* Vl = Kh + 3 * KPL;
        for (int i = tid; i < 64 * 64; i += 256) {
            int kv = i >> 6, d = i & 63;
            size_t gi = base + (size_t)(j * 64 + kv) * QLD + d;
            float kf = k[gi], vf = v[gi];
            __nv_bfloat16 khb = __float2bfloat16(kf);
            __nv_bfloat16 vhb = __float2bfloat16(vf);
            Kh[kv * ATS + d] = khb;
            Kl[kv * ATS + d] = __float2bfloat16(kf - __bfloat162float(khb));
            Vh[d * ATS + kv] = vhb;
            Vl[d * ATS + kv] = __float2bfloat16(vf - __bfloat162float(vhb));
        }
    };

    stage(0, 0);
    __syncthreads();

    uint32_t aQh[4][4], aQl[4][4];
#pragma unroll
    for (int ks = 0; ks < 4; ++ks) {
        ldm_x4(aQh[ks], sbase + qoff + ks * 32);
        ldm_x4(aQl[ks], sbase + QPL * 2 + qoff + ks * 32);
    }

    float acc[8][4];
#pragma unroll
    for (int nf = 0; nf < 8; ++nf)
#pragma unroll
        for (int e = 0; e < 4; ++e) acc[nf][e] = 0.f;
    float m0 = -1e30f, m1 = -1e30f, l0 = 0.f, l1 = 0.f;

    for (int j = 0; j <= jmax; ++j) {
        if (j + 1 <= jmax) stage(j + 1, (j + 1) & 1);

        const uint32_t kvb = sbase + (2 * QPL + (j & 1) * 4 * KPL) * 2;
        const uint32_t Kb  = kvb + boff;
        const uint32_t Klb = kvb + KPL * 2 + boff;
        const uint32_t Vb  = kvb + 2 * KPL * 2 + boff;
        const uint32_t Vlb = kvb + 3 * KPL * 2 + boff;

        float s[8][4];
#pragma unroll
        for (int nf = 0; nf < 8; ++nf)
#pragma unroll
            for (int e = 0; e < 4; ++e) s[nf][e] = 0.f;

#pragma unroll
        for (int ks = 0; ks < 4; ++ks) {
            const uint32_t kb = (uint32_t)ks * 32;
            uint32_t bk[4][4];
#pragma unroll
            for (int p = 0; p < 4; ++p) ldm_x4(bk[p], Kb + p * 2304 + kb);
#pragma unroll
            for (int nf = 0; nf < 8; ++nf) {
                mma_bf(s[nf], aQh[ks], &bk[nf >> 1][(nf & 1) * 2]);
                mma_bf(s[nf], aQl[ks], &bk[nf >> 1][(nf & 1) * 2]);
            }
            uint32_t bkl[4][4];
#pragma unroll
            for (int p = 0; p < 4; ++p) ldm_x4(bkl[p], Klb + p * 2304 + kb);
#pragma unroll
            for (int nf = 0; nf < 8; ++nf)
                mma_bf(s[nf], aQh[ks], &bkl[nf >> 1][(nf & 1) * 2]);
        }

        int row0 = qt * 128 + wm + g;
        float mx0 = NEGINF, mx1 = NEGINF;
#pragma unroll
        for (int nf = 0; nf < 8; ++nf) {
            int colb = j * 64 + nf * 8 + 2 * t4;
#pragma unroll
            for (int e = 0; e < 4; ++e) {
                float val = s[nf][e] * 0.125f;
                if (causal && (colb + (e & 1)) > (row0 + (e >> 1) * 8)) val = NEGINF;
                s[nf][e] = val;
            }
            mx0 = fmaxf(mx0, fmaxf(s[nf][0], s[nf][1]));
            mx1 = fmaxf(mx1, fmaxf(s[nf][2], s[nf][3]));
        }
        mx0 = fmaxf(mx0, __shfl_xor_sync(0xffffffffu, mx0, 1));
        mx0 = fmaxf(mx0, __shfl_xor_sync(0xffffffffu, mx0, 2));
        mx1 = fmaxf(mx1, __shfl_xor_sync(0xffffffffu, mx1, 1));
        mx1 = fmaxf(mx1, __shfl_xor_sync(0xffffffffu, mx1, 2));
        float mn0 = fmaxf(m0, mx0), mn1 = fmaxf(m1, mx1);
        float c0 = expf(m0 - mn0), c1 = expf(m1 - mn1);
        float ls0 = 0.f, ls1 = 0.f;
#pragma unroll
        for (int nf = 0; nf < 8; ++nf) {
            float p0 = expf(s[nf][0] - mn0);
            float p1 = expf(s[nf][1] - mn0);
            float p2 = expf(s[nf][2] - mn1);
            float p3 = expf(s[nf][3] - mn1);
            s[nf][0] = p0; s[nf][1] = p1; s[nf][2] = p2; s[nf][3] = p3;
            ls0 += p0 + p1; ls1 += p2 + p3;
        }
        ls0 += __shfl_xor_sync(0xffffffffu, ls0, 1);
        ls0 += __shfl_xor_sync(0xffffffffu, ls0, 2);
        ls1 += __shfl_xor_sync(0xffffffffu, ls1, 1);
        ls1 += __shfl_xor_sync(0xffffffffu, ls1, 2);
        l0 = l0 * c0 + ls0;
        l1 = l1 * c1 + ls1;
        m0 = mn0; m1 = mn1;
#pragma unroll
        for (int nf = 0; nf < 8; ++nf) {
            acc[nf][0] *= c0; acc[nf][1] *= c0;
            acc[nf][2] *= c1; acc[nf][3] *= c1;
        }

#pragma unroll
        for (int ks = 0; ks < 4; ++ks) {
            const uint32_t kb = (uint32_t)ks * 32;
            uint32_t aPh[4], aPl[4];
            split2(s[2 * ks][0],     s[2 * ks][1],     aPh[0], aPl[0]);
            split2(s[2 * ks][2],     s[2 * ks][3],     aPh[1], aPl[1]);
            split2(s[2 * ks + 1][0], s[2 * ks + 1][1], aPh[2], aPl[2]);
            split2(s[2 * ks + 1][2], s[2 * ks + 1][3], aPh[3], aPl[3]);
            uint32_t bv[4][4];
#pragma unroll
            for (int p = 0; p < 4; ++p) ldm_x4(bv[p], Vb + p * 2304 + kb);
#pragma unroll
            for (int nf = 0; nf < 8; ++nf) {
                mma_bf(acc[nf], aPh, &bv[nf >> 1][(nf & 1) * 2]);
                mma_bf(acc[nf], aPl, &bv[nf >> 1][(nf & 1) * 2]);
            }
            uint32_t bvl[4][4];
#pragma unroll
            for (int p = 0; p < 4; ++p) ldm_x4(bvl[p], Vlb + p * 2304 + kb);
#pragma unroll
            for (int nf = 0; nf < 8; ++nf)
                mma_bf(acc[nf], aPh, &bvl[nf >> 1][(nf & 1) * 2]);
        }
        __syncthreads();
    }

    float iv0 = 1.f / l0, iv1 = 1.f / l1;
    int r0 = qt * 128 + wm + g, r1 = r0 + 8;
#pragma unroll
    for (int nf = 0; nf < 8; ++nf) {
        int col = nf * 8 + 2 * t4;
        uint32_t hi, lo;
        split2(acc[nf][0] * iv0, acc[nf][1] * iv0, hi, lo);
        *(uint32_t*)(outh + obase + (size_t)r0 * DIM + col) = hi;
        *(uint32_t*)(outl + obase + (size_t)r0 * DIM + col) = lo;
        split2(acc[nf][2] * iv1, acc[nf][3] * iv1, hi, lo);
        *(uint32_t*)(outh + obase + (size_t)r1 * DIM + col) = hi;
        *(uint32_t*)(outl + obase + (size_t)r1 * DIM + col) = lo;
    }
}

// ---------------- elementwise helpers ----------------
__device__ __forceinline__ float block_reduce_sum_256(float v) {
    __shared__ float sh[8];
    int lane = threadIdx.x & 31;
    int w = threadIdx.x >> 5;
#pragma unroll
    for (int o = 16; o > 0; o >>= 1) v += __shfl_xor_sync(0xffffffffu, v, o);
    if (lane == 0) sh[w] = v;
    __syncthreads();
    float r = (threadIdx.x < 8) ? sh[threadIdx.x] : 0.f;
    if (w == 0) {
#pragma unroll
        for (int o = 4; o > 0; o >>= 1) r += __shfl_xor_sync(0xffffffffu, r, o);
        if (lane == 0) sh[0] = r;
    }
    __syncthreads();
    float out = sh[0];
    __syncthreads();
    return out;
}

__global__ void splitcopy(const float* __restrict__ in, float* __restrict__ hi,
                          float* __restrict__ lo) {
    int i = blockIdx.x * 256 + threadIdx.x;
    float4 v = ((const float4*)in)[i];
    float4 h = make_float4(tf32r(v.x), tf32r(v.y), tf32r(v.z), tf32r(v.w));
    ((float4*)hi)[i] = h;
    ((float4*)lo)[i] = make_float4(tf32r(v.x - h.x), tf32r(v.y - h.y),
                                   tf32r(v.z - h.z), tf32r(v.w - h.w));
}

__global__ void splitcopy_b4(const float* __restrict__ i0, const float* __restrict__ i1,
                             const float* __restrict__ i2, const float* __restrict__ i3,
                             __nv_bfloat16* __restrict__ hi, __nv_bfloat16* __restrict__ lo,
                             int elems4_per) {
    int w = blockIdx.y;
    const float* in = (w == 0) ? i0 : (w == 1) ? i1 : (w == 2) ? i2 : i3;
    size_t obase = (size_t)w * elems4_per;
    int i = blockIdx.x * 256 + threadIdx.x;
    float4 v = ((const float4*)in)[i];
    uint32_t h0, l0, h1, l1;
    split2(v.x, v.y, h0, l0);
    split2(v.z, v.w, h1, l1);
    ((uint32_t*)hi)[(obase + i) * 2]     = h0;
    ((uint32_t*)hi)[(obase + i) * 2 + 1] = h1;
    ((uint32_t*)lo)[(obase + i) * 2]     = l0;
    ((uint32_t*)lo)[(obase + i) * 2 + 1] = l1;
}

__global__ void splitcopy_b(const float* __restrict__ in, __nv_bfloat16* __restrict__ hi,
                            __nv_bfloat16* __restrict__ lo) {
    int i = blockIdx.x * 256 + threadIdx.x;
    float4 v = ((const float4*)in)[i];
    uint32_t h0, l0, h1, l1;
    split2(v.x, v.y, h0, l0);
    split2(v.z, v.w, h1, l1);
    ((uint32_t*)hi)[i * 2]     = h0;
    ((uint32_t*)hi)[i * 2 + 1] = h1;
    ((uint32_t*)lo)[i * 2]     = l0;
    ((uint32_t*)lo)[i * 2 + 1] = l1;
}

__global__ void rmsnorm_kernel(const float* __restrict__ in,
                               __nv_bfloat16* __restrict__ oh, __nv_bfloat16* __restrict__ ol) {
    int t = blockIdx.x;
    const float* row = in + (size_t)t * DIM;
    float v0 = row[threadIdx.x];
    float v1 = row[threadIdx.x + 256];
    float v2 = row[threadIdx.x + 512];
    float ss = block_reduce_sum_256(v0 * v0 + v1 * v1 + v2 * v2);
    float inv = rsqrtf(ss * (1.f / DIM) + EPSV);
#pragma unroll
    for (int i = 0; i < 3; ++i) {
        int d = threadIdx.x + i * 256;
        float y = (i == 0 ? v0 : (i == 1 ? v1 : v2)) * inv;
        __nv_bfloat16 hb = __float2bfloat16(y);
        oh[(size_t)t * DIM + d] = hb;
        ol[(size_t)t * DIM + d] = __float2bfloat16(y - __bfloat162float(hb));
    }
}

// rope + per-head rmsnorm on fused qkv (q at col 0, k at col 768), stride QLD
__global__ void rope_norm_kernel(float* __restrict__ qkv,
                                 const float* __restrict__ cosb, const float* __restrict__ sinb) {
    int t = blockIdx.x;
    float* arr = qkv + (blockIdx.y == 0 ? 0 : 768);
    int h = threadIdx.x >> 5;
    int f = threadIdx.x & 31;
    int n = t & (NSEQ - 1);
    float c = cosb[n * 32 + f];
    float s = sinb[n * 32 + f];
    float* p = arr + (size_t)t * QLD + h * HD;
    float re = p[2 * f], im = p[2 * f + 1];
    float r0 = re * c - im * s;
    float r1 = re * s + im * c;
    float ss = r0 * r0 + r1 * r1;
#pragma unroll
    for (int o = 16; o > 0; o >>= 1) ss += __shfl_xor_sync(0xffffffffu, ss, o);
    float inv = rsqrtf(ss * (1.f / HD) + EPSV);
    p[2 * f]     = r0 * inv;
    p[2 * f + 1] = r1 * inv;
}

__global__ void logits_kernel(const float* __restrict__ enc, const float* __restrict__ dec,
                              const float* __restrict__ Wp, const float* __restrict__ bp,
                              const float* __restrict__ Wpr, const float* __restrict__ bpr,
                              float* __restrict__ post, float* __restrict__ prior) {
    int t = blockIdx.x;
    int w = threadIdx.x >> 5;
    int lane = threadIdx.x & 31;
    const float* src  = (w < 4) ? enc + (size_t)t * DIM : dec + (size_t)t * DIM;
    const float* wrow = (w < 4) ? Wp + (size_t)w * DIM : Wpr + (size_t)(w - 4) * DIM;
    float s = 0.f;
    for (int i = lane; i < DIM; i += 32) s += src[i] * wrow[i];
#pragma unroll
    for (int o = 16; o > 0; o >>= 1) s += __shfl_xor_sync(0xffffffffu, s, o);
    if (lane == 0) {
        if (w < 4) post[t * 4 + w] = s + bp[w];
        else       prior[t * 4 + (w - 4)] = s + bpr[w - 4];
    }
}

__device__ __forceinline__ unsigned rotl32(unsigned x, int d) { return (x << d) | (x >> (32 - d)); }

__device__ __forceinline__ void threefry2x32_042(unsigned c0, unsigned c1, unsigned& o0, unsigned& o1) {
    const unsigned k0 = 0u, k1 = 42u;
    const unsigned k2 = k0 ^ k1 ^ 0x1BD11BDAu;
    const unsigned ks[3] = {k0, k1, k2};
    const int rot[2][4] = {{13, 15, 26, 6}, {17, 29, 16, 24}};
    unsigned x0 = c0 + k0, x1 = c1 + k1;
#pragma unroll
    for (int i = 0; i < 5; ++i) {
        const int* rr = rot[i & 1];
#pragma unroll
        for (int j = 0; j < 4; ++j) { x0 += x1; x1 = rotl32(x1, rr[j]); x1 ^= x0; }
        x0 += ks[(i + 1) % 3];
        x1 += ks[(i + 2) % 3] + (unsigned)(i + 1);
    }
    o0 = x0; o1 = x1;
}

__device__ __forceinline__ float log_sigmoid(float x) {
    return fminf(x, 0.f) - log1pf(expf(-fabsf(x)));
}

__global__ void latent_kernel(const float* __restrict__ post, const float* __restrict__ prior,
                              float* __restrict__ kl_out, float* __restrict__ klraw_out,
                              float* __restrict__ z_out, int* __restrict__ idx_out) {
    int t = blockIdx.x * blockDim.x + threadIdx.x;
    if (t >= TOK) return;
    float lsp[4], lsnp[4];
    int idx = 0;
    float klr = 0.f;
#pragma unroll
    for (int j = 0; j < 4; ++j) {
        unsigned e = (unsigned)(t * 4 + j);
        unsigned o0, o1;
        threefry2x32_042(0u, e, o0, o1);
        unsigned bits = o0 ^ o1;
        float u = __uint_as_float((bits >> 9) | 0x3f800000u) - 1.0f;
        float x = post[t * 4 + j];
        float pr = prior[t * 4 + j];
        float prob = 1.f / (1.f + expf(-x));
        if (u <= prob) idx |= (1 << j);
        lsp[j]  = log_sigmoid(x);
        lsnp[j] = log_sigmoid(-x);
        float lspr  = log_sigmoid(pr);
        float lsnpr = log_sigmoid(-pr);
        klr += prob * (lsp[j] - lspr) + (1.f - prob) * (lsnp[j] - lsnpr);
    }
    klraw_out[t] = klr;
    kl_out[t] = fmaxf(klr - 0.125f, 0.f);
    idx_out[t] = idx;
#pragma unroll
    for (int c = 0; c < 16; ++c) {
        float lg = 0.f;
#pragma unroll
        for (int j = 0; j < 4; ++j) lg += ((c >> j) & 1) ? lsp[j] : lsnp[j];
        float soft = expf(lg);
        float hard = (c == idx) ? 1.f : 0.f;
        z_out[t * 16 + c] = (hard + soft) - soft;
    }
}

__global__ void xmid_kernel(const float* __restrict__ x, const float* __restrict__ dec,
                            const float* __restrict__ Wz, const int* __restrict__ idx,
                            float* __restrict__ xmid, float* __restrict__ h) {
    int t = blockIdx.x;
    int code = idx[t];
    float v[3];
    float ss = 0.f;
#pragma unroll
    for (int i = 0; i < 3; ++i) {
        int d = threadIdx.x + i * 256;
        float val = x[(size_t)t * DIM + d] + dec[(size_t)t * DIM + d] + Wz[d * 16 + code];
        v[i] = val;
        ss += val * val;
    }
    ss = block_reduce_sum_256(ss);
    float inv = rsqrtf(ss * (1.f / DIM) + EPSV);
#pragma unroll
    for (int i = 0; i < 3; ++i) {
        int d = threadIdx.x + i * 256;
        xmid[(size_t)t * DIM + d] = v[i];
        h[(size_t)t * DIM + d]    = tf32r(v[i] * inv);
    }
}

// ---------------- launcher ----------------
extern "C" void kernel_launch(void* const* d_in, const int* in_sizes, int n_in,
                              void* d_out, int out_size) {
    const float* x     = (const float*)d_in[0];
    const float* cosb  = (const float*)d_in[1];
    const float* sinb  = (const float*)d_in[2];
    const float* Wq    = (const float*)d_in[3];
    const float* Wk    = (const float*)d_in[4];
    const float* Wv    = (const float*)d_in[5];
    const float* Wenc  = (const float*)d_in[6];
    const float* Wdec  = (const float*)d_in[7];
    const float* Wpost = (const float*)d_in[8];
    const float* bpost = (const float*)d_in[9];
    const float* Wpri  = (const float*)d_in[10];
    const float* bpri  = (const float*)d_in[11];
    const float* Wz    = (const float*)d_in[12];
    const float* Wfc1  = (const float*)d_in[13];
    const float* Wfc2  = (const float*)d_in[14];

    float *qkv, *enc, *dec, *xmid, *h, *act, *wh, *wl, *post, *prior;
    __nv_bfloat16 *xhb, *xlb, *ahb, *alb, *wbh, *wbl;
    int* idx;
    cudaGetSymbolAddress((void**)&xhb,  g_xhb);
    cudaGetSymbolAddress((void**)&xlb,  g_xlb);
    cudaGetSymbolAddress((void**)&ahb,  g_ahb);
    cudaGetSymbolAddress((void**)&alb,  g_alb);
    cudaGetSymbolAddress((void**)&wbh,  g_wbh);
    cudaGetSymbolAddress((void**)&wbl,  g_wbl);
    cudaGetSymbolAddress((void**)&qkv,  g_qkv);
    cudaGetSymbolAddress((void**)&enc,  g_enc);
    cudaGetSymbolAddress((void**)&dec,  g_dec);
    cudaGetSymbolAddress((void**)&xmid, g_xmid);
    cudaGetSymbolAddress((void**)&h,    g_h);
    cudaGetSymbolAddress((void**)&act,  g_act);
    cudaGetSymbolAddress((void**)&wh,   g_wh);
    cudaGetSymbolAddress((void**)&wl,   g_wl);
    cudaGetSymbolAddress((void**)&post, g_post);
    cudaGetSymbolAddress((void**)&prior, g_prior);
    cudaGetSymbolAddress((void**)&idx,  g_idx);

    float* out_x     = (float*)d_out;
    float* out_kl    = out_x + (size_t)TOK * DIM;
    float* out_klraw = out_kl + TOK;
    float* out_z     = out_klraw + TOK;

    cudaFuncSetAttribute(tgemm_b, cudaFuncAttributeMaxDynamicSharedMemorySize, SMB);
    cudaFuncSetAttribute(tgemm_t, cudaFuncAttributeMaxDynamicSharedMemorySize, SM1);
    cudaFuncSetAttribute(attn_tc, cudaFuncAttributeMaxDynamicSharedMemorySize, ATT_SMEM);

    // (1) QKV+enc weight split — everything the QKV GEMM needs
    splitcopy_b4<<<dim3(576, 4), 256>>>(Wq, Wk, Wv, Wenc, wbh, wbl, 147456);
    // (2) rmsnorm(x) -> bf16 hi/lo
    rmsnorm_kernel<<<TOK, 256>>>(x, xhb, xlb);
    // (3) fused QKV GEMM  <-- ncu profiles launch #3
    tgemm_b<<<dim3(QLD / 128, TOK / 128), 256, SMB>>>(
        xhb, xlb, DIM, wbh + OFF_WQKV, wbl + OFF_WQKV, DIM, qkv, QLD, DIM);

    // remaining weight splits (consumed later)
    splitcopy_b<<<288, 256>>>(Wdec, wbh + OFF_WDEC, wbl + OFF_WDEC);
    splitcopy<<<2304, 256>>>(Wfc1, wh + OFF_WFC1, wl + OFF_WFC1);
    splitcopy<<<2304, 256>>>(Wfc2, wh + OFF_WFC2, wl + OFF_WFC2);

    // rope + per-head rmsnorm on fused qkv
    rope_norm_kernel<<<dim3(TOK, 2), 384>>>(qkv, cosb, sinb);

    // tensor-core flash attention
    attn_tc<<<dim3(NSEQ / 128, 16 * NHEADS), 256, ATT_SMEM>>>(
        qkv, qkv + 768, qkv + 1536, ahb, alb);

    // output projections (bf16x3)
    dim3 gout(DIM / 128, TOK / 128);
    tgemm_b<<<gout, 256, SMB>>>(ahb, alb, DIM, wbh + OFF_WENC, wbl + OFF_WENC, DIM, enc, DIM, DIM);
    tgemm_b<<<gout, 256, SMB>>>(ahb + 384, alb + 384, DIM, wbh + OFF_WDEC, wbl + OFF_WDEC, 384, dec, DIM, 384);

    // posterior / prior logits
    logits_kernel<<<TOK, 256>>>(enc, dec, Wpost, bpost, Wpri, bpri, post, prior);

    // sampling / KL / z_one_hot
    latent_kernel<<<TOK / 128, 128>>>(post, prior, out_kl, out_klraw, out_z, idx);

    // x_mid + rmsnorm
    xmid_kernel<<<TOK, 256>>>(x, dec, Wz, idx, xmid, h);

    // FFN (single-pass tf32 — R11 measured-best)
    tgemm_t<<<dim3(3072 / 128, TOK / 128), 256, SM1>>>(h, DIM, wh + OFF_WFC1, DIM, act, 3072, DIM, 1, nullptr);
    tgemm_t<<<gout, 256, SM1>>>(act, 3072, wh + OFF_WFC2, 3072, out_x, DIM, 3072, 2, xmid);
}

// round 16
// speedup vs baseline: 1.1445x; 1.0042x over previous
#include <cuda_runtime.h>
#include <cuda_bf16.h>
#include <math.h>
#include <stdint.h>

#define TOK   16384
#define DIM   768
#define NSEQ  1024
#define NHEADS 12
#define HD    64
#define ENC_HEADS 6
#define EPSV  1e-5f
#define QLD   2304            // fused qkv row stride

// fp32 (tf32-rounded) weight buffer offsets — fc only
#define OFF_WFC1 2654208
#define OFF_WFC2 5013504
#define WTOT     7372800
// bf16 plane offsets (halfs) — Wq/Wk/Wv contiguous = fused [2304 x 768]
#define OFF_WQKV 0
#define OFF_WENC 1769472
#define OFF_WDEC 2359296
#define WBTOT    2654208

// ---------------- scratch (device globals; allocation is forbidden) ----------------
__device__ __nv_bfloat16 g_xhb[TOK * DIM];
__device__ __nv_bfloat16 g_xlb[TOK * DIM];
__device__ __nv_bfloat16 g_ahb[TOK * DIM];
__device__ __nv_bfloat16 g_alb[TOK * DIM];
__device__ __nv_bfloat16 g_qh[TOK * DIM];
__device__ __nv_bfloat16 g_ql[TOK * DIM];
__device__ __nv_bfloat16 g_kh[TOK * DIM];
__device__ __nv_bfloat16 g_kl[TOK * DIM];
__device__ __nv_bfloat16 g_vh[TOK * DIM];
__device__ __nv_bfloat16 g_vl[TOK * DIM];
__device__ __nv_bfloat16 g_wbh[WBTOT];
__device__ __nv_bfloat16 g_wbl[WBTOT];
__device__ float g_qkv[TOK * QLD];
__device__ float g_enc[TOK * DIM];
__device__ float g_dec[TOK * DIM];
__device__ float g_xmid[TOK * DIM];
__device__ float g_h[TOK * DIM];
__device__ float g_act[TOK * 3072];
__device__ float g_wh[WTOT];
__device__ float g_wl[WTOT];
__device__ float g_post[TOK * 4];
__device__ float g_prior[TOK * 4];
__device__ int   g_idx[TOK];

// ---------------- small PTX helpers (all sm_80-baseline legal) ----------------
__device__ __forceinline__ uint32_t s2u(const void* p) {
    uint32_t a;
    asm("{ .reg .u64 t; cvta.to.shared.u64 t, %1; cvt.u32.u64 %0, t; }" : "=r"(a) : "l"(p));
    return a;
}
__device__ __forceinline__ uint32_t f2tf32(float v) {
    uint32_t r;
    asm("cvt.rna.tf32.f32 %0, %1;" : "=r"(r) : "f"(v));
    return r;
}
__device__ __forceinline__ float tf32r(float v) { return __uint_as_float(f2tf32(v)); }

__device__ __forceinline__ void cpasync16(uint32_t dst, const void* src) {
    asm volatile("cp.async.cg.shared.global [%0], [%1], 16;" :: "r"(dst), "l"(src));
}
__device__ __forceinline__ void cp_commit() {
    asm volatile("cp.async.commit_group;" ::: "memory");
}
__device__ __forceinline__ void mma_frag(float* d, const uint32_t* a, const uint32_t* b) {
    asm volatile(
        "mma.sync.aligned.m16n8k8.row.col.f32.tf32.tf32.f32 "
        "{%0,%1,%2,%3}, {%4,%5,%6,%7}, {%8,%9}, {%0,%1,%2,%3};"
        : "+f"(d[0]), "+f"(d[1]), "+f"(d[2]), "+f"(d[3])
        : "r"(a[0]), "r"(a[1]), "r"(a[2]), "r"(a[3]), "r"(b[0]), "r"(b[1]));
}
__device__ __forceinline__ void mma_bf(float* d, const uint32_t* a, const uint32_t* b) {
    asm volatile(
        "mma.sync.aligned.m16n8k16.row.col.f32.bf16.bf16.f32 "
        "{%0,%1,%2,%3}, {%4,%5,%6,%7}, {%8,%9}, {%0,%1,%2,%3};"
        : "+f"(d[0]), "+f"(d[1]), "+f"(d[2]), "+f"(d[3])
        : "r"(a[0]), "r"(a[1]), "r"(a[2]), "r"(a[3]), "r"(b[0]), "r"(b[1]));
}
__device__ __forceinline__ void ldm_x4(uint32_t* r, uint32_t addr) {
    asm volatile("ldmatrix.sync.aligned.m8n8.x4.shared.b16 {%0,%1,%2,%3}, [%4];"
                 : "=r"(r[0]), "=r"(r[1]), "=r"(r[2]), "=r"(r[3]) : "r"(addr));
}
__device__ __forceinline__ void split2(float a, float b, uint32_t& hi, uint32_t& lo) {
    __nv_bfloat16 ha = __float2bfloat16(a), hb = __float2bfloat16(b);
    __nv_bfloat162 H(ha, hb);
    __nv_bfloat162 L(__float2bfloat16(a - __bfloat162float(ha)),
                     __float2bfloat16(b - __bfloat162float(hb)));
    hi = *(uint32_t*)&H;
    lo = *(uint32_t*)&L;
}

// ================= bf16x3 GEMM (fp32-grade): C = A*B^T, tile 128x128, Kchunk 32 ====
#define PLANE_B 10240
#define BUF_B   (4 * PLANE_B)
#define SMB     (2 * BUF_B)       // 81920

__global__ __launch_bounds__(256, 2) void tgemm_b(
    const __nv_bfloat16* __restrict__ Ah, const __nv_bfloat16* __restrict__ Al, int lda,
    const __nv_bfloat16* __restrict__ Bh, const __nv_bfloat16* __restrict__ Bl, int ldb,
    float* __restrict__ C, int ldc, int K) {
    extern __shared__ char smb[];
    const uint32_t sbase = s2u(smb);

    const int tid = threadIdx.x;
    const int wid = tid >> 5, lane = tid & 31;
    const int g = lane >> 2, t4 = lane & 3;
    const int bm = blockIdx.y * 128, bn = blockIdx.x * 128;
    const int wm = (wid & 1) * 64, wn = (wid >> 1) * 32;

    const uint32_t aoff = (uint32_t)(wm + (lane & 15)) * 80 + ((lane >> 4) * 16);
    const uint32_t boff = (uint32_t)(wn + (lane & 7) + ((lane & 16) >> 1)) * 80
                        + (((lane >> 3) & 1) * 16);

    float acc[4][4][4];
#pragma unroll
    for (int a = 0; a < 4; ++a)
#pragma unroll
        for (int b = 0; b < 4; ++b)
#pragma unroll
            for (int c = 0; c < 4; ++c) acc[a][b][c] = 0.f;

    const int nch = K >> 5;

    auto stage = [&](int ch, int buf) {
        uint32_t base = sbase + (uint32_t)buf * BUF_B;
        int kc = ch << 5;
#pragma unroll
        for (int it = 0; it < 8; ++it) {
            int idx = tid + it * 256;
            int plane = idx >> 9;
            int rem = idx & 511;
            int row = rem >> 2, j = rem & 3;
            const __nv_bfloat16* src;
            if      (plane == 0) src = Ah + (size_t)(bm + row) * lda + kc + j * 8;
            else if (plane == 1) src = Al + (size_t)(bm + row) * lda + kc + j * 8;
            else if (plane == 2) src = Bh + (size_t)(bn + row) * ldb + kc + j * 8;
            else                 src = Bl + (size_t)(bn + row) * ldb + kc + j * 8;
            cpasync16(base + (uint32_t)plane * PLANE_B + (uint32_t)row * 80 + (uint32_t)j * 16, src);
        }
        cp_commit();
    };

    stage(0, 0);
    for (int ch = 0; ch < nch; ++ch) {
        bool more = (ch + 1 < nch);
        if (more) stage(ch + 1, (ch + 1) & 1);
        if (more) asm volatile("cp.async.wait_group 1;" ::: "memory");
        else      asm volatile("cp.async.wait_group 0;" ::: "memory");
        __syncthreads();

        const uint32_t cb = sbase + (ch & 1) * BUF_B;
        const uint32_t aH = cb + aoff;
        const uint32_t aL = cb + PLANE_B + aoff;
        const uint32_t bH = cb + 2u * PLANE_B + boff;
        const uint32_t bL = cb + 3u * PLANE_B + boff;

#pragma unroll
        for (int ks = 0; ks < 2; ++ks) {
            const uint32_t kb = (uint32_t)ks * 32;
            uint32_t ah[4][4], bh[2][4];
#pragma unroll
            for (int mf = 0; mf < 4; ++mf) ldm_x4(ah[mf], aH + mf * 1280 + kb);
#pragma unroll
            for (int p = 0; p < 2; ++p) ldm_x4(bh[p], bH + p * 1280 + kb);
#pragma unroll
            for (int mf = 0; mf < 4; ++mf)
#pragma unroll
                for (int nf = 0; nf < 4; ++nf)
                    mma_bf(acc[mf][nf], ah[mf], &bh[nf >> 1][(nf & 1) * 2]);

            uint32_t al[4][4];
#pragma unroll
            for (int mf = 0; mf < 4; ++mf) ldm_x4(al[mf], aL + mf * 1280 + kb);
#pragma unroll
            for (int mf = 0; mf < 4; ++mf)
#pragma unroll
                for (int nf = 0; nf < 4; ++nf)
                    mma_bf(acc[mf][nf], al[mf], &bh[nf >> 1][(nf & 1) * 2]);

            uint32_t bl[2][4];
#pragma unroll
            for (int p = 0; p < 2; ++p) ldm_x4(bl[p], bL + p * 1280 + kb);
#pragma unroll
            for (int mf = 0; mf < 4; ++mf)
#pragma unroll
                for (int nf = 0; nf < 4; ++nf)
                    mma_bf(acc[mf][nf], ah[mf], &bl[nf >> 1][(nf & 1) * 2]);
        }
        __syncthreads();
    }

#pragma unroll
    for (int mf = 0; mf < 4; ++mf) {
#pragma unroll
        for (int half = 0; half < 2; ++half) {
            int row = bm + wm + mf * 16 + g + half * 8;
            float* cp = C + (size_t)row * ldc + bn + wn;
#pragma unroll
            for (int nf = 0; nf < 4; ++nf) {
                int col = nf * 8 + 2 * t4;
                *(float2*)(cp + col) =
                    make_float2(acc[mf][nf][half * 2 + 0], acc[mf][nf][half * 2 + 1]);
            }
        }
    }
}

// ================= tf32 single-pass GEMM (for FFN) ==========
#define ASTR 36
#define MATF (128 * ASTR)
#define MATB (MATF * 4)
#define SM1 (2 * 2 * MATB)   // 73728

__global__ __launch_bounds__(256, 2) void tgemm_t(
    const float* __restrict__ Ah, int lda,
    const float* __restrict__ Bh, int ldb,
    float* __restrict__ C, int ldc, int K, int epi, const float* __restrict__ res) {
    extern __shared__ float smf[];
    const uint32_t sbase = s2u(smf);
    constexpr int BUFF = 2 * MATF;

    const int tid = threadIdx.x;
    const int wid = tid >> 5, lane = tid & 31;
    const int g = lane >> 2, t4 = lane & 3;
    const int bm = blockIdx.y * 128, bn = blockIdx.x * 128;
    const int wm = (wid & 1) * 64, wn = (wid >> 1) * 32;

    float acc[4][4][4];
#pragma unroll
    for (int a = 0; a < 4; ++a)
#pragma unroll
        for (int b = 0; b < 4; ++b)
#pragma unroll
            for (int c = 0; c < 4; ++c) acc[a][b][c] = 0.f;

    const int nch = K >> 5;

    auto stage = [&](int ch, int buf) {
        uint32_t base = sbase + (uint32_t)buf * (BUFF * 4);
        int kc = ch << 5;
#pragma unroll
        for (int it = 0; it < 4; ++it) {
            int idx = tid + it * 256;
            int row = idx >> 3, j = idx & 7;
            uint32_t doff = (uint32_t)row * (ASTR * 4) + (uint32_t)j * 16;
            cpasync16(base + doff, Ah + (size_t)(bm + row) * lda + kc + j * 4);
            cpasync16(base + MATB + doff, Bh + (size_t)(bn + row) * ldb + kc + j * 4);
        }
        cp_commit();
    };

    stage(0, 0);
    for (int ch = 0; ch < nch; ++ch) {
        bool more = (ch + 1 < nch);
        if (more) stage(ch + 1, (ch + 1) & 1);
        if (more) asm volatile("cp.async.wait_group 1;" ::: "memory");
        else      asm volatile("cp.async.wait_group 0;" ::: "memory");
        __syncthreads();

        const float* As = smf + (ch & 1) * BUFF;
        const float* Bs = As + MATF;

#pragma unroll
        for (int ks = 0; ks < 4; ++ks) {
            const int ko = ks * 8 + t4;
            uint32_t ah[4][4], bh[4][2];
#pragma unroll
            for (int mf = 0; mf < 4; ++mf) {
                int r0 = (wm + mf * 16 + g) * ASTR + ko;
                ah[mf][0] = __float_as_uint(As[r0]);
                ah[mf][1] = __float_as_uint(As[r0 + 8 * ASTR]);
                ah[mf][2] = __float_as_uint(As[r0 + 4]);
                ah[mf][3] = __float_as_uint(As[r0 + 8 * ASTR + 4]);
            }
#pragma unroll
            for (int nf = 0; nf < 4; ++nf) {
                int rb = (wn + nf * 8 + g) * ASTR + ko;
                bh[nf][0] = __float_as_uint(Bs[rb]);
                bh[nf][1] = __float_as_uint(Bs[rb + 4]);
            }
#pragma unroll
            for (int mf = 0; mf < 4; ++mf)
#pragma unroll
                for (int nf = 0; nf < 4; ++nf)
                    mma_frag(acc[mf][nf], ah[mf], bh[nf]);
        }
        __syncthreads();
    }

#pragma unroll
    for (int mf = 0; mf < 4; ++mf) {
#pragma unroll
        for (int half = 0; half < 2; ++half) {
            int row = bm + wm + mf * 16 + g + half * 8;
            float* cp = C + (size_t)row * ldc + bn + wn;
            const float* rp = (epi == 2) ? (res + (size_t)row * ldc + bn + wn) : nullptr;
#pragma unroll
            for (int nf = 0; nf < 4; ++nf) {
                float v0 = acc[mf][nf][half * 2 + 0];
                float v1 = acc[mf][nf][half * 2 + 1];
                int col = nf * 8 + 2 * t4;
                if (epi == 1) {
                    float a = fmaxf(v0, 0.f), b = fmaxf(v1, 0.f);
                    v0 = tf32r(a * a); v1 = tf32r(b * b);
                } else if (epi == 2) {
                    v0 += rp[col]; v1 += rp[col + 1];
                }
                *(float2*)(cp + col) = make_float2(v0, v1);
            }
        }
    }
}

// ================= tensor-core flash attention (bf16x3, pre-split planes) =========
#define ATS   72
#define QPL   (128 * ATS)
#define KPL   (64 * ATS)
#define ATT_SMEM ((2 * QPL + 8 * KPL) * 2)   // 110592 bytes

__global__ __launch_bounds__(256) void attn_tc(
    const __nv_bfloat16* __restrict__ qh, const __nv_bfloat16* __restrict__ ql,
    const __nv_bfloat16* __restrict__ kh, const __nv_bfloat16* __restrict__ kl,
    const __nv_bfloat16* __restrict__ vh, const __nv_bfloat16* __restrict__ vl,
    __nv_bfloat16* __restrict__ outh, __nv_bfloat16* __restrict__ outl) {
    extern __shared__ __nv_bfloat16 sm[];
    const uint32_t sbase = s2u(sm);
    const int tid = threadIdx.x, wid = tid >> 5, lane = tid & 31;
    const int g = lane >> 2, t4 = lane & 3;
    const int qt = blockIdx.x, bh_ = blockIdx.y;
    const int b = bh_ / NHEADS, h = bh_ - b * NHEADS;
    const size_t pbase = (size_t)b * NSEQ * DIM + (size_t)h * HD;   // bf16 plane base
    const bool causal = (h >= ENC_HEADS);
    const int jmax = causal ? 2 * qt + 1 : (NSEQ / 64 - 1);
    const int wm = wid * 16;
    const float NEGINF = __int_as_float(0xff800000);

    const uint32_t qoff = (uint32_t)(wm + (lane & 15)) * 144 + ((lane >> 4) * 16);
    const uint32_t boff = (uint32_t)((lane & 7) + ((lane & 16) >> 1)) * 144
                        + (((lane >> 3) & 1) * 16);

    // stage Q: pure 16B copies of pre-split planes
    for (int i = tid; i < 128 * 8; i += 256) {
        int row = i >> 3, c16 = i & 7;
        size_t gi = pbase + (size_t)(qt * 128 + row) * DIM + c16 * 8;
        *(uint4*)(sm + row * ATS + c16 * 8)       = *(const uint4*)(qh + gi);
        *(uint4*)(sm + QPL + row * ATS + c16 * 8) = *(const uint4*)(ql + gi);
    }

    auto stage = [&](int j, int buf) {
        __nv_bfloat16* Kh = sm + 2 * QPL + buf * 4 * KPL;
        __nv_bfloat16* Kl = Kh + KPL;
        __nv_bfloat16* Vh = Kh + 2 * KPL;
        __nv_bfloat16* Vl = Kh + 3 * KPL;
        // K: 16B copies
        for (int i = tid; i < 64 * 8; i += 256) {
            int kv = i >> 3, c16 = i & 7;
            size_t gi = pbase + (size_t)(j * 64 + kv) * DIM + c16 * 8;
            *(uint4*)(Kh + kv * ATS + c16 * 8) = *(const uint4*)(kh + gi);
            *(uint4*)(Kl + kv * ATS + c16 * 8) = *(const uint4*)(kl + gi);
        }
        // V: transposed 2-half copies
        for (int i = tid; i < 64 * 32; i += 256) {
            int kv = i >> 5, dp = i & 31;
            size_t gi = pbase + (size_t)(j * 64 + kv) * DIM + 2 * dp;
            __nv_bfloat162 vv = *(const __nv_bfloat162*)(vh + gi);
            Vh[(2 * dp) * ATS + kv]     = vv.x;
            Vh[(2 * dp + 1) * ATS + kv] = vv.y;
            __nv_bfloat162 wl = *(const __nv_bfloat162*)(vl + gi);
            Vl[(2 * dp) * ATS + kv]     = wl.x;
            Vl[(2 * dp + 1) * ATS + kv] = wl.y;
        }
    };

    stage(0, 0);
    __syncthreads();

    uint32_t aQh[4][4], aQl[4][4];
#pragma unroll
    for (int ks = 0; ks < 4; ++ks) {
        ldm_x4(aQh[ks], sbase + qoff + ks * 32);
        ldm_x4(aQl[ks], sbase + QPL * 2 + qoff + ks * 32);
    }

    float acc[8][4];
#pragma unroll
    for (int nf = 0; nf < 8; ++nf)
#pragma unroll
        for (int e = 0; e < 4; ++e) acc[nf][e] = 0.f;
    float m0 = -1e30f, m1 = -1e30f, l0 = 0.f, l1 = 0.f;

    for (int j = 0; j <= jmax; ++j) {
        if (j + 1 <= jmax) stage(j + 1, (j + 1) & 1);

        const uint32_t kvb = sbase + (2 * QPL + (j & 1) * 4 * KPL) * 2;
        const uint32_t Kb  = kvb + boff;
        const uint32_t Klb = kvb + KPL * 2 + boff;
        const uint32_t Vb  = kvb + 2 * KPL * 2 + boff;
        const uint32_t Vlb = kvb + 3 * KPL * 2 + boff;

        float s[8][4];
#pragma unroll
        for (int nf = 0; nf < 8; ++nf)
#pragma unroll
            for (int e = 0; e < 4; ++e) s[nf][e] = 0.f;

#pragma unroll
        for (int ks = 0; ks < 4; ++ks) {
            const uint32_t kb = (uint32_t)ks * 32;
            uint32_t bk[4][4];
#pragma unroll
            for (int p = 0; p < 4; ++p) ldm_x4(bk[p], Kb + p * 2304 + kb);
#pragma unroll
            for (int nf = 0; nf < 8; ++nf) {
                mma_bf(s[nf], aQh[ks], &bk[nf >> 1][(nf & 1) * 2]);
                mma_bf(s[nf], aQl[ks], &bk[nf >> 1][(nf & 1) * 2]);
            }
            uint32_t bkl[4][4];
#pragma unroll
            for (int p = 0; p < 4; ++p) ldm_x4(bkl[p], Klb + p * 2304 + kb);
#pragma unroll
            for (int nf = 0; nf < 8; ++nf)
                mma_bf(s[nf], aQh[ks], &bkl[nf >> 1][(nf & 1) * 2]);
        }

        int row0 = qt * 128 + wm + g;
        float mx0 = NEGINF, mx1 = NEGINF;
#pragma unroll
        for (int nf = 0; nf < 8; ++nf) {
            int colb = j * 64 + nf * 8 + 2 * t4;
#pragma unroll
            for (int e = 0; e < 4; ++e) {
                float val = s[nf][e] * 0.125f;
                if (causal && (colb + (e & 1)) > (row0 + (e >> 1) * 8)) val = NEGINF;
                s[nf][e] = val;
            }
            mx0 = fmaxf(mx0, fmaxf(s[nf][0], s[nf][1]));
            mx1 = fmaxf(mx1, fmaxf(s[nf][2], s[nf][3]));
        }
        mx0 = fmaxf(mx0, __shfl_xor_sync(0xffffffffu, mx0, 1));
        mx0 = fmaxf(mx0, __shfl_xor_sync(0xffffffffu, mx0, 2));
        mx1 = fmaxf(mx1, __shfl_xor_sync(0xffffffffu, mx1, 1));
        mx1 = fmaxf(mx1, __shfl_xor_sync(0xffffffffu, mx1, 2));
        float mn0 = fmaxf(m0, mx0), mn1 = fmaxf(m1, mx1);
        float c0 = expf(m0 - mn0), c1 = expf(m1 - mn1);
        float ls0 = 0.f, ls1 = 0.f;
#pragma unroll
        for (int nf = 0; nf < 8; ++nf) {
            float p0 = expf(s[nf][0] - mn0);
            float p1 = expf(s[nf][1] - mn0);
            float p2 = expf(s[nf][2] - mn1);
            float p3 = expf(s[nf][3] - mn1);
            s[nf][0] = p0; s[nf][1] = p1; s[nf][2] = p2; s[nf][3] = p3;
            ls0 += p0 + p1; ls1 += p2 + p3;
        }
        ls0 += __shfl_xor_sync(0xffffffffu, ls0, 1);
        ls0 += __shfl_xor_sync(0xffffffffu, ls0, 2);
        ls1 += __shfl_xor_sync(0xffffffffu, ls1, 1);
        ls1 += __shfl_xor_sync(0xffffffffu, ls1, 2);
        l0 = l0 * c0 + ls0;
        l1 = l1 * c1 + ls1;
        m0 = mn0; m1 = mn1;
#pragma unroll
        for (int nf = 0; nf < 8; ++nf) {
            acc[nf][0] *= c0; acc[nf][1] *= c0;
            acc[nf][2] *= c1; acc[nf][3] *= c1;
        }

#pragma unroll
        for (int ks = 0; ks < 4; ++ks) {
            const uint32_t kb = (uint32_t)ks * 32;
            uint32_t aPh[4], aPl[4];
            split2(s[2 * ks][0],     s[2 * ks][1],     aPh[0], aPl[0]);
            split2(s[2 * ks][2],     s[2 * ks][3],     aPh[1], aPl[1]);
            split2(s[2 * ks + 1][0], s[2 * ks + 1][1], aPh[2], aPl[2]);
            split2(s[2 * ks + 1][2], s[2 * ks + 1][3], aPh[3], aPl[3]);
            uint32_t bv[4][4];
#pragma unroll
            for (int p = 0; p < 4; ++p) ldm_x4(bv[p], Vb + p * 2304 + kb);
#pragma unroll
            for (int nf = 0; nf < 8; ++nf) {
                mma_bf(acc[nf], aPh, &bv[nf >> 1][(nf & 1) * 2]);
                mma_bf(acc[nf], aPl, &bv[nf >> 1][(nf & 1) * 2]);
            }
            uint32_t bvl[4][4];
#pragma unroll
            for (int p = 0; p < 4; ++p) ldm_x4(bvl[p], Vlb + p * 2304 + kb);
#pragma unroll
            for (int nf = 0; nf < 8; ++nf)
                mma_bf(acc[nf], aPh, &bvl[nf >> 1][(nf & 1) * 2]);
        }
        __syncthreads();
    }

    float iv0 = 1.f / l0, iv1 = 1.f / l1;
    int r0 = qt * 128 + wm + g, r1 = r0 + 8;
#pragma unroll
    for (int nf = 0; nf < 8; ++nf) {
        int col = nf * 8 + 2 * t4;
        uint32_t hi, lo;
        split2(acc[nf][0] * iv0, acc[nf][1] * iv0, hi, lo);
        *(uint32_t*)(outh + pbase + (size_t)r0 * DIM + col - (size_t)h * HD + (size_t)h * HD) = hi;
        *(uint32_t*)(outl + pbase + (size_t)r0 * DIM + col - (size_t)h * HD + (size_t)h * HD) = lo;
        split2(acc[nf][2] * iv1, acc[nf][3] * iv1, hi, lo);
        *(uint32_t*)(outh + pbase + (size_t)r1 * DIM + col) = hi;
        *(uint32_t*)(outl + pbase + (size_t)r1 * DIM + col) = lo;
    }
}

// ---------------- elementwise helpers ----------------
__device__ __forceinline__ float block_reduce_sum_256(float v) {
    __shared__ float sh[8];
    int lane = threadIdx.x & 31;
    int w = threadIdx.x >> 5;
#pragma unroll
    for (int o = 16; o > 0; o >>= 1) v += __shfl_xor_sync(0xffffffffu, v, o);
    if (lane == 0) sh[w] = v;
    __syncthreads();
    float r = (threadIdx.x < 8) ? sh[threadIdx.x] : 0.f;
    if (w == 0) {
#pragma unroll
        for (int o = 4; o > 0; o >>= 1) r += __shfl_xor_sync(0xffffffffu, r, o);
        if (lane == 0) sh[0] = r;
    }
    __syncthreads();
    float out = sh[0];
    __syncthreads();
    return out;
}

__global__ void splitcopy(const float* __restrict__ in, float* __restrict__ hi,
                          float* __restrict__ lo) {
    int i = blockIdx.x * 256 + threadIdx.x;
    float4 v = ((const float4*)in)[i];
    float4 h = make_float4(tf32r(v.x), tf32r(v.y), tf32r(v.z), tf32r(v.w));
    ((float4*)hi)[i] = h;
    ((float4*)lo)[i] = make_float4(tf32r(v.x - h.x), tf32r(v.y - h.y),
                                   tf32r(v.z - h.z), tf32r(v.w - h.w));
}

__global__ void splitcopy_b4(const float* __restrict__ i0, const float* __restrict__ i1,
                             const float* __restrict__ i2, const float* __restrict__ i3,
                             __nv_bfloat16* __restrict__ hi, __nv_bfloat16* __restrict__ lo,
                             int elems4_per) {
    int w = blockIdx.y;
    const float* in = (w == 0) ? i0 : (w == 1) ? i1 : (w == 2) ? i2 : i3;
    size_t obase = (size_t)w * elems4_per;
    int i = blockIdx.x * 256 + threadIdx.x;
    float4 v = ((const float4*)in)[i];
    uint32_t h0, l0, h1, l1;
    split2(v.x, v.y, h0, l0);
    split2(v.z, v.w, h1, l1);
    ((uint32_t*)hi)[(obase + i) * 2]     = h0;
    ((uint32_t*)hi)[(obase + i) * 2 + 1] = h1;
    ((uint32_t*)lo)[(obase + i) * 2]     = l0;
    ((uint32_t*)lo)[(obase + i) * 2 + 1] = l1;
}

__global__ void splitcopy_b(const float* __restrict__ in, __nv_bfloat16* __restrict__ hi,
                            __nv_bfloat16* __restrict__ lo) {
    int i = blockIdx.x * 256 + threadIdx.x;
    float4 v = ((const float4*)in)[i];
    uint32_t h0, l0, h1, l1;
    split2(v.x, v.y, h0, l0);
    split2(v.z, v.w, h1, l1);
    ((uint32_t*)hi)[i * 2]     = h0;
    ((uint32_t*)hi)[i * 2 + 1] = h1;
    ((uint32_t*)lo)[i * 2]     = l0;
    ((uint32_t*)lo)[i * 2 + 1] = l1;
}

__global__ void rmsnorm_kernel(const float* __restrict__ in,
                               __nv_bfloat16* __restrict__ oh, __nv_bfloat16* __restrict__ ol) {
    int t = blockIdx.x;
    const float* row = in + (size_t)t * DIM;
    float v0 = row[threadIdx.x];
    float v1 = row[threadIdx.x + 256];
    float v2 = row[threadIdx.x + 512];
    float ss = block_reduce_sum_256(v0 * v0 + v1 * v1 + v2 * v2);
    float inv = rsqrtf(ss * (1.f / DIM) + EPSV);
#pragma unroll
    for (int i = 0; i < 3; ++i) {
        int d = threadIdx.x + i * 256;
        float y = (i == 0 ? v0 : (i == 1 ? v1 : v2)) * inv;
        __nv_bfloat16 hb = __float2bfloat16(y);
        oh[(size_t)t * DIM + d] = hb;
        ol[(size_t)t * DIM + d] = __float2bfloat16(y - __bfloat162float(hb));
    }
}

// rope + per-head rmsnorm on fused qkv, output bf16 hi/lo planes (q or k by blockIdx.y)
__global__ void rope_norm_kernel(const float* __restrict__ qkv,
                                 const float* __restrict__ cosb, const float* __restrict__ sinb,
                                 __nv_bfloat16* __restrict__ qh, __nv_bfloat16* __restrict__ ql,
                                 __nv_bfloat16* __restrict__ kh, __nv_bfloat16* __restrict__ kl) {
    int t = blockIdx.x;
    int sel = blockIdx.y;
    __nv_bfloat16* oh = sel ? kh : qh;
    __nv_bfloat16* ol = sel ? kl : ql;
    int h = threadIdx.x >> 5;
    int f = threadIdx.x & 31;
    int n = t & (NSEQ - 1);
    float c = cosb[n * 32 + f];
    float s = sinb[n * 32 + f];
    const float* p = qkv + (size_t)t * QLD + (sel ? 768 : 0) + h * HD;
    float re = p[2 * f], im = p[2 * f + 1];
    float r0 = re * c - im * s;
    float r1 = re * s + im * c;
    float ss = r0 * r0 + r1 * r1;
#pragma unroll
    for (int o = 16; o > 0; o >>= 1) ss += __shfl_xor_sync(0xffffffffu, ss, o);
    float inv = rsqrtf(ss * (1.f / HD) + EPSV);
    uint32_t hi, lo;
    split2(r0 * inv, r1 * inv, hi, lo);
    size_t oidx = (size_t)t * DIM + h * HD + 2 * f;
    *(uint32_t*)(oh + oidx) = hi;
    *(uint32_t*)(ol + oidx) = lo;
}

// V section of qkv -> bf16 hi/lo planes
__global__ void vsplit_kernel(const float* __restrict__ qkv,
                              __nv_bfloat16* __restrict__ vh, __nv_bfloat16* __restrict__ vl) {
    int t = blockIdx.x;
    int j = threadIdx.x;   // 192 float4 per row
    float4 v = *(const float4*)(qkv + (size_t)t * QLD + 1536 + j * 4);
    uint32_t h0, l0, h1, l1;
    split2(v.x, v.y, h0, l0);
    split2(v.z, v.w, h1, l1);
    size_t o = ((size_t)t * DIM + j * 4) >> 1;
    ((uint32_t*)vh)[o]     = h0;
    ((uint32_t*)vh)[o + 1] = h1;
    ((uint32_t*)vl)[o]     = l0;
    ((uint32_t*)vl)[o + 1] = l1;
}

__global__ void logits_kernel(const float* __restrict__ enc, const float* __restrict__ dec,
                              const float* __restrict__ Wp, const float* __restrict__ bp,
                              const float* __restrict__ Wpr, const float* __restrict__ bpr,
                              float* __restrict__ post, float* __restrict__ prior) {
    int t = blockIdx.x;
    int w = threadIdx.x >> 5;
    int lane = threadIdx.x & 31;
    const float* src  = (w < 4) ? enc + (size_t)t * DIM : dec + (size_t)t * DIM;
    const float* wrow = (w < 4) ? Wp + (size_t)w * DIM : Wpr + (size_t)(w - 4) * DIM;
    float s = 0.f;
    for (int i = lane; i < DIM; i += 32) s += src[i] * wrow[i];
#pragma unroll
    for (int o = 16; o > 0; o >>= 1) s += __shfl_xor_sync(0xffffffffu, s, o);
    if (lane == 0) {
        if (w < 4) post[t * 4 + w] = s + bp[w];
        else       prior[t * 4 + (w - 4)] = s + bpr[w - 4];
    }
}

__device__ __forceinline__ unsigned rotl32(unsigned x, int d) { return (x << d) | (x >> (32 - d)); }

__device__ __forceinline__ void threefry2x32_042(unsigned c0, unsigned c1, unsigned& o0, unsigned& o1) {
    const unsigned k0 = 0u, k1 = 42u;
    const unsigned k2 = k0 ^ k1 ^ 0x1BD11BDAu;
    const unsigned ks[3] = {k0, k1, k2};
    const int rot[2][4] = {{13, 15, 26, 6}, {17, 29, 16, 24}};
    unsigned x0 = c0 + k0, x1 = c1 + k1;
#pragma unroll
    for (int i = 0; i < 5; ++i) {
        const int* rr = rot[i & 1];
#pragma unroll
        for (int j = 0; j < 4; ++j) { x0 += x1; x1 = rotl32(x1, rr[j]); x1 ^= x0; }
        x0 += ks[(i + 1) % 3];
        x1 += ks[(i + 2) % 3] + (unsigned)(i + 1);
    }
    o0 = x0; o1 = x1;
}

__device__ __forceinline__ float log_sigmoid(float x) {
    return fminf(x, 0.f) - log1pf(expf(-fabsf(x)));
}

__global__ void latent_kernel(const float* __restrict__ post, const float* __restrict__ prior,
                              float* __restrict__ kl_out, float* __restrict__ klraw_out,
                              float* __restrict__ z_out, int* __restrict__ idx_out) {
    int t = blockIdx.x * blockDim.x + threadIdx.x;
    if (t >= TOK) return;
    float lsp[4], lsnp[4];
    int idx = 0;
    float klr = 0.f;
#pragma unroll
    for (int j = 0; j < 4; ++j) {
        unsigned e = (unsigned)(t * 4 + j);
        unsigned o0, o1;
        threefry2x32_042(0u, e, o0, o1);
        unsigned bits = o0 ^ o1;
        float u = __uint_as_float((bits >> 9) | 0x3f800000u) - 1.0f;
        float x = post[t * 4 + j];
        float pr = prior[t * 4 + j];
        float prob = 1.f / (1.f + expf(-x));
        if (u <= prob) idx |= (1 << j);
        lsp[j]  = log_sigmoid(x);
        lsnp[j] = log_sigmoid(-x);
        float lspr  = log_sigmoid(pr);
        float lsnpr = log_sigmoid(-pr);
        klr += prob * (lsp[j] - lspr) + (1.f - prob) * (lsnp[j] - lsnpr);
    }
    klraw_out[t] = klr;
    kl_out[t] = fmaxf(klr - 0.125f, 0.f);
    idx_out[t] = idx;
#pragma unroll
    for (int c = 0; c < 16; ++c) {
        float lg = 0.f;
#pragma unroll
        for (int j = 0; j < 4; ++j) lg += ((c >> j) & 1) ? lsp[j] : lsnp[j];
        float soft = expf(lg);
        float hard = (c == idx) ? 1.f : 0.f;
        z_out[t * 16 + c] = (hard + soft) - soft;
    }
}

__global__ void xmid_kernel(const float* __restrict__ x, const float* __restrict__ dec,
                            const float* __restrict__ Wz, const int* __restrict__ idx,
                            float* __restrict__ xmid, float* __restrict__ h) {
    int t = blockIdx.x;
    int code = idx[t];
    float v[3];
    float ss = 0.f;
#pragma unroll
    for (int i = 0; i < 3; ++i) {
        int d = threadIdx.x + i * 256;
        float val = x[(size_t)t * DIM + d] + dec[(size_t)t * DIM + d] + Wz[d * 16 + code];
        v[i] = val;
        ss += val * val;
    }
    ss = block_reduce_sum_256(ss);
    float inv = rsqrtf(ss * (1.f / DIM) + EPSV);
#pragma unroll
    for (int i = 0; i < 3; ++i) {
        int d = threadIdx.x + i * 256;
        xmid[(size_t)t * DIM + d] = v[i];
        h[(size_t)t * DIM + d]    = tf32r(v[i] * inv);
    }
}

// ---------------- launcher ----------------
extern "C" void kernel_launch(void* const* d_in, const int* in_sizes, int n_in,
                              void* d_out, int out_size) {
    const float* x     = (const float*)d_in[0];
    const float* cosb  = (const float*)d_in[1];
    const float* sinb  = (const float*)d_in[2];
    const float* Wq    = (const float*)d_in[3];
    const float* Wk    = (const float*)d_in[4];
    const float* Wv    = (const float*)d_in[5];
    const float* Wenc  = (const float*)d_in[6];
    const float* Wdec  = (const float*)d_in[7];
    const float* Wpost = (const float*)d_in[8];
    const float* bpost = (const float*)d_in[9];
    const float* Wpri  = (const float*)d_in[10];
    const float* bpri  = (const float*)d_in[11];
    const float* Wz    = (const float*)d_in[12];
    const float* Wfc1  = (const float*)d_in[13];
    const float* Wfc2  = (const float*)d_in[14];

    float *qkv, *enc, *dec, *xmid, *h, *act, *wh, *wl, *post, *prior;
    __nv_bfloat16 *xhb, *xlb, *ahb, *alb, *wbh, *wbl, *qh, *ql, *kh, *kl, *vh, *vl;
    int* idx;
    cudaGetSymbolAddress((void**)&xhb,  g_xhb);
    cudaGetSymbolAddress((void**)&xlb,  g_xlb);
    cudaGetSymbolAddress((void**)&ahb,  g_ahb);
    cudaGetSymbolAddress((void**)&alb,  g_alb);
    cudaGetSymbolAddress((void**)&qh,   g_qh);
    cudaGetSymbolAddress((void**)&ql,   g_ql);
    cudaGetSymbolAddress((void**)&kh,   g_kh);
    cudaGetSymbolAddress((void**)&kl,   g_kl);
    cudaGetSymbolAddress((void**)&vh,   g_vh);
    cudaGetSymbolAddress((void**)&vl,   g_vl);
    cudaGetSymbolAddress((void**)&wbh,  g_wbh);
    cudaGetSymbolAddress((void**)&wbl,  g_wbl);
    cudaGetSymbolAddress((void**)&qkv,  g_qkv);
    cudaGetSymbolAddress((void**)&enc,  g_enc);
    cudaGetSymbolAddress((void**)&dec,  g_dec);
    cudaGetSymbolAddress((void**)&xmid, g_xmid);
    cudaGetSymbolAddress((void**)&h,    g_h);
    cudaGetSymbolAddress((void**)&act,  g_act);
    cudaGetSymbolAddress((void**)&wh,   g_wh);
    cudaGetSymbolAddress((void**)&wl,   g_wl);
    cudaGetSymbolAddress((void**)&post, g_post);
    cudaGetSymbolAddress((void**)&prior, g_prior);
    cudaGetSymbolAddress((void**)&idx,  g_idx);

    float* out_x     = (float*)d_out;
    float* out_kl    = out_x + (size_t)TOK * DIM;
    float* out_klraw = out_kl + TOK;
    float* out_z     = out_klraw + TOK;

    cudaFuncSetAttribute(tgemm_b, cudaFuncAttributeMaxDynamicSharedMemorySize, SMB);
    cudaFuncSetAttribute(tgemm_t, cudaFuncAttributeMaxDynamicSharedMemorySize, SM1);
    cudaFuncSetAttribute(attn_tc, cudaFuncAttributeMaxDynamicSharedMemorySize, ATT_SMEM);

    // weight splits for QKV/enc, then rmsnorm, then QKV GEMM
    splitcopy_b4<<<dim3(576, 4), 256>>>(Wq, Wk, Wv, Wenc, wbh, wbl, 147456);
    rmsnorm_kernel<<<TOK, 256>>>(x, xhb, xlb);
    tgemm_b<<<dim3(QLD / 128, TOK / 128), 256, SMB>>>(
        xhb, xlb, DIM, wbh + OFF_WQKV, wbl + OFF_WQKV, DIM, qkv, QLD, DIM);

    // remaining weight splits
    splitcopy_b<<<288, 256>>>(Wdec, wbh + OFF_WDEC, wbl + OFF_WDEC);
    splitcopy<<<2304, 256>>>(Wfc1, wh + OFF_WFC1, wl + OFF_WFC1);
    splitcopy<<<2304, 256>>>(Wfc2, wh + OFF_WFC2, wl + OFF_WFC2);

    // rope + rmsnorm -> q/k bf16 planes;  V -> bf16 planes
    rope_norm_kernel<<<dim3(TOK, 2), 384>>>(qkv, cosb, sinb, qh, ql, kh, kl);
    vsplit_kernel<<<TOK, 192>>>(qkv, vh, vl);

    // tensor-core flash attention from pre-split planes
    attn_tc<<<dim3(NSEQ / 128, 16 * NHEADS), 256, ATT_SMEM>>>(
        qh, ql, kh, kl, vh, vl, ahb, alb);

    // output projections (bf16x3)
    dim3 gout(DIM / 128, TOK / 128);
    tgemm_b<<<gout, 256, SMB>>>(ahb, alb, DIM, wbh + OFF_WENC, wbl + OFF_WENC, DIM, enc, DIM, DIM);
    tgemm_b<<<gout, 256, SMB>>>(ahb + 384, alb + 384, DIM, wbh + OFF_WDEC, wbl + OFF_WDEC, 384, dec, DIM, 384);

    // posterior / prior logits
    logits_kernel<<<TOK, 256>>>(enc, dec, Wpost, bpost, Wpri, bpri, post, prior);

    // sampling / KL / z_one_hot
    latent_kernel<<<TOK / 128, 128>>>(post, prior, out_kl, out_klraw, out_z, idx);

    // x_mid + rmsnorm
    xmid_kernel<<<TOK, 256>>>(x, dec, Wz, idx, xmid, h);

    // FFN (single-pass tf32 — measured best)
    tgemm_t<<<dim3(3072 / 128, TOK / 128), 256, SM1>>>(h, DIM, wh + OFF_WFC1, DIM, act, 3072, DIM, 1, nullptr);
    tgemm_t<<<gout, 256, SM1>>>(act, 3072, wh + OFF_WFC2, 3072, out_x, DIM, 3072, 2, xmid);
}

// round 17
// speedup vs baseline: 1.1503x; 1.0051x over previous
#include <cuda_runtime.h>
#include <cuda_bf16.h>
#include <math.h>
#include <stdint.h>

#define TOK   16384
#define DIM   768
#define NSEQ  1024
#define NHEADS 12
#define HD    64
#define ENC_HEADS 6
#define EPSV  1e-5f
#define QLD   2304            // fused qkv row stride

// fp32 (tf32-rounded) weight buffer offsets — fc only
#define OFF_WFC1 2654208
#define OFF_WFC2 5013504
#define WTOT     7372800
// bf16 plane offsets (halfs) — Wq/Wk/Wv contiguous = fused [2304 x 768]
#define OFF_WQKV 0
#define OFF_WENC 1769472
#define OFF_WDEC 2359296
#define WBTOT    2654208

// ---------------- scratch (device globals; allocation is forbidden) ----------------
__device__ __nv_bfloat16 g_xhb[TOK * DIM];
__device__ __nv_bfloat16 g_xlb[TOK * DIM];
__device__ __nv_bfloat16 g_ahb[TOK * DIM];
__device__ __nv_bfloat16 g_alb[TOK * DIM];
__device__ __nv_bfloat16 g_qh[TOK * DIM];
__device__ __nv_bfloat16 g_ql[TOK * DIM];
__device__ __nv_bfloat16 g_kh[TOK * DIM];
__device__ __nv_bfloat16 g_kl[TOK * DIM];
__device__ __nv_bfloat16 g_vh[TOK * DIM];
__device__ __nv_bfloat16 g_vl[TOK * DIM];
__device__ __nv_bfloat16 g_wbh[WBTOT];
__device__ __nv_bfloat16 g_wbl[WBTOT];
__device__ float g_qkv[TOK * QLD];
__device__ float g_enc[TOK * DIM];
__device__ float g_dec[TOK * DIM];
__device__ float g_xmid[TOK * DIM];
__device__ float g_h[TOK * DIM];
__device__ float g_act[TOK * 3072];
__device__ float g_wh[WTOT];
__device__ float g_wl[WTOT];
__device__ float g_post[TOK * 4];
__device__ float g_prior[TOK * 4];
__device__ int   g_idx[TOK];

// ---------------- small PTX helpers (all sm_80-baseline legal) ----------------
__device__ __forceinline__ uint32_t s2u(const void* p) {
    uint32_t a;
    asm("{ .reg .u64 t; cvta.to.shared.u64 t, %1; cvt.u32.u64 %0, t; }" : "=r"(a) : "l"(p));
    return a;
}
__device__ __forceinline__ uint32_t f2tf32(float v) {
    uint32_t r;
    asm("cvt.rna.tf32.f32 %0, %1;" : "=r"(r) : "f"(v));
    return r;
}
__device__ __forceinline__ float tf32r(float v) { return __uint_as_float(f2tf32(v)); }

__device__ __forceinline__ void cpasync16(uint32_t dst, const void* src) {
    asm volatile("cp.async.cg.shared.global [%0], [%1], 16;" :: "r"(dst), "l"(src));
}
__device__ __forceinline__ void cp_commit() {
    asm volatile("cp.async.commit_group;" ::: "memory");
}
__device__ __forceinline__ void mma_frag(float* d, const uint32_t* a, const uint32_t* b) {
    asm volatile(
        "mma.sync.aligned.m16n8k8.row.col.f32.tf32.tf32.f32 "
        "{%0,%1,%2,%3}, {%4,%5,%6,%7}, {%8,%9}, {%0,%1,%2,%3};"
        : "+f"(d[0]), "+f"(d[1]), "+f"(d[2]), "+f"(d[3])
        : "r"(a[0]), "r"(a[1]), "r"(a[2]), "r"(a[3]), "r"(b[0]), "r"(b[1]));
}
__device__ __forceinline__ void mma_bf(float* d, const uint32_t* a, const uint32_t* b) {
    asm volatile(
        "mma.sync.aligned.m16n8k16.row.col.f32.bf16.bf16.f32 "
        "{%0,%1,%2,%3}, {%4,%5,%6,%7}, {%8,%9}, {%0,%1,%2,%3};"
        : "+f"(d[0]), "+f"(d[1]), "+f"(d[2]), "+f"(d[3])
        : "r"(a[0]), "r"(a[1]), "r"(a[2]), "r"(a[3]), "r"(b[0]), "r"(b[1]));
}
__device__ __forceinline__ void ldm_x4(uint32_t* r, uint32_t addr) {
    asm volatile("ldmatrix.sync.aligned.m8n8.x4.shared.b16 {%0,%1,%2,%3}, [%4];"
                 : "=r"(r[0]), "=r"(r[1]), "=r"(r[2]), "=r"(r[3]) : "r"(addr));
}
__device__ __forceinline__ void split2(float a, float b, uint32_t& hi, uint32_t& lo) {
    __nv_bfloat16 ha = __float2bfloat16(a), hb = __float2bfloat16(b);
    __nv_bfloat162 H(ha, hb);
    __nv_bfloat162 L(__float2bfloat16(a - __bfloat162float(ha)),
                     __float2bfloat16(b - __bfloat162float(hb)));
    hi = *(uint32_t*)&H;
    lo = *(uint32_t*)&L;
}

// ================= bf16x3 GEMM (fp32-grade): C = A*B^T, tile 128x128, Kchunk 32 ====
#define PLANE_B 10240
#define BUF_B   (4 * PLANE_B)
#define SMB     (2 * BUF_B)       // 81920

__global__ __launch_bounds__(256, 2) void tgemm_b(
    const __nv_bfloat16* __restrict__ Ah, const __nv_bfloat16* __restrict__ Al, int lda,
    const __nv_bfloat16* __restrict__ Bh, const __nv_bfloat16* __restrict__ Bl, int ldb,
    float* __restrict__ C, int ldc, int K) {
    extern __shared__ char smb[];
    const uint32_t sbase = s2u(smb);

    const int tid = threadIdx.x;
    const int wid = tid >> 5, lane = tid & 31;
    const int g = lane >> 2, t4 = lane & 3;
    const int bm = blockIdx.y * 128, bn = blockIdx.x * 128;
    const int wm = (wid & 1) * 64, wn = (wid >> 1) * 32;

    const uint32_t aoff = (uint32_t)(wm + (lane & 15)) * 80 + ((lane >> 4) * 16);
    const uint32_t boff = (uint32_t)(wn + (lane & 7) + ((lane & 16) >> 1)) * 80
                        + (((lane >> 3) & 1) * 16);

    float acc[4][4][4];
#pragma unroll
    for (int a = 0; a < 4; ++a)
#pragma unroll
        for (int b = 0; b < 4; ++b)
#pragma unroll
            for (int c = 0; c < 4; ++c) acc[a][b][c] = 0.f;

    const int nch = K >> 5;

    auto stage = [&](int ch, int buf) {
        uint32_t base = sbase + (uint32_t)buf * BUF_B;
        int kc = ch << 5;
#pragma unroll
        for (int it = 0; it < 8; ++it) {
            int idx = tid + it * 256;
            int plane = idx >> 9;
            int rem = idx & 511;
            int row = rem >> 2, j = rem & 3;
            const __nv_bfloat16* src;
            if      (plane == 0) src = Ah + (size_t)(bm + row) * lda + kc + j * 8;
            else if (plane == 1) src = Al + (size_t)(bm + row) * lda + kc + j * 8;
            else if (plane == 2) src = Bh + (size_t)(bn + row) * ldb + kc + j * 8;
            else                 src = Bl + (size_t)(bn + row) * ldb + kc + j * 8;
            cpasync16(base + (uint32_t)plane * PLANE_B + (uint32_t)row * 80 + (uint32_t)j * 16, src);
        }
        cp_commit();
    };

    stage(0, 0);
    for (int ch = 0; ch < nch; ++ch) {
        bool more = (ch + 1 < nch);
        if (more) stage(ch + 1, (ch + 1) & 1);
        if (more) asm volatile("cp.async.wait_group 1;" ::: "memory");
        else      asm volatile("cp.async.wait_group 0;" ::: "memory");
        __syncthreads();

        const uint32_t cb = sbase + (ch & 1) * BUF_B;
        const uint32_t aH = cb + aoff;
        const uint32_t aL = cb + PLANE_B + aoff;
        const uint32_t bH = cb + 2u * PLANE_B + boff;
        const uint32_t bL = cb + 3u * PLANE_B + boff;

#pragma unroll
        for (int ks = 0; ks < 2; ++ks) {
            const uint32_t kb = (uint32_t)ks * 32;
            uint32_t ah[4][4], bh[2][4];
#pragma unroll
            for (int mf = 0; mf < 4; ++mf) ldm_x4(ah[mf], aH + mf * 1280 + kb);
#pragma unroll
            for (int p = 0; p < 2; ++p) ldm_x4(bh[p], bH + p * 1280 + kb);
#pragma unroll
            for (int mf = 0; mf < 4; ++mf)
#pragma unroll
                for (int nf = 0; nf < 4; ++nf)
                    mma_bf(acc[mf][nf], ah[mf], &bh[nf >> 1][(nf & 1) * 2]);

            uint32_t al[4][4];
#pragma unroll
            for (int mf = 0; mf < 4; ++mf) ldm_x4(al[mf], aL + mf * 1280 + kb);
#pragma unroll
            for (int mf = 0; mf < 4; ++mf)
#pragma unroll
                for (int nf = 0; nf < 4; ++nf)
                    mma_bf(acc[mf][nf], al[mf], &bh[nf >> 1][(nf & 1) * 2]);

            uint32_t bl[2][4];
#pragma unroll
            for (int p = 0; p < 2; ++p) ldm_x4(bl[p], bL + p * 1280 + kb);
#pragma unroll
            for (int mf = 0; mf < 4; ++mf)
#pragma unroll
                for (int nf = 0; nf < 4; ++nf)
                    mma_bf(acc[mf][nf], ah[mf], &bl[nf >> 1][(nf & 1) * 2]);
        }
        __syncthreads();
    }

#pragma unroll
    for (int mf = 0; mf < 4; ++mf) {
#pragma unroll
        for (int half = 0; half < 2; ++half) {
            int row = bm + wm + mf * 16 + g + half * 8;
            float* cp = C + (size_t)row * ldc + bn + wn;
#pragma unroll
            for (int nf = 0; nf < 4; ++nf) {
                int col = nf * 8 + 2 * t4;
                *(float2*)(cp + col) =
                    make_float2(acc[mf][nf][half * 2 + 0], acc[mf][nf][half * 2 + 1]);
            }
        }
    }
}

// ================= tf32 single-pass GEMM (for FFN) ==========
#define ASTR 36
#define MATF (128 * ASTR)
#define MATB (MATF * 4)
#define SM1 (2 * 2 * MATB)   // 73728

__global__ __launch_bounds__(256, 2) void tgemm_t(
    const float* __restrict__ Ah, int lda,
    const float* __restrict__ Bh, int ldb,
    float* __restrict__ C, int ldc, int K, int epi, const float* __restrict__ res) {
    extern __shared__ float smf[];
    const uint32_t sbase = s2u(smf);
    constexpr int BUFF = 2 * MATF;

    const int tid = threadIdx.x;
    const int wid = tid >> 5, lane = tid & 31;
    const int g = lane >> 2, t4 = lane & 3;
    const int bm = blockIdx.y * 128, bn = blockIdx.x * 128;
    const int wm = (wid & 1) * 64, wn = (wid >> 1) * 32;

    float acc[4][4][4];
#pragma unroll
    for (int a = 0; a < 4; ++a)
#pragma unroll
        for (int b = 0; b < 4; ++b)
#pragma unroll
            for (int c = 0; c < 4; ++c) acc[a][b][c] = 0.f;

    const int nch = K >> 5;

    auto stage = [&](int ch, int buf) {
        uint32_t base = sbase + (uint32_t)buf * (BUFF * 4);
        int kc = ch << 5;
#pragma unroll
        for (int it = 0; it < 4; ++it) {
            int idx = tid + it * 256;
            int row = idx >> 3, j = idx & 7;
            uint32_t doff = (uint32_t)row * (ASTR * 4) + (uint32_t)j * 16;
            cpasync16(base + doff, Ah + (size_t)(bm + row) * lda + kc + j * 4);
            cpasync16(base + MATB + doff, Bh + (size_t)(bn + row) * ldb + kc + j * 4);
        }
        cp_commit();
    };

    stage(0, 0);
    for (int ch = 0; ch < nch; ++ch) {
        bool more = (ch + 1 < nch);
        if (more) stage(ch + 1, (ch + 1) & 1);
        if (more) asm volatile("cp.async.wait_group 1;" ::: "memory");
        else      asm volatile("cp.async.wait_group 0;" ::: "memory");
        __syncthreads();

        const float* As = smf + (ch & 1) * BUFF;
        const float* Bs = As + MATF;

#pragma unroll
        for (int ks = 0; ks < 4; ++ks) {
            const int ko = ks * 8 + t4;
            uint32_t ah[4][4], bh[4][2];
#pragma unroll
            for (int mf = 0; mf < 4; ++mf) {
                int r0 = (wm + mf * 16 + g) * ASTR + ko;
                ah[mf][0] = __float_as_uint(As[r0]);
                ah[mf][1] = __float_as_uint(As[r0 + 8 * ASTR]);
                ah[mf][2] = __float_as_uint(As[r0 + 4]);
                ah[mf][3] = __float_as_uint(As[r0 + 8 * ASTR + 4]);
            }
#pragma unroll
            for (int nf = 0; nf < 4; ++nf) {
                int rb = (wn + nf * 8 + g) * ASTR + ko;
                bh[nf][0] = __float_as_uint(Bs[rb]);
                bh[nf][1] = __float_as_uint(Bs[rb + 4]);
            }
#pragma unroll
            for (int mf = 0; mf < 4; ++mf)
#pragma unroll
                for (int nf = 0; nf < 4; ++nf)
                    mma_frag(acc[mf][nf], ah[mf], bh[nf]);
        }
        __syncthreads();
    }

#pragma unroll
    for (int mf = 0; mf < 4; ++mf) {
#pragma unroll
        for (int half = 0; half < 2; ++half) {
            int row = bm + wm + mf * 16 + g + half * 8;
            float* cp = C + (size_t)row * ldc + bn + wn;
            const float* rp = (epi == 2) ? (res + (size_t)row * ldc + bn + wn) : nullptr;
#pragma unroll
            for (int nf = 0; nf < 4; ++nf) {
                float v0 = acc[mf][nf][half * 2 + 0];
                float v1 = acc[mf][nf][half * 2 + 1];
                int col = nf * 8 + 2 * t4;
                if (epi == 1) {
                    float a = fmaxf(v0, 0.f), b = fmaxf(v1, 0.f);
                    v0 = tf32r(a * a); v1 = tf32r(b * b);
                } else if (epi == 2) {
                    v0 += rp[col]; v1 += rp[col + 1];
                }
                *(float2*)(cp + col) = make_float2(v0, v1);
            }
        }
    }
}

// ================= tensor-core flash attention (bf16x3, pre-split planes) =========
#define ATS   72
#define QPL   (128 * ATS)
#define KPL   (64 * ATS)
#define ATT_SMEM ((2 * QPL + 8 * KPL) * 2)   // 110592 bytes

__global__ __launch_bounds__(256) void attn_tc(
    const __nv_bfloat16* __restrict__ qh, const __nv_bfloat16* __restrict__ ql,
    const __nv_bfloat16* __restrict__ kh, const __nv_bfloat16* __restrict__ kl,
    const __nv_bfloat16* __restrict__ vh, const __nv_bfloat16* __restrict__ vl,
    __nv_bfloat16* __restrict__ outh, __nv_bfloat16* __restrict__ outl) {
    extern __shared__ __nv_bfloat16 sm[];
    const uint32_t sbase = s2u(sm);
    const int tid = threadIdx.x, wid = tid >> 5, lane = tid & 31;
    const int g = lane >> 2, t4 = lane & 3;
    const int qt = blockIdx.x, bh_ = blockIdx.y;
    const int b = bh_ / NHEADS, h = bh_ - b * NHEADS;
    const size_t pbase = (size_t)b * NSEQ * DIM + (size_t)h * HD;   // bf16 plane base
    const bool causal = (h >= ENC_HEADS);
    const int jmax = causal ? 2 * qt + 1 : (NSEQ / 64 - 1);
    const int wm = wid * 16;
    const float NEGINF = __int_as_float(0xff800000);

    const uint32_t qoff = (uint32_t)(wm + (lane & 15)) * 144 + ((lane >> 4) * 16);
    const uint32_t boff = (uint32_t)((lane & 7) + ((lane & 16) >> 1)) * 144
                        + (((lane >> 3) & 1) * 16);

    // stage Q: pure 16B copies of pre-split planes
    for (int i = tid; i < 128 * 8; i += 256) {
        int row = i >> 3, c16 = i & 7;
        size_t gi = pbase + (size_t)(qt * 128 + row) * DIM + c16 * 8;
        *(uint4*)(sm + row * ATS + c16 * 8)       = *(const uint4*)(qh + gi);
        *(uint4*)(sm + QPL + row * ATS + c16 * 8) = *(const uint4*)(ql + gi);
    }

    auto stage = [&](int j, int buf) {
        __nv_bfloat16* Kh = sm + 2 * QPL + buf * 4 * KPL;
        __nv_bfloat16* Kl = Kh + KPL;
        __nv_bfloat16* Vh = Kh + 2 * KPL;
        __nv_bfloat16* Vl = Kh + 3 * KPL;
        // K: 16B copies
        for (int i = tid; i < 64 * 8; i += 256) {
            int kv = i >> 3, c16 = i & 7;
            size_t gi = pbase + (size_t)(j * 64 + kv) * DIM + c16 * 8;
            *(uint4*)(Kh + kv * ATS + c16 * 8) = *(const uint4*)(kh + gi);
            *(uint4*)(Kl + kv * ATS + c16 * 8) = *(const uint4*)(kl + gi);
        }
        // V: transposed 2-half copies
        for (int i = tid; i < 64 * 32; i += 256) {
            int kv = i >> 5, dp = i & 31;
            size_t gi = pbase + (size_t)(j * 64 + kv) * DIM + 2 * dp;
            __nv_bfloat162 vv = *(const __nv_bfloat162*)(vh + gi);
            Vh[(2 * dp) * ATS + kv]     = vv.x;
            Vh[(2 * dp + 1) * ATS + kv] = vv.y;
            __nv_bfloat162 wl = *(const __nv_bfloat162*)(vl + gi);
            Vl[(2 * dp) * ATS + kv]     = wl.x;
            Vl[(2 * dp + 1) * ATS + kv] = wl.y;
        }
    };

    stage(0, 0);
    __syncthreads();

    uint32_t aQh[4][4], aQl[4][4];
#pragma unroll
    for (int ks = 0; ks < 4; ++ks) {
        ldm_x4(aQh[ks], sbase + qoff + ks * 32);
        ldm_x4(aQl[ks], sbase + QPL * 2 + qoff + ks * 32);
    }

    float acc[8][4];
#pragma unroll
    for (int nf = 0; nf < 8; ++nf)
#pragma unroll
        for (int e = 0; e < 4; ++e) acc[nf][e] = 0.f;
    float m0 = -1e30f, m1 = -1e30f, l0 = 0.f, l1 = 0.f;

    for (int j = 0; j <= jmax; ++j) {
        if (j + 1 <= jmax) stage(j + 1, (j + 1) & 1);

        const uint32_t kvb = sbase + (2 * QPL + (j & 1) * 4 * KPL) * 2;
        const uint32_t Kb  = kvb + boff;
        const uint32_t Klb = kvb + KPL * 2 + boff;
        const uint32_t Vb  = kvb + 2 * KPL * 2 + boff;
        const uint32_t Vlb = kvb + 3 * KPL * 2 + boff;

        float s[8][4];
#pragma unroll
        for (int nf = 0; nf < 8; ++nf)
#pragma unroll
            for (int e = 0; e < 4; ++e) s[nf][e] = 0.f;

#pragma unroll
        for (int ks = 0; ks < 4; ++ks) {
            const uint32_t kb = (uint32_t)ks * 32;
            uint32_t bk[4][4];
#pragma unroll
            for (int p = 0; p < 4; ++p) ldm_x4(bk[p], Kb + p * 2304 + kb);
#pragma unroll
            for (int nf = 0; nf < 8; ++nf) {
                mma_bf(s[nf], aQh[ks], &bk[nf >> 1][(nf & 1) * 2]);
                mma_bf(s[nf], aQl[ks], &bk[nf >> 1][(nf & 1) * 2]);
            }
            uint32_t bkl[4][4];
#pragma unroll
            for (int p = 0; p < 4; ++p) ldm_x4(bkl[p], Klb + p * 2304 + kb);
#pragma unroll
            for (int nf = 0; nf < 8; ++nf)
                mma_bf(s[nf], aQh[ks], &bkl[nf >> 1][(nf & 1) * 2]);
        }

        int row0 = qt * 128 + wm + g;
        float mx0 = NEGINF, mx1 = NEGINF;
#pragma unroll
        for (int nf = 0; nf < 8; ++nf) {
            int colb = j * 64 + nf * 8 + 2 * t4;
#pragma unroll
            for (int e = 0; e < 4; ++e) {
                float val = s[nf][e] * 0.125f;
                if (causal && (colb + (e & 1)) > (row0 + (e >> 1) * 8)) val = NEGINF;
                s[nf][e] = val;
            }
            mx0 = fmaxf(mx0, fmaxf(s[nf][0], s[nf][1]));
            mx1 = fmaxf(mx1, fmaxf(s[nf][2], s[nf][3]));
        }
        mx0 = fmaxf(mx0, __shfl_xor_sync(0xffffffffu, mx0, 1));
        mx0 = fmaxf(mx0, __shfl_xor_sync(0xffffffffu, mx0, 2));
        mx1 = fmaxf(mx1, __shfl_xor_sync(0xffffffffu, mx1, 1));
        mx1 = fmaxf(mx1, __shfl_xor_sync(0xffffffffu, mx1, 2));
        float mn0 = fmaxf(m0, mx0), mn1 = fmaxf(m1, mx1);
        float c0 = expf(m0 - mn0), c1 = expf(m1 - mn1);
        float ls0 = 0.f, ls1 = 0.f;
#pragma unroll
        for (int nf = 0; nf < 8; ++nf) {
            float p0 = expf(s[nf][0] - mn0);
            float p1 = expf(s[nf][1] - mn0);
            float p2 = expf(s[nf][2] - mn1);
            float p3 = expf(s[nf][3] - mn1);
            s[nf][0] = p0; s[nf][1] = p1; s[nf][2] = p2; s[nf][3] = p3;
            ls0 += p0 + p1; ls1 += p2 + p3;
        }
        ls0 += __shfl_xor_sync(0xffffffffu, ls0, 1);
        ls0 += __shfl_xor_sync(0xffffffffu, ls0, 2);
        ls1 += __shfl_xor_sync(0xffffffffu, ls1, 1);
        ls1 += __shfl_xor_sync(0xffffffffu, ls1, 2);
        l0 = l0 * c0 + ls0;
        l1 = l1 * c1 + ls1;
        m0 = mn0; m1 = mn1;
#pragma unroll
        for (int nf = 0; nf < 8; ++nf) {
            acc[nf][0] *= c0; acc[nf][1] *= c0;
            acc[nf][2] *= c1; acc[nf][3] *= c1;
        }

#pragma unroll
        for (int ks = 0; ks < 4; ++ks) {
            const uint32_t kb = (uint32_t)ks * 32;
            uint32_t aPh[4], aPl[4];
            split2(s[2 * ks][0],     s[2 * ks][1],     aPh[0], aPl[0]);
            split2(s[2 * ks][2],     s[2 * ks][3],     aPh[1], aPl[1]);
            split2(s[2 * ks + 1][0], s[2 * ks + 1][1], aPh[2], aPl[2]);
            split2(s[2 * ks + 1][2], s[2 * ks + 1][3], aPh[3], aPl[3]);
            uint32_t bv[4][4];
#pragma unroll
            for (int p = 0; p < 4; ++p) ldm_x4(bv[p], Vb + p * 2304 + kb);
#pragma unroll
            for (int nf = 0; nf < 8; ++nf) {
                mma_bf(acc[nf], aPh, &bv[nf >> 1][(nf & 1) * 2]);
                mma_bf(acc[nf], aPl, &bv[nf >> 1][(nf & 1) * 2]);
            }
            uint32_t bvl[4][4];
#pragma unroll
            for (int p = 0; p < 4; ++p) ldm_x4(bvl[p], Vlb + p * 2304 + kb);
#pragma unroll
            for (int nf = 0; nf < 8; ++nf)
                mma_bf(acc[nf], aPh, &bvl[nf >> 1][(nf & 1) * 2]);
        }
        __syncthreads();
    }

    float iv0 = 1.f / l0, iv1 = 1.f / l1;
    int r0 = qt * 128 + wm + g, r1 = r0 + 8;
#pragma unroll
    for (int nf = 0; nf < 8; ++nf) {
        int col = nf * 8 + 2 * t4;
        uint32_t hi, lo;
        split2(acc[nf][0] * iv0, acc[nf][1] * iv0, hi, lo);
        *(uint32_t*)(outh + pbase + (size_t)r0 * DIM + col - (size_t)h * HD + (size_t)h * HD) = hi;
        *(uint32_t*)(outl + pbase + (size_t)r0 * DIM + col - (size_t)h * HD + (size_t)h * HD) = lo;
        split2(acc[nf][2] * iv1, acc[nf][3] * iv1, hi, lo);
        *(uint32_t*)(outh + pbase + (size_t)r1 * DIM + col) = hi;
        *(uint32_t*)(outl + pbase + (size_t)r1 * DIM + col) = lo;
    }
}

// ---------------- elementwise helpers ----------------
__device__ __forceinline__ float block_reduce_sum_256(float v) {
    __shared__ float sh[8];
    int lane = threadIdx.x & 31;
    int w = threadIdx.x >> 5;
#pragma unroll
    for (int o = 16; o > 0; o >>= 1) v += __shfl_xor_sync(0xffffffffu, v, o);
    if (lane == 0) sh[w] = v;
    __syncthreads();
    float r = (threadIdx.x < 8) ? sh[threadIdx.x] : 0.f;
    if (w == 0) {
#pragma unroll
        for (int o = 4; o > 0; o >>= 1) r += __shfl_xor_sync(0xffffffffu, r, o);
        if (lane == 0) sh[0] = r;
    }
    __syncthreads();
    float out = sh[0];
    __syncthreads();
    return out;
}

__global__ void splitcopy(const float* __restrict__ in, float* __restrict__ hi,
                          float* __restrict__ lo) {
    int i = blockIdx.x * 256 + threadIdx.x;
    float4 v = ((const float4*)in)[i];
    float4 h = make_float4(tf32r(v.x), tf32r(v.y), tf32r(v.z), tf32r(v.w));
    ((float4*)hi)[i] = h;
    ((float4*)lo)[i] = make_float4(tf32r(v.x - h.x), tf32r(v.y - h.y),
                                   tf32r(v.z - h.z), tf32r(v.w - h.w));
}

__global__ void splitcopy_b4(const float* __restrict__ i0, const float* __restrict__ i1,
                             const float* __restrict__ i2, const float* __restrict__ i3,
                             __nv_bfloat16* __restrict__ hi, __nv_bfloat16* __restrict__ lo,
                             int elems4_per) {
    int w = blockIdx.y;
    const float* in = (w == 0) ? i0 : (w == 1) ? i1 : (w == 2) ? i2 : i3;
    size_t obase = (size_t)w * elems4_per;
    int i = blockIdx.x * 256 + threadIdx.x;
    float4 v = ((const float4*)in)[i];
    uint32_t h0, l0, h1, l1;
    split2(v.x, v.y, h0, l0);
    split2(v.z, v.w, h1, l1);
    ((uint32_t*)hi)[(obase + i) * 2]     = h0;
    ((uint32_t*)hi)[(obase + i) * 2 + 1] = h1;
    ((uint32_t*)lo)[(obase + i) * 2]     = l0;
    ((uint32_t*)lo)[(obase + i) * 2 + 1] = l1;
}

__global__ void splitcopy_b(const float* __restrict__ in, __nv_bfloat16* __restrict__ hi,
                            __nv_bfloat16* __restrict__ lo) {
    int i = blockIdx.x * 256 + threadIdx.x;
    float4 v = ((const float4*)in)[i];
    uint32_t h0, l0, h1, l1;
    split2(v.x, v.y, h0, l0);
    split2(v.z, v.w, h1, l1);
    ((uint32_t*)hi)[i * 2]     = h0;
    ((uint32_t*)hi)[i * 2 + 1] = h1;
    ((uint32_t*)lo)[i * 2]     = l0;
    ((uint32_t*)lo)[i * 2 + 1] = l1;
}

__global__ void rmsnorm_kernel(const float* __restrict__ in,
                               __nv_bfloat16* __restrict__ oh, __nv_bfloat16* __restrict__ ol) {
    int t = blockIdx.x;
    const float* row = in + (size_t)t * DIM;
    float v0 = row[threadIdx.x];
    float v1 = row[threadIdx.x + 256];
    float v2 = row[threadIdx.x + 512];
    float ss = block_reduce_sum_256(v0 * v0 + v1 * v1 + v2 * v2);
    float inv = rsqrtf(ss * (1.f / DIM) + EPSV);
#pragma unroll
    for (int i = 0; i < 3; ++i) {
        int d = threadIdx.x + i * 256;
        float y = (i == 0 ? v0 : (i == 1 ? v1 : v2)) * inv;
        __nv_bfloat16 hb = __float2bfloat16(y);
        oh[(size_t)t * DIM + d] = hb;
        ol[(size_t)t * DIM + d] = __float2bfloat16(y - __bfloat162float(hb));
    }
}

// rope + per-head rmsnorm on fused qkv, output bf16 hi/lo planes (q or k by blockIdx.y)
__global__ void rope_norm_kernel(const float* __restrict__ qkv,
                                 const float* __restrict__ cosb, const float* __restrict__ sinb,
                                 __nv_bfloat16* __restrict__ qh, __nv_bfloat16* __restrict__ ql,
                                 __nv_bfloat16* __restrict__ kh, __nv_bfloat16* __restrict__ kl) {
    int t = blockIdx.x;
    int sel = blockIdx.y;
    __nv_bfloat16* oh = sel ? kh : qh;
    __nv_bfloat16* ol = sel ? kl : ql;
    int h = threadIdx.x >> 5;
    int f = threadIdx.x & 31;
    int n = t & (NSEQ - 1);
    float c = cosb[n * 32 + f];
    float s = sinb[n * 32 + f];
    const float* p = qkv + (size_t)t * QLD + (sel ? 768 : 0) + h * HD;
    float re = p[2 * f], im = p[2 * f + 1];
    float r0 = re * c - im * s;
    float r1 = re * s + im * c;
    float ss = r0 * r0 + r1 * r1;
#pragma unroll
    for (int o = 16; o > 0; o >>= 1) ss += __shfl_xor_sync(0xffffffffu, ss, o);
    float inv = rsqrtf(ss * (1.f / HD) + EPSV);
    uint32_t hi, lo;
    split2(r0 * inv, r1 * inv, hi, lo);
    size_t oidx = (size_t)t * DIM + h * HD + 2 * f;
    *(uint32_t*)(oh + oidx) = hi;
    *(uint32_t*)(ol + oidx) = lo;
}

// V section of qkv -> bf16 hi/lo planes
__global__ void vsplit_kernel(const float* __restrict__ qkv,
                              __nv_bfloat16* __restrict__ vh, __nv_bfloat16* __restrict__ vl) {
    int t = blockIdx.x;
    int j = threadIdx.x;   // 192 float4 per row
    float4 v = *(const float4*)(qkv + (size_t)t * QLD + 1536 + j * 4);
    uint32_t h0, l0, h1, l1;
    split2(v.x, v.y, h0, l0);
    split2(v.z, v.w, h1, l1);
    size_t o = ((size_t)t * DIM + j * 4) >> 1;
    ((uint32_t*)vh)[o]     = h0;
    ((uint32_t*)vh)[o + 1] = h1;
    ((uint32_t*)vl)[o]     = l0;
    ((uint32_t*)vl)[o + 1] = l1;
}

__global__ void logits_kernel(const float* __restrict__ enc, const float* __restrict__ dec,
                              const float* __restrict__ Wp, const float* __restrict__ bp,
                              const float* __restrict__ Wpr, const float* __restrict__ bpr,
                              float* __restrict__ post, float* __restrict__ prior) {
    int t = blockIdx.x;
    int w = threadIdx.x >> 5;
    int lane = threadIdx.x & 31;
    const float* src  = (w < 4) ? enc + (size_t)t * DIM : dec + (size_t)t * DIM;
    const float* wrow = (w < 4) ? Wp + (size_t)w * DIM : Wpr + (size_t)(w - 4) * DIM;
    float s = 0.f;
    for (int i = lane; i < DIM; i += 32) s += src[i] * wrow[i];
#pragma unroll
    for (int o = 16; o > 0; o >>= 1) s += __shfl_xor_sync(0xffffffffu, s, o);
    if (lane == 0) {
        if (w < 4) post[t * 4 + w] = s + bp[w];
        else       prior[t * 4 + (w - 4)] = s + bpr[w - 4];
    }
}

__device__ __forceinline__ unsigned rotl32(unsigned x, int d) { return (x << d) | (x >> (32 - d)); }

__device__ __forceinline__ void threefry2x32_042(unsigned c0, unsigned c1, unsigned& o0, unsigned& o1) {
    const unsigned k0 = 0u, k1 = 42u;
    const unsigned k2 = k0 ^ k1 ^ 0x1BD11BDAu;
    const unsigned ks[3] = {k0, k1, k2};
    const int rot[2][4] = {{13, 15, 26, 6}, {17, 29, 16, 24}};
    unsigned x0 = c0 + k0, x1 = c1 + k1;
#pragma unroll
    for (int i = 0; i < 5; ++i) {
        const int* rr = rot[i & 1];
#pragma unroll
        for (int j = 0; j < 4; ++j) { x0 += x1; x1 = rotl32(x1, rr[j]); x1 ^= x0; }
        x0 += ks[(i + 1) % 3];
        x1 += ks[(i + 2) % 3] + (unsigned)(i + 1);
    }
    o0 = x0; o1 = x1;
}

__device__ __forceinline__ float log_sigmoid(float x) {
    return fminf(x, 0.f) - log1pf(expf(-fabsf(x)));
}

__global__ void latent_kernel(const float* __restrict__ post, const float* __restrict__ prior,
                              float* __restrict__ kl_out, float* __restrict__ klraw_out,
                              float* __restrict__ z_out, int* __restrict__ idx_out) {
    int t = blockIdx.x * blockDim.x + threadIdx.x;
    if (t >= TOK) return;
    float lsp[4], lsnp[4];
    int idx = 0;
    float klr = 0.f;
#pragma unroll
    for (int j = 0; j < 4; ++j) {
        unsigned e = (unsigned)(t * 4 + j);
        unsigned o0, o1;
        threefry2x32_042(0u, e, o0, o1);
        unsigned bits = o0 ^ o1;
        float u = __uint_as_float((bits >> 9) | 0x3f800000u) - 1.0f;
        float x = post[t * 4 + j];
        float pr = prior[t * 4 + j];
        float prob = 1.f / (1.f + expf(-x));
        if (u <= prob) idx |= (1 << j);
        lsp[j]  = log_sigmoid(x);
        lsnp[j] = log_sigmoid(-x);
        float lspr  = log_sigmoid(pr);
        float lsnpr = log_sigmoid(-pr);
        klr += prob * (lsp[j] - lspr) + (1.f - prob) * (lsnp[j] - lsnpr);
    }
    klraw_out[t] = klr;
    kl_out[t] = fmaxf(klr - 0.125f, 0.f);
    idx_out[t] = idx;
#pragma unroll
    for (int c = 0; c < 16; ++c) {
        float lg = 0.f;
#pragma unroll
        for (int j = 0; j < 4; ++j) lg += ((c >> j) & 1) ? lsp[j] : lsnp[j];
        float soft = expf(lg);
        float hard = (c == idx) ? 1.f : 0.f;
        z_out[t * 16 + c] = (hard + soft) - soft;
    }
}

__global__ void xmid_kernel(const float* __restrict__ x, const float* __restrict__ dec,
                            const float* __restrict__ Wz, const int* __restrict__ idx,
                            float* __restrict__ xmid, float* __restrict__ h) {
    int t = blockIdx.x;
    int code = idx[t];
    float v[3];
    float ss = 0.f;
#pragma unroll
    for (int i = 0; i < 3; ++i) {
        int d = threadIdx.x + i * 256;
        float val = x[(size_t)t * DIM + d] + dec[(size_t)t * DIM + d] + Wz[d * 16 + code];
        v[i] = val;
        ss += val * val;
    }
    ss = block_reduce_sum_256(ss);
    float inv = rsqrtf(ss * (1.f / DIM) + EPSV);
#pragma unroll
    for (int i = 0; i < 3; ++i) {
        int d = threadIdx.x + i * 256;
        xmid[(size_t)t * DIM + d] = v[i];
        h[(size_t)t * DIM + d]    = tf32r(v[i] * inv);
    }
}

// ---------------- launcher ----------------
extern "C" void kernel_launch(void* const* d_in, const int* in_sizes, int n_in,
                              void* d_out, int out_size) {
    const float* x     = (const float*)d_in[0];
    const float* cosb  = (const float*)d_in[1];
    const float* sinb  = (const float*)d_in[2];
    const float* Wq    = (const float*)d_in[3];
    const float* Wk    = (const float*)d_in[4];
    const float* Wv    = (const float*)d_in[5];
    const float* Wenc  = (const float*)d_in[6];
    const float* Wdec  = (const float*)d_in[7];
    const float* Wpost = (const float*)d_in[8];
    const float* bpost = (const float*)d_in[9];
    const float* Wpri  = (const float*)d_in[10];
    const float* bpri  = (const float*)d_in[11];
    const float* Wz    = (const float*)d_in[12];
    const float* Wfc1  = (const float*)d_in[13];
    const float* Wfc2  = (const float*)d_in[14];

    float *qkv, *enc, *dec, *xmid, *h, *act, *wh, *wl, *post, *prior;
    __nv_bfloat16 *xhb, *xlb, *ahb, *alb, *wbh, *wbl, *qh, *ql, *kh, *kl, *vh, *vl;
    int* idx;
    cudaGetSymbolAddress((void**)&xhb,  g_xhb);
    cudaGetSymbolAddress((void**)&xlb,  g_xlb);
    cudaGetSymbolAddress((void**)&ahb,  g_ahb);
    cudaGetSymbolAddress((void**)&alb,  g_alb);
    cudaGetSymbolAddress((void**)&qh,   g_qh);
    cudaGetSymbolAddress((void**)&ql,   g_ql);
    cudaGetSymbolAddress((void**)&kh,   g_kh);
    cudaGetSymbolAddress((void**)&kl,   g_kl);
    cudaGetSymbolAddress((void**)&vh,   g_vh);
    cudaGetSymbolAddress((void**)&vl,   g_vl);
    cudaGetSymbolAddress((void**)&wbh,  g_wbh);
    cudaGetSymbolAddress((void**)&wbl,  g_wbl);
    cudaGetSymbolAddress((void**)&qkv,  g_qkv);
    cudaGetSymbolAddress((void**)&enc,  g_enc);
    cudaGetSymbolAddress((void**)&dec,  g_dec);
    cudaGetSymbolAddress((void**)&xmid, g_xmid);
    cudaGetSymbolAddress((void**)&h,    g_h);
    cudaGetSymbolAddress((void**)&act,  g_act);
    cudaGetSymbolAddress((void**)&wh,   g_wh);
    cudaGetSymbolAddress((void**)&wl,   g_wl);
    cudaGetSymbolAddress((void**)&post, g_post);
    cudaGetSymbolAddress((void**)&prior, g_prior);
    cudaGetSymbolAddress((void**)&idx,  g_idx);

    float* out_x     = (float*)d_out;
    float* out_kl    = out_x + (size_t)TOK * DIM;
    float* out_klraw = out_kl + TOK;
    float* out_z     = out_klraw + TOK;

    cudaFuncSetAttribute(tgemm_b, cudaFuncAttributeMaxDynamicSharedMemorySize, SMB);
    cudaFuncSetAttribute(tgemm_t, cudaFuncAttributeMaxDynamicSharedMemorySize, SM1);
    cudaFuncSetAttribute(attn_tc, cudaFuncAttributeMaxDynamicSharedMemorySize, ATT_SMEM);

    // weight splits for QKV/enc, then rmsnorm, then QKV GEMM
    splitcopy_b4<<<dim3(576, 4), 256>>>(Wq, Wk, Wv, Wenc, wbh, wbl, 147456);
    rmsnorm_kernel<<<TOK, 256>>>(x, xhb, xlb);
    tgemm_b<<<dim3(QLD / 128, TOK / 128), 256, SMB>>>(
        xhb, xlb, DIM, wbh + OFF_WQKV, wbl + OFF_WQKV, DIM, qkv, QLD, DIM);

    // remaining weight splits
    splitcopy_b<<<288, 256>>>(Wdec, wbh + OFF_WDEC, wbl + OFF_WDEC);
    splitcopy<<<2304, 256>>>(Wfc1, wh + OFF_WFC1, wl + OFF_WFC1);
    splitcopy<<<2304, 256>>>(Wfc2, wh + OFF_WFC2, wl + OFF_WFC2);

    // rope + rmsnorm -> q/k bf16 planes;  V -> bf16 planes
    rope_norm_kernel<<<dim3(TOK, 2), 384>>>(qkv, cosb, sinb, qh, ql, kh, kl);
    vsplit_kernel<<<TOK, 192>>>(qkv, vh, vl);

    // tensor-core flash attention from pre-split planes
    attn_tc<<<dim3(NSEQ / 128, 16 * NHEADS), 256, ATT_SMEM>>>(
        qh, ql, kh, kl, vh, vl, ahb, alb);

    // output projections (bf16x3)
    dim3 gout(DIM / 128, TOK / 128);
    tgemm_b<<<gout, 256, SMB>>>(ahb, alb, DIM, wbh + OFF_WENC, wbl + OFF_WENC, DIM, enc, DIM, DIM);
    tgemm_b<<<gout, 256, SMB>>>(ahb + 384, alb + 384, DIM, wbh + OFF_WDEC, wbl + OFF_WDEC, 384, dec, DIM, 384);

    // posterior / prior logits
    logits_kernel<<<TOK, 256>>>(enc, dec, Wpost, bpost, Wpri, bpri, post, prior);

    // sampling / KL / z_one_hot
    latent_kernel<<<TOK / 128, 128>>>(post, prior, out_kl, out_klraw, out_z, idx);

    // x_mid + rmsnorm
    xmid_kernel<<<TOK, 256>>>(x, dec, Wz, idx, xmid, h);

    // FFN (single-pass tf32 — measured best)
    tgemm_t<<<dim3(3072 / 128, TOK / 128), 256, SM1>>>(h, DIM, wh + OFF_WFC1, DIM, act, 3072, DIM, 1, nullptr);
    tgemm_t<<<gout, 256, SM1>>>(act, 3072, wh + OFF_WFC2, 3072, out_x, DIM, 3072, 2, xmid);
}